// round 7
// baseline (speedup 1.0000x reference)
#include <cuda_runtime.h>
#include <cuda_bf16.h>
#include <math.h>
#include <stdint.h>

#define DIMC 768
#define NHEAD 12
#define HDIM 64
#define BATCH 8
#define SEQ 1024
#define MTOT (BATCH*SEQ)   // 8192
#define NQKV (3*DIMC)      // 2304

#if defined(__CUDA_ARCH__) && (defined(__CUDA_ARCH_FEAT_SM103_ALL) || defined(__CUDA_ARCH_FEAT_SM100_ALL))
#define HAS_TCGEN05 1
#else
#define HAS_TCGEN05 0
#endif

// ---------------------------------------------------------------------------
// Scratch
// ---------------------------------------------------------------------------
__device__ __align__(16) float g_qkv[(size_t)MTOT * NQKV];
__device__ __align__(16) float g_attn[(size_t)MTOT * DIMC];
__device__ __align__(16) __nv_bfloat16 g_ah[(size_t)MTOT * DIMC];
__device__ __align__(16) __nv_bfloat16 g_al[(size_t)MTOT * DIMC];
__device__ __align__(16) __nv_bfloat16 g_wqh[(size_t)NQKV * DIMC];
__device__ __align__(16) __nv_bfloat16 g_wql[(size_t)NQKV * DIMC];
__device__ __align__(16) __nv_bfloat16 g_wph[(size_t)DIMC * DIMC];
__device__ __align__(16) __nv_bfloat16 g_wpl[(size_t)DIMC * DIMC];

// ---------------------------------------------------------------------------
// Probe kernel (host dispatch signal)
// ---------------------------------------------------------------------------
__global__ void feat_probe(int* out) {
#if HAS_TCGEN05
    __shared__ int s[256];
#else
    __shared__ int s[2];
#endif
    int n = (int)(sizeof(s) / sizeof(int));
    s[threadIdx.x % n] = (int)clock();
    __syncthreads();
    if (out) *out = s[0];
}

// ---------------------------------------------------------------------------
// Split fp32 -> bf16 hi/lo
// ---------------------------------------------------------------------------
__global__ __launch_bounds__(256)
void split_kernel(const float* __restrict__ src, __nv_bfloat16* __restrict__ hi,
                  __nv_bfloat16* __restrict__ lo, int n4)
{
    int i = blockIdx.x * blockDim.x + threadIdx.x;
    if (i >= n4) return;
    float4 v = reinterpret_cast<const float4*>(src)[i];
    __nv_bfloat16 h0 = __float2bfloat16(v.x);
    __nv_bfloat16 h1 = __float2bfloat16(v.y);
    __nv_bfloat16 h2 = __float2bfloat16(v.z);
    __nv_bfloat16 h3 = __float2bfloat16(v.w);
    __nv_bfloat16 l0 = __float2bfloat16(v.x - __bfloat162float(h0));
    __nv_bfloat16 l1 = __float2bfloat16(v.y - __bfloat162float(h1));
    __nv_bfloat16 l2 = __float2bfloat16(v.z - __bfloat162float(h2));
    __nv_bfloat16 l3 = __float2bfloat16(v.w - __bfloat162float(h3));
    __nv_bfloat162* ph = reinterpret_cast<__nv_bfloat162*>(hi);
    __nv_bfloat162* pl = reinterpret_cast<__nv_bfloat162*>(lo);
    ph[2*i]   = __nv_bfloat162{h0, h1};
    ph[2*i+1] = __nv_bfloat162{h2, h3};
    pl[2*i]   = __nv_bfloat162{l0, l1};
    pl[2*i+1] = __nv_bfloat162{l2, l3};
}

__global__ __launch_bounds__(1024)
void transpose_split_kernel(const float* __restrict__ W,
                            __nv_bfloat16* __restrict__ hiT,
                            __nv_bfloat16* __restrict__ loT, int K, int N)
{
    __shared__ float t[32][33];
    int n0 = blockIdx.x * 32, k0 = blockIdx.y * 32;
    int tx = threadIdx.x, ty = threadIdx.y;
    t[ty][tx] = W[(size_t)(k0 + ty) * N + n0 + tx];
    __syncthreads();
    float v = t[tx][ty];
    __nv_bfloat16 h = __float2bfloat16(v);
    __nv_bfloat16 l = __float2bfloat16(v - __bfloat162float(h));
    size_t off = (size_t)(n0 + ty) * K + k0 + tx;
    hiT[off] = h;
    loT[off] = l;
}

// ---------------------------------------------------------------------------
// helpers
// ---------------------------------------------------------------------------
__device__ __forceinline__ uint32_t smem_u32(const void* p) {
    uint32_t a;
    asm("{ .reg .u64 t; cvta.to.shared.u64 t, %1; cvt.u32.u64 %0, t; }"
        : "=r"(a) : "l"(p));
    return a;
}

#define SWZ128(o) ((o) ^ (((o) >> 3) & 0x70))

#define MBAR_INIT(addr, cnt) \
    asm volatile("mbarrier.init.shared.b64 [%0], %1;" :: "r"(addr), "r"(cnt) : "memory")

#define MBAR_WAIT(addr, parity) do {                                          \
    uint32_t _m = (addr); uint32_t _p = (parity); uint32_t _done;             \
    asm volatile("{\n\t.reg .pred p;\n\t"                                     \
        "mbarrier.try_wait.parity.acquire.cta.shared::cta.b64 p, [%1], %2;\n\t"\
        "selp.b32 %0, 1, 0, p;\n\t}" : "=r"(_done) : "r"(_m), "r"(_p) : "memory");\
    if (!_done) {                                                             \
        asm volatile("{\n\t.reg .pred P1;\n\t"                                \
            "WL_%=:\n\t"                                                      \
            "mbarrier.try_wait.parity.acquire.cta.shared::cta.b64 P1, [%0], %1, 0x989680;\n\t"\
            "@P1 bra.uni WD_%=;\n\t"                                          \
            "bra.uni WL_%=;\n\t"                                              \
            "WD_%=:\n\t}" :: "r"(_m), "r"(_p) : "memory");                    \
    }                                                                         \
} while (0)

#if HAS_TCGEN05
__device__ __forceinline__ uint32_t elect_one() {
    uint32_t pred;
    asm volatile("{\n\t.reg .pred p;\n\telect.sync _|p, 0xFFFFFFFF;\n\t"
                 "selp.b32 %0, 1, 0, p;\n\t}" : "=r"(pred));
    return pred;
}

#define TC_ALLOC(sm_dst, ncols) \
    asm volatile("tcgen05.alloc.cta_group::1.sync.aligned.shared::cta.b32 [%0], %1;" \
                 :: "r"(sm_dst), "r"(ncols) : "memory")
#define TC_DEALLOC(tm, ncols) \
    asm volatile("tcgen05.dealloc.cta_group::1.sync.aligned.b32 %0, %1;" :: "r"(tm), "r"(ncols))
#define TC_RELINQ() \
    asm volatile("tcgen05.relinquish_alloc_permit.cta_group::1.sync.aligned;")
#define TC_COMMIT(mbar) \
    asm volatile("tcgen05.commit.cta_group::1.mbarrier::arrive::one.shared::cluster.b64 [%0];" \
                 :: "r"(mbar) : "memory")
#define TC_FENCE_AFTER()  asm volatile("tcgen05.fence::after_thread_sync;" ::: "memory")
#define TC_FENCE_BEFORE() asm volatile("tcgen05.fence::before_thread_sync;" ::: "memory")
#define TC_WAIT_LD() asm volatile("tcgen05.wait::ld.sync.aligned;" ::: "memory")
#define FENCE_ASYNC() asm volatile("fence.proxy.async.shared::cta;" ::: "memory")

#define CP_ASYNC16(dst, src) \
    asm volatile("cp.async.cg.shared.global [%0], [%1], 16;" :: "r"(dst), "l"(src) : "memory")
#define CP_COMMIT() asm volatile("cp.async.commit_group;" ::: "memory")
#define CP_WAIT2()  asm volatile("cp.async.wait_group 2;" ::: "memory")

#define TC_LD_X32(r, tm) \
    asm volatile("tcgen05.ld.sync.aligned.32x32b.x32.b32 "                    \
        "{%0, %1, %2, %3, %4, %5, %6, %7, "                                   \
        " %8, %9, %10, %11, %12, %13, %14, %15, "                             \
        " %16, %17, %18, %19, %20, %21, %22, %23, "                           \
        " %24, %25, %26, %27, %28, %29, %30, %31}, [%32];"                    \
        : "=r"((r)[0]),  "=r"((r)[1]),  "=r"((r)[2]),  "=r"((r)[3]),          \
          "=r"((r)[4]),  "=r"((r)[5]),  "=r"((r)[6]),  "=r"((r)[7]),          \
          "=r"((r)[8]),  "=r"((r)[9]),  "=r"((r)[10]), "=r"((r)[11]),         \
          "=r"((r)[12]), "=r"((r)[13]), "=r"((r)[14]), "=r"((r)[15]),         \
          "=r"((r)[16]), "=r"((r)[17]), "=r"((r)[18]), "=r"((r)[19]),         \
          "=r"((r)[20]), "=r"((r)[21]), "=r"((r)[22]), "=r"((r)[23]),         \
          "=r"((r)[24]), "=r"((r)[25]), "=r"((r)[26]), "=r"((r)[27]),         \
          "=r"((r)[28]), "=r"((r)[29]), "=r"((r)[30]), "=r"((r)[31])          \
        : "r"(tm))

#define MAKE_DESC(base) \
    ((uint64_t(2) << 61) | (uint64_t(1) << 46) | (uint64_t(64) << 32) | \
     (uint64_t(1) << 16) | ((uint64_t)((base) >> 4) & 0x3FFF))

__device__ __forceinline__ void mma_ss_f16(uint32_t d, uint64_t ad, uint64_t bd,
                                           uint32_t idesc, uint32_t en) {
    asm volatile(
        "{\n\t.reg .pred p;\n\t"
        "setp.ne.u32 p, %4, 0;\n\t"
        "tcgen05.mma.cta_group::1.kind::f16 [%0], %1, %2, %3, {%5, %5, %5, %5}, p;\n\t}"
        :: "r"(d), "l"(ad), "l"(bd), "r"(idesc), "r"(en), "r"(0u) : "memory");
}

#define IDESC_N128 (0x10u | 0x80u | 0x400u | (16u << 17) | (8u << 24))
#define IDESC_N64  (0x10u | 0x80u | 0x400u | (8u  << 17) | (8u << 24))

__device__ __forceinline__ void split2(float x, float y, uint32_t& hi, uint32_t& lo) {
    __nv_bfloat162 h = __floats2bfloat162_rn(x, y);
    float hx = __bfloat162float(__low2bfloat16(h));
    float hy = __bfloat162float(__high2bfloat16(h));
    __nv_bfloat162 l = __floats2bfloat162_rn(x - hx, y - hy);
    hi = *reinterpret_cast<uint32_t*>(&h);
    lo = *reinterpret_cast<uint32_t*>(&l);
}
#endif  // HAS_TCGEN05

// ---------------------------------------------------------------------------
// tcgen05 bf16x3 GEMM — 3-stage cp.async pipeline, 3 MMA mbars.
// ---------------------------------------------------------------------------
#define ST_TILE 16384
#define ST_STAGE 65536
#define SMEM_GEMM (1024 + 1024 + 3 * ST_STAGE)   // 198656

__global__ __launch_bounds__(256, 1)
void gemm_bf16x3_kernel(const __nv_bfloat16* __restrict__ Ah,
                        const __nv_bfloat16* __restrict__ Al,
                        const __nv_bfloat16* __restrict__ Bh,
                        const __nv_bfloat16* __restrict__ Bl,
                        const float* __restrict__ bias,
                        float* __restrict__ C, int N, int K)
{
#if HAS_TCGEN05
    extern __shared__ char smem[];
    uint32_t sb = smem_u32(smem);
    uint32_t ab = (sb + 1023u) & ~1023u;
    char* smp = smem + (ab - sb);

    int tid = threadIdx.x;
    int wid = tid >> 5, lid = tid & 31;
    int rowBase = blockIdx.y * 128;
    int colBase = blockIdx.x * 128;

    if (wid == 0) TC_ALLOC(ab + 0, 128);
    if (tid == 0) { MBAR_INIT(ab + 8, 1); MBAR_INIT(ab + 16, 1); MBAR_INIT(ab + 24, 1); }
    __syncthreads();
    uint32_t tmem;
    asm volatile("ld.shared.b32 %0, [%1];" : "=r"(tmem) : "r"(ab + 0));

    const int KC = K >> 6;
    const size_t rowK = (size_t)K;

    const __nv_bfloat16* srcs[4] = { Ah, Al, Bh, Bl };
    const int bases[4] = { rowBase, rowBase, colBase, colBase };

    // per-thread fixed (row, col16) assignment within a 128x64 tile
    // 1024 16B-vectors per tile, 4 per thread
    auto load_stage = [&](int kc, int buf) {
        uint32_t stbase = ab + 1024 + buf * ST_STAGE;
        #pragma unroll
        for (int tl = 0; tl < 4; tl++) {
            const char* g = reinterpret_cast<const char*>(
                srcs[tl] + (size_t)bases[tl] * rowK + kc * 64);
            uint32_t tb = stbase + tl * ST_TILE;
            #pragma unroll
            for (int t = 0; t < 4; t++) {
                int i = tid + t * 256;
                int r = i >> 3, c = i & 7;
                uint32_t bo = r * 128 + c * 16;
                CP_ASYNC16(tb + SWZ128(bo), g + (size_t)r * (rowK * 2) + c * 16);
            }
        }
    };

    // prologue: stages 0,1,2 in flight
    #pragma unroll
    for (int s = 0; s < 3; s++) { load_stage(s, s); CP_COMMIT(); }

    int ph[3] = { 0, 0, 0 };

    for (int kc = 0; kc < KC; kc++) {
        int buf = kc - (kc / 3) * 3;
        CP_WAIT2();              // stage kc's group complete (2 newer pending)
        __syncthreads();
        FENCE_ASYNC();

        uint32_t stage = ab + 1024 + buf * ST_STAGE;
        if (wid == 0 && elect_one()) {
            uint64_t ahd = MAKE_DESC(stage + 0 * ST_TILE);
            uint64_t ald = MAKE_DESC(stage + 1 * ST_TILE);
            uint64_t bhd = MAKE_DESC(stage + 2 * ST_TILE);
            uint64_t bld = MAKE_DESC(stage + 3 * ST_TILE);
            #pragma unroll
            for (int ks = 0; ks < 4; ks++) {
                uint64_t off = ks * 2;
                mma_ss_f16(tmem, ahd + off, bhd + off, IDESC_N128,
                           (kc == 0 && ks == 0) ? 0u : 1u);
                mma_ss_f16(tmem, ahd + off, bld + off, IDESC_N128, 1u);
                mma_ss_f16(tmem, ald + off, bhd + off, IDESC_N128, 1u);
            }
            TC_COMMIT(ab + 8 + 8 * buf);
        }

        // refill this buffer with stage kc+3 once MMA(kc) has drained it
        if (kc + 3 < KC) {
            MBAR_WAIT(ab + 8 + 8 * buf, ph[buf] & 1); ph[buf]++;
            load_stage(kc + 3, buf);
        }
        CP_COMMIT();             // real or dummy — keeps group accounting exact
    }
    // drain: each mbar has exactly one outstanding commit
    MBAR_WAIT(ab + 8,  ph[0] & 1);
    MBAR_WAIT(ab + 16, ph[1] & 1);
    MBAR_WAIT(ab + 24, ph[2] & 1);
    TC_FENCE_AFTER();

    float* Ct = reinterpret_cast<float*>(smp + 1024);
    if (wid < 4) {
        int row = wid * 32 + lid;
        #pragma unroll
        for (int cb = 0; cb < 4; cb++) {
            uint32_t r[32];
            TC_LD_X32(r, tmem + cb * 32);
            TC_WAIT_LD();
            #pragma unroll
            for (int j = 0; j < 32; j++)
                Ct[row * 129 + cb * 32 + j] = __uint_as_float(r[j]);
        }
        TC_FENCE_BEFORE();
    }
    __syncthreads();

    for (int i = tid; i < 128 * 32; i += 256) {
        int r = i >> 5, c = (i & 31) * 4;
        float4 v;
        v.x = Ct[r * 129 + c + 0] + bias[colBase + c + 0];
        v.y = Ct[r * 129 + c + 1] + bias[colBase + c + 1];
        v.z = Ct[r * 129 + c + 2] + bias[colBase + c + 2];
        v.w = Ct[r * 129 + c + 3] + bias[colBase + c + 3];
        *reinterpret_cast<float4*>(&C[(size_t)(rowBase + r) * N + colBase + c]) = v;
    }

    __syncthreads();
    if (wid == 0) { TC_RELINQ(); TC_DEALLOC(tmem, 128); }
#endif
}

// ---------------------------------------------------------------------------
// tcgen05 attention, kv-tile = 64, ~99KB smem => 2 CTAs/SM.
// ---------------------------------------------------------------------------
#define AT_Q_H  2048
#define AT_Q_L  (AT_Q_H  + 16384)    // 18432
#define AT_K_H  (AT_Q_L  + 16384)    // 34816  (64x64: 8KB)
#define AT_K_L  (AT_K_H  + 8192)     // 43008
#define AT_VT_H (AT_K_L  + 8192)     // 51200  (64d x 64kv: 8KB)
#define AT_VT_L (AT_VT_H + 8192)     // 59392
#define AT_P_H  (AT_VT_L + 8192)     // 67584  (128q x 64kv: 16KB)
#define AT_P_L  (AT_P_H  + 16384)    // 83968
#define SMEM_ATTN (AT_P_L + 16384 + 1024)   // 101376

#if HAS_TCGEN05
__device__ __forceinline__ void attn_load_k64(char* smp, int b, int h, int kt, int tid)
{
    const int RS = 3 * DIMC;
    const float* ksrc = g_qkv + ((size_t)(b * SEQ + kt * 64)) * RS + DIMC + h * HDIM;
    #pragma unroll
    for (int t = 0; t < 2; t++) {
        int i = tid + t * 256;           // 512 items: r 0..63, g 0..7
        int r = i >> 3, g = i & 7;
        const float4* p = reinterpret_cast<const float4*>(ksrc + (size_t)r * RS + g * 8);
        float4 a = p[0], c = p[1];
        uint4 hi, lo;
        split2(a.x, a.y, hi.x, lo.x); split2(a.z, a.w, hi.y, lo.y);
        split2(c.x, c.y, hi.z, lo.z); split2(c.z, c.w, hi.w, lo.w);
        uint32_t off = SWZ128((uint32_t)(r * 128 + g * 16));
        *reinterpret_cast<uint4*>(smp + AT_K_H + off) = hi;
        *reinterpret_cast<uint4*>(smp + AT_K_L + off) = lo;
    }
}

__device__ __forceinline__ void attn_load_v64(char* smp, int b, int h, int kt, int tid)
{
    const int RS = 3 * DIMC;
    const float* vsrc = g_qkv + ((size_t)(b * SEQ + kt * 64)) * RS + 2 * DIMC + h * HDIM;
    #pragma unroll
    for (int t = 0; t < 4; t++) {
        int i = tid + t * 256;           // 1024 items: r(kv) 0..63, g 0..15
        int r = i >> 4, g = i & 15;
        float4 v = *reinterpret_cast<const float4*>(vsrc + (size_t)r * RS + g * 4);
        float vals[4] = { v.x, v.y, v.z, v.w };
        #pragma unroll
        for (int j = 0; j < 4; j++) {
            int d = g * 4 + j;
            __nv_bfloat16 hv = __float2bfloat16(vals[j]);
            __nv_bfloat16 lv = __float2bfloat16(vals[j] - __bfloat162float(hv));
            uint32_t off = SWZ128((uint32_t)(d * 128 + r * 2));
            *reinterpret_cast<__nv_bfloat16*>(smp + AT_VT_H + off) = hv;
            *reinterpret_cast<__nv_bfloat16*>(smp + AT_VT_L + off) = lv;
        }
    }
}
#endif

__global__ __launch_bounds__(256, 2)
void attn_tc_kernel()
{
#if HAS_TCGEN05
    extern __shared__ char smem[];
    uint32_t sb = smem_u32(smem);
    uint32_t ab = (sb + 1023u) & ~1023u;
    char* smp = smem + (ab - sb);

    int tid = threadIdx.x;
    int wid = tid >> 5, lane = tid & 31;
    int sub = wid & 3, half = wid >> 2;
    int row = sub * 32 + lane;
    int qt = blockIdx.x, h = blockIdx.y, b = blockIdx.z;
    const int RS = 3 * DIMC;

    if (wid == 0) TC_ALLOC(ab + 0, 128);
    if (tid == 0) { MBAR_INIT(ab + 8, 1); MBAR_INIT(ab + 16, 1); }  // S, O
    __syncthreads();
    uint32_t tmem;
    asm volatile("ld.shared.b32 %0, [%1];" : "=r"(tmem) : "r"(ab + 0));

    // ---- load Q tile [128 x 64] ----
    {
        const float* qsrc = g_qkv + ((size_t)(b * SEQ + qt * 128)) * RS + h * HDIM;
        #pragma unroll
        for (int t = 0; t < 4; t++) {
            int i = tid + t * 256;
            int r = i >> 3, g = i & 7;
            const float4* p = reinterpret_cast<const float4*>(qsrc + (size_t)r * RS + g * 8);
            float4 a = p[0], c = p[1];
            uint4 hi, lo;
            split2(a.x, a.y, hi.x, lo.x); split2(a.z, a.w, hi.y, lo.y);
            split2(c.x, c.y, hi.z, lo.z); split2(c.z, c.w, hi.w, lo.w);
            uint32_t off = SWZ128((uint32_t)(r * 128 + g * 16));
            *reinterpret_cast<uint4*>(smp + AT_Q_H + off) = hi;
            *reinterpret_cast<uint4*>(smp + AT_Q_L + off) = lo;
        }
    }
    attn_load_k64(smp, b, h, 0, tid);

    float rsum = 0.f;
    const float scale = 0.125f;

    for (int kt = 0; kt < 16; kt++) {
        __syncthreads();
        FENCE_ASYNC();

        // ---- issue S = Q K^T  (S in TMEM cols 0..63) ----
        if (wid == 0 && elect_one()) {
            uint64_t qh = MAKE_DESC(ab + AT_Q_H), ql = MAKE_DESC(ab + AT_Q_L);
            uint64_t kh = MAKE_DESC(ab + AT_K_H), kl = MAKE_DESC(ab + AT_K_L);
            #pragma unroll
            for (int ks = 0; ks < 4; ks++) {
                uint64_t off = ks * 2;
                mma_ss_f16(tmem, qh + off, kh + off, IDESC_N64, ks > 0 ? 1u : 0u);
                mma_ss_f16(tmem, qh + off, kl + off, IDESC_N64, 1u);
                mma_ss_f16(tmem, ql + off, kh + off, IDESC_N64, 1u);
            }
            TC_COMMIT(ab + 8);
        }

        // ---- wait O(kt-1) (frees Vt, P), load V(kt) under S-MMA ----
        if (kt > 0) MBAR_WAIT(ab + 16, (kt - 1) & 1);
        attn_load_v64(smp, b, h, kt, tid);

        // ---- wait S(kt), exp + split P ----
        MBAR_WAIT(ab + 8, kt & 1);
        TC_FENCE_AFTER();
        {
            uint32_t r0[32];
            TC_LD_X32(r0, tmem + half * 32);
            TC_WAIT_LD();
            char* pH = smp + AT_P_H;
            char* pL = smp + AT_P_L;
            #pragma unroll
            for (int g = 0; g < 4; g++) {
                float e[8];
                #pragma unroll
                for (int j = 0; j < 8; j++) {
                    float s = __uint_as_float(r0[g * 8 + j]);
                    e[j] = __expf(s * scale);
                    rsum += e[j];
                }
                uint4 hi, lo;
                split2(e[0], e[1], hi.x, lo.x); split2(e[2], e[3], hi.y, lo.y);
                split2(e[4], e[5], hi.z, lo.z); split2(e[6], e[7], hi.w, lo.w);
                uint32_t off = SWZ128((uint32_t)(row * 128 + (half * 32 + g * 8) * 2));
                *reinterpret_cast<uint4*>(pH + off) = hi;
                *reinterpret_cast<uint4*>(pL + off) = lo;
            }
            TC_FENCE_BEFORE();
        }
        __syncthreads();
        FENCE_ASYNC();

        // ---- issue O += P V  (O in TMEM cols 64..127) ----
        if (wid == 0 && elect_one()) {
            uint64_t ph_ = MAKE_DESC(ab + AT_P_H);
            uint64_t pl_ = MAKE_DESC(ab + AT_P_L);
            uint64_t vh  = MAKE_DESC(ab + AT_VT_H);
            uint64_t vl  = MAKE_DESC(ab + AT_VT_L);
            #pragma unroll
            for (int ks = 0; ks < 4; ks++) {
                uint64_t off = ks * 2;
                uint32_t acc = (kt == 0 && ks == 0) ? 0u : 1u;
                mma_ss_f16(tmem + 64, ph_ + off, vh + off, IDESC_N64, acc);
                mma_ss_f16(tmem + 64, ph_ + off, vl + off, IDESC_N64, 1u);
                mma_ss_f16(tmem + 64, pl_ + off, vh + off, IDESC_N64, 1u);
            }
            TC_COMMIT(ab + 16);
        }

        // ---- prefetch K(kt+1) under O-MMA ----
        if (kt < 15) attn_load_k64(smp, b, h, kt + 1, tid);
    }
    MBAR_WAIT(ab + 16, 15 & 1);
    TC_FENCE_AFTER();

    // ---- normalize O and write out ----
    float* rs = reinterpret_cast<float*>(smp + 512);   // [2][128]
    rs[half * 128 + row] = rsum;
    __syncthreads();

    {
        uint32_t o[32];
        TC_LD_X32(o, tmem + 64 + half * 32);
        TC_WAIT_LD();
        TC_FENCE_BEFORE();
        float inv = 1.0f / (rs[row] + rs[128 + row]);
        float* dst = g_attn + ((size_t)(b * SEQ + qt * 128 + row)) * DIMC + h * HDIM + half * 32;
        #pragma unroll
        for (int j = 0; j < 32; j += 4) {
            float4 v;
            v.x = __uint_as_float(o[j + 0]) * inv;
            v.y = __uint_as_float(o[j + 1]) * inv;
            v.z = __uint_as_float(o[j + 2]) * inv;
            v.w = __uint_as_float(o[j + 3]) * inv;
            *reinterpret_cast<float4*>(dst + j) = v;
        }
    }

    __syncthreads();
    if (wid == 0) { TC_RELINQ(); TC_DEALLOC(tmem, 128); }
#endif  // HAS_TCGEN05
}

// ---------------------------------------------------------------------------
// fp32 fallbacks (proven round-1 kernels)
// ---------------------------------------------------------------------------
__global__ __launch_bounds__(256)
void sgemm_bias_kernel(const float* __restrict__ A, const float* __restrict__ Bm,
                       const float* __restrict__ bias, float* __restrict__ C,
                       int M, int N, int K)
{
    const int BK = 16, PAD = 132;
    __shared__ float As[BK * PAD];
    __shared__ float Bs[BK * PAD];

    int tid = threadIdx.x;
    int tx = tid & 15, ty = tid >> 4;
    int rowBase = blockIdx.y * 128;
    int colBase = blockIdx.x * 128;

    float acc[8][8] = {};

    for (int k0 = 0; k0 < K; k0 += BK) {
        #pragma unroll
        for (int t = 0; t < 2; t++) {
            int i  = tid + t * 256;
            int r  = i >> 2;
            int kq = (i & 3) << 2;
            float4 v = *reinterpret_cast<const float4*>(
                &A[(size_t)(rowBase + r) * K + k0 + kq]);
            As[(kq + 0) * PAD + r] = v.x;
            As[(kq + 1) * PAD + r] = v.y;
            As[(kq + 2) * PAD + r] = v.z;
            As[(kq + 3) * PAD + r] = v.w;
        }
        #pragma unroll
        for (int t = 0; t < 2; t++) {
            int i  = tid + t * 256;
            int kk = i >> 5;
            int n4 = (i & 31) << 2;
            float4 v = *reinterpret_cast<const float4*>(
                &Bm[(size_t)(k0 + kk) * N + colBase + n4]);
            *reinterpret_cast<float4*>(&Bs[kk * PAD + n4]) = v;
        }
        __syncthreads();

        #pragma unroll
        for (int kk = 0; kk < BK; kk++) {
            float a[8], b[8];
            *(float4*)&a[0] = *(float4*)&As[kk * PAD + ty * 8];
            *(float4*)&a[4] = *(float4*)&As[kk * PAD + ty * 8 + 4];
            *(float4*)&b[0] = *(float4*)&Bs[kk * PAD + tx * 8];
            *(float4*)&b[4] = *(float4*)&Bs[kk * PAD + tx * 8 + 4];
            #pragma unroll
            for (int i = 0; i < 8; i++)
                #pragma unroll
                for (int j = 0; j < 8; j++)
                    acc[i][j] += a[i] * b[j];
        }
        __syncthreads();
    }

    #pragma unroll
    for (int i = 0; i < 8; i++) {
        int r = rowBase + ty * 8 + i;
        #pragma unroll
        for (int j = 0; j < 8; j += 4) {
            int c = colBase + tx * 8 + j;
            float4 v;
            v.x = acc[i][j + 0] + bias[c + 0];
            v.y = acc[i][j + 1] + bias[c + 1];
            v.z = acc[i][j + 2] + bias[c + 2];
            v.w = acc[i][j + 3] + bias[c + 3];
            *reinterpret_cast<float4*>(&C[(size_t)r * N + c]) = v;
        }
    }
}

__global__ __launch_bounds__(256)
void attn_kernel()
{
    extern __shared__ float sm[];
    float* Qs  = sm;
    float* Ks  = Qs + 64 * 64;
    float* Vs  = Ks + 64 * 65;
    float* Ss  = Vs + 64 * 64;
    float* m_s = Ss + 64 * 65;
    float* l_s = m_s + 64;
    float* a_s = l_s + 64;

    int qt = blockIdx.x, h = blockIdx.y, b = blockIdx.z;
    int tid = threadIdx.x;
    int tx = tid & 15, ty = tid >> 4;
    const float scale = 0.125f;
    const int RS = 3 * DIMC;

    size_t qoff = ((size_t)(b * SEQ + qt * 64)) * RS + h * HDIM;

    #pragma unroll
    for (int t = 0; t < 4; t++) {
        int i  = tid + t * 256;
        int r  = i >> 4;
        int d4 = (i & 15) << 2;
        float4 v = *reinterpret_cast<const float4*>(&g_qkv[qoff + (size_t)r * RS + d4]);
        *reinterpret_cast<float4*>(&Qs[r * 64 + d4]) = v;
    }
    if (tid < 64) { m_s[tid] = -1e30f; l_s[tid] = 0.f; }
    float O[4][4] = {};
    __syncthreads();

    for (int kt = 0; kt < 16; kt++) {
        size_t koff = ((size_t)(b * SEQ + kt * 64)) * RS + DIMC + h * HDIM;
        size_t voff = koff + DIMC;
        #pragma unroll
        for (int t = 0; t < 4; t++) {
            int i  = tid + t * 256;
            int r  = i >> 4;
            int d4 = (i & 15) << 2;
            float4 kv = *reinterpret_cast<const float4*>(&g_qkv[koff + (size_t)r * RS + d4]);
            Ks[r * 65 + d4 + 0] = kv.x;
            Ks[r * 65 + d4 + 1] = kv.y;
            Ks[r * 65 + d4 + 2] = kv.z;
            Ks[r * 65 + d4 + 3] = kv.w;
            float4 vv = *reinterpret_cast<const float4*>(&g_qkv[voff + (size_t)r * RS + d4]);
            *reinterpret_cast<float4*>(&Vs[r * 64 + d4]) = vv;
        }
        __syncthreads();

        float s[4][4] = {};
        #pragma unroll 8
        for (int d = 0; d < 64; d++) {
            float qv[4], kv[4];
            #pragma unroll
            for (int i = 0; i < 4; i++) qv[i] = Qs[(ty * 4 + i) * 64 + d];
            #pragma unroll
            for (int j = 0; j < 4; j++) kv[j] = Ks[(tx * 4 + j) * 65 + d];
            #pragma unroll
            for (int i = 0; i < 4; i++)
                #pragma unroll
                for (int j = 0; j < 4; j++)
                    s[i][j] += qv[i] * kv[j];
        }
        #pragma unroll
        for (int i = 0; i < 4; i++)
            #pragma unroll
            for (int j = 0; j < 4; j++)
                Ss[(ty * 4 + i) * 65 + tx * 4 + j] = s[i][j] * scale;
        __syncthreads();

        if (tid < 64) {
            float mold = m_s[tid];
            float mx = mold;
            #pragma unroll 8
            for (int j = 0; j < 64; j++) mx = fmaxf(mx, Ss[tid * 65 + j]);
            float sum = 0.f;
            #pragma unroll 8
            for (int j = 0; j < 64; j++) {
                float p = __expf(Ss[tid * 65 + j] - mx);
                Ss[tid * 65 + j] = p;
                sum += p;
            }
            float alpha = __expf(mold - mx);
            a_s[tid] = alpha;
            m_s[tid] = mx;
            l_s[tid] = l_s[tid] * alpha + sum;
        }
        __syncthreads();

        float alpha[4];
        #pragma unroll
        for (int i = 0; i < 4; i++) alpha[i] = a_s[ty * 4 + i];
        #pragma unroll
        for (int i = 0; i < 4; i++)
            #pragma unroll
            for (int j = 0; j < 4; j++)
                O[i][j] *= alpha[i];
        #pragma unroll 8
        for (int kv = 0; kv < 64; kv++) {
            float p[4], v[4];
            #pragma unroll
            for (int i = 0; i < 4; i++) p[i] = Ss[(ty * 4 + i) * 65 + kv];
            #pragma unroll
            for (int j = 0; j < 4; j++) v[j] = Vs[kv * 64 + tx * 4 + j];
            #pragma unroll
            for (int i = 0; i < 4; i++)
                #pragma unroll
                for (int j = 0; j < 4; j++)
                    O[i][j] += p[i] * v[j];
        }
        __syncthreads();
    }

    float inv_l[4];
    #pragma unroll
    for (int i = 0; i < 4; i++) inv_l[i] = 1.0f / l_s[ty * 4 + i];
    #pragma unroll
    for (int i = 0; i < 4; i++) {
        int q = qt * 64 + ty * 4 + i;
        size_t off = ((size_t)(b * SEQ + q)) * DIMC + h * HDIM + tx * 4;
        float4 v;
        v.x = O[i][0] * inv_l[i];
        v.y = O[i][1] * inv_l[i];
        v.z = O[i][2] * inv_l[i];
        v.w = O[i][3] * inv_l[i];
        *reinterpret_cast<float4*>(&g_attn[off]) = v;
    }
}

// ---------------------------------------------------------------------------

extern "C" void kernel_launch(void* const* d_in, const int* in_sizes, int n_in,
                              void* d_out, int out_size)
{
    const float* x     = (const float*)d_in[0];
    const float* Wqkv  = (const float*)d_in[1];
    const float* bqkv  = (const float*)d_in[2];
    const float* Wproj = (const float*)d_in[3];
    const float* bproj = (const float*)d_in[4];
    float* out = (float*)d_out;

    float *qkv = nullptr, *attn = nullptr;
    __nv_bfloat16 *ah, *al, *wqh, *wql, *wph, *wpl;
    cudaGetSymbolAddress((void**)&qkv,  g_qkv);
    cudaGetSymbolAddress((void**)&attn, g_attn);
    cudaGetSymbolAddress((void**)&ah,   g_ah);
    cudaGetSymbolAddress((void**)&al,   g_al);
    cudaGetSymbolAddress((void**)&wqh,  g_wqh);
    cudaGetSymbolAddress((void**)&wql,  g_wql);
    cudaGetSymbolAddress((void**)&wph,  g_wph);
    cudaGetSymbolAddress((void**)&wpl,  g_wpl);

    cudaFuncAttributes pa{};
    cudaFuncGetAttributes(&pa, feat_probe);
    bool use_tc = pa.sharedSizeBytes >= 1024;

    dim3 blk(256);

    if (use_tc) {
        cudaFuncSetAttribute(gemm_bf16x3_kernel,
                             cudaFuncAttributeMaxDynamicSharedMemorySize, SMEM_GEMM);
        cudaFuncSetAttribute(attn_tc_kernel,
                             cudaFuncAttributeMaxDynamicSharedMemorySize, SMEM_ATTN);

        int n4 = MTOT * DIMC / 4;
        split_kernel<<<(n4 + 255) / 256, 256>>>(x, ah, al, n4);
        dim3 tb(32, 32);
        transpose_split_kernel<<<dim3(NQKV / 32, DIMC / 32), tb>>>(Wqkv, wqh, wql, DIMC, NQKV);
        transpose_split_kernel<<<dim3(DIMC / 32, DIMC / 32), tb>>>(Wproj, wph, wpl, DIMC, DIMC);

        dim3 g1(NQKV / 128, MTOT / 128);
        gemm_bf16x3_kernel<<<g1, blk, SMEM_GEMM>>>(ah, al, wqh, wql, bqkv, qkv, NQKV, DIMC);

        dim3 g2(SEQ / 128, NHEAD, BATCH);
        attn_tc_kernel<<<g2, blk, SMEM_ATTN>>>();

        split_kernel<<<(n4 + 255) / 256, 256>>>(attn, ah, al, n4);
        dim3 g3(DIMC / 128, MTOT / 128);
        gemm_bf16x3_kernel<<<g3, blk, SMEM_GEMM>>>(ah, al, wph, wpl, bproj, out, DIMC, DIMC);
    } else {
        const int ATTN_SMEM = (64*64 + 64*65 + 64*64 + 64*65 + 3*64) * 4;
        cudaFuncSetAttribute(attn_kernel,
                             cudaFuncAttributeMaxDynamicSharedMemorySize, ATTN_SMEM);
        dim3 g1(NQKV / 128, MTOT / 128);
        sgemm_bias_kernel<<<g1, blk>>>(x, Wqkv, bqkv, qkv, MTOT, NQKV, DIMC);

        dim3 g2(SEQ / 64, NHEAD, BATCH);
        attn_kernel<<<g2, blk, ATTN_SMEM>>>();

        dim3 g3(DIMC / 128, MTOT / 128);
        sgemm_bias_kernel<<<g3, blk>>>(attn, Wproj, bproj, out, MTOT, DIMC, DIMC);
    }
}

// round 8
// speedup vs baseline: 1.3637x; 1.3637x over previous
#include <cuda_runtime.h>
#include <cuda_bf16.h>
#include <math.h>
#include <stdint.h>

#define DIMC 768
#define NHEAD 12
#define HDIM 64
#define BATCH 8
#define SEQ 1024
#define MTOT (BATCH*SEQ)   // 8192
#define NQKV (3*DIMC)      // 2304

#if defined(__CUDA_ARCH__) && (defined(__CUDA_ARCH_FEAT_SM103_ALL) || defined(__CUDA_ARCH_FEAT_SM100_ALL))
#define HAS_TCGEN05 1
#else
#define HAS_TCGEN05 0
#endif

// ---------------------------------------------------------------------------
// Scratch
// ---------------------------------------------------------------------------
__device__ __align__(16) float g_qkv[(size_t)MTOT * NQKV];      // fallback path only
__device__ __align__(16) float g_attn[(size_t)MTOT * DIMC];     // fallback path only
__device__ __align__(16) __nv_bfloat16 g_ah[(size_t)MTOT * DIMC];
__device__ __align__(16) __nv_bfloat16 g_al[(size_t)MTOT * DIMC];
__device__ __align__(16) __nv_bfloat16 g_wqh[(size_t)NQKV * DIMC];
__device__ __align__(16) __nv_bfloat16 g_wql[(size_t)NQKV * DIMC];
__device__ __align__(16) __nv_bfloat16 g_wph[(size_t)DIMC * DIMC];
__device__ __align__(16) __nv_bfloat16 g_wpl[(size_t)DIMC * DIMC];
// attention-ready operands (tc path): Q,K token-major [b,h,tok,64]; V^T blocks
__device__ __align__(16) __nv_bfloat16 g_q_h[(size_t)BATCH * NHEAD * SEQ * HDIM];
__device__ __align__(16) __nv_bfloat16 g_q_l[(size_t)BATCH * NHEAD * SEQ * HDIM];
__device__ __align__(16) __nv_bfloat16 g_k_h[(size_t)BATCH * NHEAD * SEQ * HDIM];
__device__ __align__(16) __nv_bfloat16 g_k_l[(size_t)BATCH * NHEAD * SEQ * HDIM];
__device__ __align__(16) __nv_bfloat16 g_vt_h[(size_t)BATCH * NHEAD * SEQ * HDIM];
__device__ __align__(16) __nv_bfloat16 g_vt_l[(size_t)BATCH * NHEAD * SEQ * HDIM];

// ---------------------------------------------------------------------------
// Probe kernel (host dispatch signal)
// ---------------------------------------------------------------------------
__global__ void feat_probe(int* out) {
#if HAS_TCGEN05
    __shared__ int s[256];
#else
    __shared__ int s[2];
#endif
    int n = (int)(sizeof(s) / sizeof(int));
    s[threadIdx.x % n] = (int)clock();
    __syncthreads();
    if (out) *out = s[0];
}

// ---------------------------------------------------------------------------
// Split fp32 -> bf16 hi/lo
// ---------------------------------------------------------------------------
__global__ __launch_bounds__(256)
void split_kernel(const float* __restrict__ src, __nv_bfloat16* __restrict__ hi,
                  __nv_bfloat16* __restrict__ lo, int n4)
{
    int i = blockIdx.x * blockDim.x + threadIdx.x;
    if (i >= n4) return;
    float4 v = reinterpret_cast<const float4*>(src)[i];
    __nv_bfloat16 h0 = __float2bfloat16(v.x);
    __nv_bfloat16 h1 = __float2bfloat16(v.y);
    __nv_bfloat16 h2 = __float2bfloat16(v.z);
    __nv_bfloat16 h3 = __float2bfloat16(v.w);
    __nv_bfloat16 l0 = __float2bfloat16(v.x - __bfloat162float(h0));
    __nv_bfloat16 l1 = __float2bfloat16(v.y - __bfloat162float(h1));
    __nv_bfloat16 l2 = __float2bfloat16(v.z - __bfloat162float(h2));
    __nv_bfloat16 l3 = __float2bfloat16(v.w - __bfloat162float(h3));
    __nv_bfloat162* ph = reinterpret_cast<__nv_bfloat162*>(hi);
    __nv_bfloat162* pl = reinterpret_cast<__nv_bfloat162*>(lo);
    ph[2*i]   = __nv_bfloat162{h0, h1};
    ph[2*i+1] = __nv_bfloat162{h2, h3};
    pl[2*i]   = __nv_bfloat162{l0, l1};
    pl[2*i+1] = __nv_bfloat162{l2, l3};
}

__global__ __launch_bounds__(1024)
void transpose_split_kernel(const float* __restrict__ W,
                            __nv_bfloat16* __restrict__ hiT,
                            __nv_bfloat16* __restrict__ loT, int K, int N)
{
    __shared__ float t[32][33];
    int n0 = blockIdx.x * 32, k0 = blockIdx.y * 32;
    int tx = threadIdx.x, ty = threadIdx.y;
    t[ty][tx] = W[(size_t)(k0 + ty) * N + n0 + tx];
    __syncthreads();
    float v = t[tx][ty];
    __nv_bfloat16 h = __float2bfloat16(v);
    __nv_bfloat16 l = __float2bfloat16(v - __bfloat162float(h));
    size_t off = (size_t)(n0 + ty) * K + k0 + tx;
    hiT[off] = h;
    loT[off] = l;
}

// ---------------------------------------------------------------------------
// helpers
// ---------------------------------------------------------------------------
__device__ __forceinline__ uint32_t smem_u32(const void* p) {
    uint32_t a;
    asm("{ .reg .u64 t; cvta.to.shared.u64 t, %1; cvt.u32.u64 %0, t; }"
        : "=r"(a) : "l"(p));
    return a;
}

#define SWZ128(o) ((o) ^ (((o) >> 3) & 0x70))

#define MBAR_INIT(addr, cnt) \
    asm volatile("mbarrier.init.shared.b64 [%0], %1;" :: "r"(addr), "r"(cnt) : "memory")

#define MBAR_WAIT(addr, parity) do {                                          \
    uint32_t _m = (addr); uint32_t _p = (parity); uint32_t _done;             \
    asm volatile("{\n\t.reg .pred p;\n\t"                                     \
        "mbarrier.try_wait.parity.acquire.cta.shared::cta.b64 p, [%1], %2;\n\t"\
        "selp.b32 %0, 1, 0, p;\n\t}" : "=r"(_done) : "r"(_m), "r"(_p) : "memory");\
    if (!_done) {                                                             \
        asm volatile("{\n\t.reg .pred P1;\n\t"                                \
            "WL_%=:\n\t"                                                      \
            "mbarrier.try_wait.parity.acquire.cta.shared::cta.b64 P1, [%0], %1, 0x989680;\n\t"\
            "@P1 bra.uni WD_%=;\n\t"                                          \
            "bra.uni WL_%=;\n\t"                                              \
            "WD_%=:\n\t}" :: "r"(_m), "r"(_p) : "memory");                    \
    }                                                                         \
} while (0)

#if HAS_TCGEN05
__device__ __forceinline__ uint32_t elect_one() {
    uint32_t pred;
    asm volatile("{\n\t.reg .pred p;\n\telect.sync _|p, 0xFFFFFFFF;\n\t"
                 "selp.b32 %0, 1, 0, p;\n\t}" : "=r"(pred));
    return pred;
}

#define TC_ALLOC(sm_dst, ncols) \
    asm volatile("tcgen05.alloc.cta_group::1.sync.aligned.shared::cta.b32 [%0], %1;" \
                 :: "r"(sm_dst), "r"(ncols) : "memory")
#define TC_DEALLOC(tm, ncols) \
    asm volatile("tcgen05.dealloc.cta_group::1.sync.aligned.b32 %0, %1;" :: "r"(tm), "r"(ncols))
#define TC_RELINQ() \
    asm volatile("tcgen05.relinquish_alloc_permit.cta_group::1.sync.aligned;")
#define TC_COMMIT(mbar) \
    asm volatile("tcgen05.commit.cta_group::1.mbarrier::arrive::one.shared::cluster.b64 [%0];" \
                 :: "r"(mbar) : "memory")
#define TC_FENCE_AFTER()  asm volatile("tcgen05.fence::after_thread_sync;" ::: "memory")
#define TC_FENCE_BEFORE() asm volatile("tcgen05.fence::before_thread_sync;" ::: "memory")
#define TC_WAIT_LD() asm volatile("tcgen05.wait::ld.sync.aligned;" ::: "memory")
#define FENCE_ASYNC() asm volatile("fence.proxy.async.shared::cta;" ::: "memory")

#define CP_ASYNC16(dst, src) \
    asm volatile("cp.async.cg.shared.global [%0], [%1], 16;" :: "r"(dst), "l"(src) : "memory")
#define CP_COMMIT() asm volatile("cp.async.commit_group;" ::: "memory")
#define CP_WAIT2()  asm volatile("cp.async.wait_group 2;" ::: "memory")
#define CP_WAIT0()  asm volatile("cp.async.wait_group 0;" ::: "memory")

#define TC_LD_X32(r, tm) \
    asm volatile("tcgen05.ld.sync.aligned.32x32b.x32.b32 "                    \
        "{%0, %1, %2, %3, %4, %5, %6, %7, "                                   \
        " %8, %9, %10, %11, %12, %13, %14, %15, "                             \
        " %16, %17, %18, %19, %20, %21, %22, %23, "                           \
        " %24, %25, %26, %27, %28, %29, %30, %31}, [%32];"                    \
        : "=r"((r)[0]),  "=r"((r)[1]),  "=r"((r)[2]),  "=r"((r)[3]),          \
          "=r"((r)[4]),  "=r"((r)[5]),  "=r"((r)[6]),  "=r"((r)[7]),          \
          "=r"((r)[8]),  "=r"((r)[9]),  "=r"((r)[10]), "=r"((r)[11]),         \
          "=r"((r)[12]), "=r"((r)[13]), "=r"((r)[14]), "=r"((r)[15]),         \
          "=r"((r)[16]), "=r"((r)[17]), "=r"((r)[18]), "=r"((r)[19]),         \
          "=r"((r)[20]), "=r"((r)[21]), "=r"((r)[22]), "=r"((r)[23]),         \
          "=r"((r)[24]), "=r"((r)[25]), "=r"((r)[26]), "=r"((r)[27]),         \
          "=r"((r)[28]), "=r"((r)[29]), "=r"((r)[30]), "=r"((r)[31])          \
        : "r"(tm))

#define MAKE_DESC(base) \
    ((uint64_t(2) << 61) | (uint64_t(1) << 46) | (uint64_t(64) << 32) | \
     (uint64_t(1) << 16) | ((uint64_t)((base) >> 4) & 0x3FFF))

__device__ __forceinline__ void mma_ss_f16(uint32_t d, uint64_t ad, uint64_t bd,
                                           uint32_t idesc, uint32_t en) {
    asm volatile(
        "{\n\t.reg .pred p;\n\t"
        "setp.ne.u32 p, %4, 0;\n\t"
        "tcgen05.mma.cta_group::1.kind::f16 [%0], %1, %2, %3, {%5, %5, %5, %5}, p;\n\t}"
        :: "r"(d), "l"(ad), "l"(bd), "r"(idesc), "r"(en), "r"(0u) : "memory");
}

#define IDESC_N128 (0x10u | 0x80u | 0x400u | (16u << 17) | (8u << 24))
#define IDESC_N64  (0x10u | 0x80u | 0x400u | (8u  << 17) | (8u << 24))

__device__ __forceinline__ void split2(float x, float y, uint32_t& hi, uint32_t& lo) {
    __nv_bfloat162 h = __floats2bfloat162_rn(x, y);
    float hx = __bfloat162float(__low2bfloat16(h));
    float hy = __bfloat162float(__high2bfloat16(h));
    __nv_bfloat162 l = __floats2bfloat162_rn(x - hx, y - hy);
    hi = *reinterpret_cast<uint32_t*>(&h);
    lo = *reinterpret_cast<uint32_t*>(&l);
}
#endif  // HAS_TCGEN05

// ---------------------------------------------------------------------------
// tcgen05 bf16x3 GEMM — 3-stage cp.async pipeline (proven round-7 mainloop).
// MODE 0: C = A@B^T + bias (fp32 out)
// MODE 1: QKV fused epilogue — writes Q/K token-major hi/lo and V^T blocks.
// ---------------------------------------------------------------------------
#define ST_TILE 16384
#define ST_STAGE 65536
#define SMEM_GEMM (1024 + 1024 + 3 * ST_STAGE)   // 198656

template<int MODE>
__global__ __launch_bounds__(256, 1)
void gemm_bf16x3_kernel(const __nv_bfloat16* __restrict__ Ah,
                        const __nv_bfloat16* __restrict__ Al,
                        const __nv_bfloat16* __restrict__ Bh,
                        const __nv_bfloat16* __restrict__ Bl,
                        const float* __restrict__ bias,
                        float* __restrict__ C, int N, int K,
                        __nv_bfloat16* qh, __nv_bfloat16* ql,
                        __nv_bfloat16* kh, __nv_bfloat16* kl,
                        __nv_bfloat16* vth, __nv_bfloat16* vtl)
{
#if HAS_TCGEN05
    extern __shared__ char smem[];
    uint32_t sb = smem_u32(smem);
    uint32_t ab = (sb + 1023u) & ~1023u;
    char* smp = smem + (ab - sb);

    int tid = threadIdx.x;
    int wid = tid >> 5, lid = tid & 31;
    int rowBase = blockIdx.y * 128;
    int colBase = blockIdx.x * 128;

    if (wid == 0) TC_ALLOC(ab + 0, 128);
    if (tid == 0) { MBAR_INIT(ab + 8, 1); MBAR_INIT(ab + 16, 1); MBAR_INIT(ab + 24, 1); }
    __syncthreads();
    uint32_t tmem;
    asm volatile("ld.shared.b32 %0, [%1];" : "=r"(tmem) : "r"(ab + 0));

    const int KC = K >> 6;
    const size_t rowK = (size_t)K;

    const __nv_bfloat16* srcs[4] = { Ah, Al, Bh, Bl };
    const int bases[4] = { rowBase, rowBase, colBase, colBase };

    auto load_stage = [&](int kc, int buf) {
        uint32_t stbase = ab + 1024 + buf * ST_STAGE;
        #pragma unroll
        for (int tl = 0; tl < 4; tl++) {
            const char* g = reinterpret_cast<const char*>(
                srcs[tl] + (size_t)bases[tl] * rowK + kc * 64);
            uint32_t tb = stbase + tl * ST_TILE;
            #pragma unroll
            for (int t = 0; t < 4; t++) {
                int i = tid + t * 256;
                int r = i >> 3, c = i & 7;
                uint32_t bo = r * 128 + c * 16;
                CP_ASYNC16(tb + SWZ128(bo), g + (size_t)r * (rowK * 2) + c * 16);
            }
        }
    };

    #pragma unroll
    for (int s = 0; s < 3; s++) { load_stage(s, s); CP_COMMIT(); }

    int ph[3] = { 0, 0, 0 };

    for (int kc = 0; kc < KC; kc++) {
        int buf = kc - (kc / 3) * 3;
        CP_WAIT2();
        __syncthreads();
        FENCE_ASYNC();

        uint32_t stage = ab + 1024 + buf * ST_STAGE;
        if (wid == 0 && elect_one()) {
            uint64_t ahd = MAKE_DESC(stage + 0 * ST_TILE);
            uint64_t ald = MAKE_DESC(stage + 1 * ST_TILE);
            uint64_t bhd = MAKE_DESC(stage + 2 * ST_TILE);
            uint64_t bld = MAKE_DESC(stage + 3 * ST_TILE);
            #pragma unroll
            for (int ks = 0; ks < 4; ks++) {
                uint64_t off = ks * 2;
                mma_ss_f16(tmem, ahd + off, bhd + off, IDESC_N128,
                           (kc == 0 && ks == 0) ? 0u : 1u);
                mma_ss_f16(tmem, ahd + off, bld + off, IDESC_N128, 1u);
                mma_ss_f16(tmem, ald + off, bhd + off, IDESC_N128, 1u);
            }
            TC_COMMIT(ab + 8 + 8 * buf);
        }

        if (kc + 3 < KC) {
            MBAR_WAIT(ab + 8 + 8 * buf, ph[buf] & 1); ph[buf]++;
            load_stage(kc + 3, buf);
        }
        CP_COMMIT();
    }
    MBAR_WAIT(ab + 8,  ph[0] & 1);
    MBAR_WAIT(ab + 16, ph[1] & 1);
    MBAR_WAIT(ab + 24, ph[2] & 1);
    TC_FENCE_AFTER();

    float* Ct = reinterpret_cast<float*>(smp + 1024);
    if (wid < 4) {
        int row = wid * 32 + lid;
        #pragma unroll
        for (int cb = 0; cb < 4; cb++) {
            uint32_t r[32];
            TC_LD_X32(r, tmem + cb * 32);
            TC_WAIT_LD();
            #pragma unroll
            for (int j = 0; j < 32; j++)
                Ct[row * 129 + cb * 32 + j] = __uint_as_float(r[j]);
        }
        TC_FENCE_BEFORE();
    }
    __syncthreads();

    if (MODE == 0) {
        for (int i = tid; i < 128 * 32; i += 256) {
            int r = i >> 5, c = (i & 31) * 4;
            float4 v;
            v.x = Ct[r * 129 + c + 0] + bias[colBase + c + 0];
            v.y = Ct[r * 129 + c + 1] + bias[colBase + c + 1];
            v.z = Ct[r * 129 + c + 2] + bias[colBase + c + 2];
            v.w = Ct[r * 129 + c + 3] + bias[colBase + c + 3];
            *reinterpret_cast<float4*>(&C[(size_t)(rowBase + r) * N + colBase + c]) = v;
        }
    } else {
        int type = colBase / DIMC;               // tile fully inside one of Q/K/V
        if (type < 2) {
            __nv_bfloat16* dh = (type == 0) ? qh : kh;
            __nv_bfloat16* dl = (type == 0) ? ql : kl;
            for (int i = tid; i < 128 * 32; i += 256) {
                int r = i >> 5, c4 = (i & 31) * 4;
                int token = rowBase + r;
                int b = token >> 10, tokin = token & 1023;
                int col = colBase + c4;
                int hh = (col % DIMC) / HDIM;
                int d = c4 & 63;
                float v0 = Ct[r * 129 + c4 + 0] + bias[col + 0];
                float v1 = Ct[r * 129 + c4 + 1] + bias[col + 1];
                float v2 = Ct[r * 129 + c4 + 2] + bias[col + 2];
                float v3 = Ct[r * 129 + c4 + 3] + bias[col + 3];
                uint2 hi, lo;
                split2(v0, v1, hi.x, lo.x);
                split2(v2, v3, hi.y, lo.y);
                size_t off = (((size_t)(b * NHEAD + hh) * SEQ + tokin) * HDIM + d);
                *reinterpret_cast<uint2*>(dh + off) = hi;
                *reinterpret_cast<uint2*>(dl + off) = lo;
            }
        } else {
            // V: transpose to [b,h,kvblk,d,kv64] blocks; 2 tokens per thread-step
            for (int t = 0; t < 32; t++) {
                int idx = t * 256 + tid;          // 0..8191
                int c  = idx >> 6;                // 0..127 (feature col in tile)
                int rp = (idx & 63) * 2;          // token pair
                int token = rowBase + rp;
                int b = token >> 10, tokin = token & 1023;
                int kvblk = tokin >> 6, kvin = tokin & 63;
                int col = colBase + c;
                int hh = (col % DIMC) / HDIM;
                int d = c & 63;
                float v0 = Ct[rp * 129 + c] + bias[col];
                float v1 = Ct[(rp + 1) * 129 + c] + bias[col];
                uint32_t hi, lo;
                split2(v0, v1, hi, lo);
                size_t off = (((size_t)(b * NHEAD + hh) * 16 + kvblk) * HDIM + d) * 64 + kvin;
                *reinterpret_cast<uint32_t*>(vth + off) = hi;
                *reinterpret_cast<uint32_t*>(vtl + off) = lo;
            }
        }
    }

    __syncthreads();
    if (wid == 0) { TC_RELINQ(); TC_DEALLOC(tmem, 128); }
#endif
}

// ---------------------------------------------------------------------------
// tcgen05 attention, kv-tile = 128, pre-split bf16 operands, cp.async loads.
// ---------------------------------------------------------------------------
#define AT_Q_H  2048
#define AT_Q_L  (AT_Q_H  + 16384)
#define AT_K_H  (AT_Q_L  + 16384)
#define AT_K_L  (AT_K_H  + 16384)
#define AT_VT_H (AT_K_L  + 16384)   // 2 blocks x 8192 ([64 d x 64 kv])
#define AT_VT_L (AT_VT_H + 16384)
#define AT_P_H  (AT_VT_L + 16384)   // 2 blocks x 16384 ([128 q x 64 kv])
#define AT_P_L  (AT_P_H  + 32768)
#define SMEM_ATTN (AT_P_L + 32768 + 1024)   // 166912

#if HAS_TCGEN05
// copy 128 rows x 128B from contiguous gmem into SW128-swizzled smem
__device__ __forceinline__ void cp_tile128(uint32_t dst, const __nv_bfloat16* src, int tid)
{
    const char* g = reinterpret_cast<const char*>(src);
    #pragma unroll
    for (int t = 0; t < 4; t++) {
        uint32_t bo = (uint32_t)(tid + t * 256) * 16;
        CP_ASYNC16(dst + SWZ128(bo), g + bo);
    }
}
#endif

__global__ __launch_bounds__(256, 1)
void attn_tc_kernel(const __nv_bfloat16* __restrict__ qh, const __nv_bfloat16* __restrict__ ql,
                    const __nv_bfloat16* __restrict__ kh, const __nv_bfloat16* __restrict__ kl,
                    const __nv_bfloat16* __restrict__ vth, const __nv_bfloat16* __restrict__ vtl,
                    __nv_bfloat16* __restrict__ oh, __nv_bfloat16* __restrict__ ol)
{
#if HAS_TCGEN05
    extern __shared__ char smem[];
    uint32_t sb = smem_u32(smem);
    uint32_t ab = (sb + 1023u) & ~1023u;
    char* smp = smem + (ab - sb);

    int tid = threadIdx.x;
    int wid = tid >> 5, lane = tid & 31;
    int sub = wid & 3, half = wid >> 2;
    int row = sub * 32 + lane;
    int qt = blockIdx.x, h = blockIdx.y, b = blockIdx.z;

    if (wid == 0) TC_ALLOC(ab + 0, 256);
    if (tid == 0) { MBAR_INIT(ab + 8, 1); MBAR_INIT(ab + 16, 1); }  // S, O
    __syncthreads();
    uint32_t tmem;
    asm volatile("ld.shared.b32 %0, [%1];" : "=r"(tmem) : "r"(ab + 0));

    const size_t bh = (size_t)(b * NHEAD + h);
    const size_t qbase = (bh * SEQ + (size_t)qt * 128) * HDIM;

    // prologue: Q + K(0)
    cp_tile128(ab + AT_Q_H, qh + qbase, tid);
    cp_tile128(ab + AT_Q_L, ql + qbase, tid);
    cp_tile128(ab + AT_K_H, kh + bh * SEQ * HDIM, tid);
    cp_tile128(ab + AT_K_L, kl + bh * SEQ * HDIM, tid);
    CP_COMMIT();

    float rsum = 0.f;
    const float scale = 0.125f;

    for (int kt = 0; kt < 8; kt++) {
        CP_WAIT0();              // K(kt) (and prior V) in smem
        __syncthreads();
        FENCE_ASYNC();

        // ---- issue S = Q K^T ----
        if (wid == 0 && elect_one()) {
            uint64_t qhd = MAKE_DESC(ab + AT_Q_H), qld = MAKE_DESC(ab + AT_Q_L);
            uint64_t khd = MAKE_DESC(ab + AT_K_H), kld = MAKE_DESC(ab + AT_K_L);
            #pragma unroll
            for (int ks = 0; ks < 4; ks++) {
                uint64_t off = ks * 2;
                mma_ss_f16(tmem, qhd + off, khd + off, IDESC_N128, ks > 0 ? 1u : 0u);
                mma_ss_f16(tmem, qhd + off, kld + off, IDESC_N128, 1u);
                mma_ss_f16(tmem, qld + off, khd + off, IDESC_N128, 1u);
            }
            TC_COMMIT(ab + 8);
        }

        // ---- wait O(kt-1) (frees Vt, P), then async-load V(kt) ----
        if (kt > 0) MBAR_WAIT(ab + 16, (kt - 1) & 1);
        {
            const size_t vbase = (bh * 16 + (size_t)kt * 2) * (HDIM * 64);
            cp_tile128(ab + AT_VT_H, vth + vbase, tid);
            cp_tile128(ab + AT_VT_L, vtl + vbase, tid);
            CP_COMMIT();
        }

        // ---- wait S(kt), exp + split P ----
        MBAR_WAIT(ab + 8, kt & 1);
        TC_FENCE_AFTER();
        {
            uint32_t r0[32], r1[32];
            TC_LD_X32(r0, tmem + half * 64);
            TC_LD_X32(r1, tmem + half * 64 + 32);
            TC_WAIT_LD();
            char* pH = smp + AT_P_H + half * 16384;
            char* pL = smp + AT_P_L + half * 16384;
            #pragma unroll
            for (int g = 0; g < 8; g++) {
                float e[8];
                #pragma unroll
                for (int j = 0; j < 8; j++) {
                    int c = g * 8 + j;
                    float s = __uint_as_float(c < 32 ? r0[c] : r1[c - 32]);
                    e[j] = __expf(s * scale);
                    rsum += e[j];
                }
                uint4 hi, lo;
                split2(e[0], e[1], hi.x, lo.x); split2(e[2], e[3], hi.y, lo.y);
                split2(e[4], e[5], hi.z, lo.z); split2(e[6], e[7], hi.w, lo.w);
                uint32_t off = SWZ128((uint32_t)(row * 128 + g * 16));
                *reinterpret_cast<uint4*>(pH + off) = hi;
                *reinterpret_cast<uint4*>(pL + off) = lo;
            }
            TC_FENCE_BEFORE();
        }
        CP_WAIT0();              // V(kt) arrived (overlapped with exp)
        __syncthreads();         // P + V visible
        FENCE_ASYNC();

        // ---- issue O += P V ----
        if (wid == 0 && elect_one()) {
            #pragma unroll
            for (int blk = 0; blk < 2; blk++) {
                uint64_t phd = MAKE_DESC(ab + AT_P_H + blk * 16384);
                uint64_t pld = MAKE_DESC(ab + AT_P_L + blk * 16384);
                uint64_t vhd = MAKE_DESC(ab + AT_VT_H + blk * 8192);
                uint64_t vld = MAKE_DESC(ab + AT_VT_L + blk * 8192);
                #pragma unroll
                for (int ks = 0; ks < 4; ks++) {
                    uint64_t off = ks * 2;
                    uint32_t acc = (kt == 0 && blk == 0 && ks == 0) ? 0u : 1u;
                    mma_ss_f16(tmem + 128, phd + off, vhd + off, IDESC_N64, acc);
                    mma_ss_f16(tmem + 128, phd + off, vld + off, IDESC_N64, 1u);
                    mma_ss_f16(tmem + 128, pld + off, vhd + off, IDESC_N64, 1u);
                }
            }
            TC_COMMIT(ab + 16);
        }

        // ---- prefetch K(kt+1) under O-MMA ----
        if (kt < 7) {
            const size_t kbase = (bh * SEQ + (size_t)(kt + 1) * 128) * HDIM;
            cp_tile128(ab + AT_K_H, kh + kbase, tid);
            cp_tile128(ab + AT_K_L, kl + kbase, tid);
        }
        CP_COMMIT();
    }
    MBAR_WAIT(ab + 16, 7 & 1);
    TC_FENCE_AFTER();

    // ---- normalize O and write split output ----
    float* rs = reinterpret_cast<float*>(smp + 512);   // [2][128]
    rs[half * 128 + row] = rsum;
    __syncthreads();

    {
        uint32_t o[32];
        TC_LD_X32(o, tmem + 128 + half * 32);
        TC_WAIT_LD();
        TC_FENCE_BEFORE();
        float inv = 1.0f / (rs[row] + rs[128 + row]);
        size_t off = ((size_t)(b * SEQ + qt * 128 + row)) * DIMC + h * HDIM + half * 32;
        #pragma unroll
        for (int j = 0; j < 32; j += 2) {
            uint32_t hi, lo;
            split2(__uint_as_float(o[j]) * inv, __uint_as_float(o[j + 1]) * inv, hi, lo);
            *reinterpret_cast<uint32_t*>(oh + off + j) = hi;
            *reinterpret_cast<uint32_t*>(ol + off + j) = lo;
        }
    }

    __syncthreads();
    if (wid == 0) { TC_RELINQ(); TC_DEALLOC(tmem, 256); }
#endif  // HAS_TCGEN05
}

// ---------------------------------------------------------------------------
// fp32 fallbacks (proven round-1 kernels)
// ---------------------------------------------------------------------------
__global__ __launch_bounds__(256)
void sgemm_bias_kernel(const float* __restrict__ A, const float* __restrict__ Bm,
                       const float* __restrict__ bias, float* __restrict__ C,
                       int M, int N, int K)
{
    const int BK = 16, PAD = 132;
    __shared__ float As[BK * PAD];
    __shared__ float Bs[BK * PAD];

    int tid = threadIdx.x;
    int tx = tid & 15, ty = tid >> 4;
    int rowBase = blockIdx.y * 128;
    int colBase = blockIdx.x * 128;

    float acc[8][8] = {};

    for (int k0 = 0; k0 < K; k0 += BK) {
        #pragma unroll
        for (int t = 0; t < 2; t++) {
            int i  = tid + t * 256;
            int r  = i >> 2;
            int kq = (i & 3) << 2;
            float4 v = *reinterpret_cast<const float4*>(
                &A[(size_t)(rowBase + r) * K + k0 + kq]);
            As[(kq + 0) * PAD + r] = v.x;
            As[(kq + 1) * PAD + r] = v.y;
            As[(kq + 2) * PAD + r] = v.z;
            As[(kq + 3) * PAD + r] = v.w;
        }
        #pragma unroll
        for (int t = 0; t < 2; t++) {
            int i  = tid + t * 256;
            int kk = i >> 5;
            int n4 = (i & 31) << 2;
            float4 v = *reinterpret_cast<const float4*>(
                &Bm[(size_t)(k0 + kk) * N + colBase + n4]);
            *reinterpret_cast<float4*>(&Bs[kk * PAD + n4]) = v;
        }
        __syncthreads();

        #pragma unroll
        for (int kk = 0; kk < BK; kk++) {
            float a[8], b[8];
            *(float4*)&a[0] = *(float4*)&As[kk * PAD + ty * 8];
            *(float4*)&a[4] = *(float4*)&As[kk * PAD + ty * 8 + 4];
            *(float4*)&b[0] = *(float4*)&Bs[kk * PAD + tx * 8];
            *(float4*)&b[4] = *(float4*)&Bs[kk * PAD + tx * 8 + 4];
            #pragma unroll
            for (int i = 0; i < 8; i++)
                #pragma unroll
                for (int j = 0; j < 8; j++)
                    acc[i][j] += a[i] * b[j];
        }
        __syncthreads();
    }

    #pragma unroll
    for (int i = 0; i < 8; i++) {
        int r = rowBase + ty * 8 + i;
        #pragma unroll
        for (int j = 0; j < 8; j += 4) {
            int c = colBase + tx * 8 + j;
            float4 v;
            v.x = acc[i][j + 0] + bias[c + 0];
            v.y = acc[i][j + 1] + bias[c + 1];
            v.z = acc[i][j + 2] + bias[c + 2];
            v.w = acc[i][j + 3] + bias[c + 3];
            *reinterpret_cast<float4*>(&C[(size_t)r * N + c]) = v;
        }
    }
}

__global__ __launch_bounds__(256)
void attn_kernel()
{
    extern __shared__ float sm[];
    float* Qs  = sm;
    float* Ks  = Qs + 64 * 64;
    float* Vs  = Ks + 64 * 65;
    float* Ss  = Vs + 64 * 64;
    float* m_s = Ss + 64 * 65;
    float* l_s = m_s + 64;
    float* a_s = l_s + 64;

    int qt = blockIdx.x, h = blockIdx.y, b = blockIdx.z;
    int tid = threadIdx.x;
    int tx = tid & 15, ty = tid >> 4;
    const float scale = 0.125f;
    const int RS = 3 * DIMC;

    size_t qoff = ((size_t)(b * SEQ + qt * 64)) * RS + h * HDIM;

    #pragma unroll
    for (int t = 0; t < 4; t++) {
        int i  = tid + t * 256;
        int r  = i >> 4;
        int d4 = (i & 15) << 2;
        float4 v = *reinterpret_cast<const float4*>(&g_qkv[qoff + (size_t)r * RS + d4]);
        *reinterpret_cast<float4*>(&Qs[r * 64 + d4]) = v;
    }
    if (tid < 64) { m_s[tid] = -1e30f; l_s[tid] = 0.f; }
    float O[4][4] = {};
    __syncthreads();

    for (int kt = 0; kt < 16; kt++) {
        size_t koff = ((size_t)(b * SEQ + kt * 64)) * RS + DIMC + h * HDIM;
        size_t voff = koff + DIMC;
        #pragma unroll
        for (int t = 0; t < 4; t++) {
            int i  = tid + t * 256;
            int r  = i >> 4;
            int d4 = (i & 15) << 2;
            float4 kv = *reinterpret_cast<const float4*>(&g_qkv[koff + (size_t)r * RS + d4]);
            Ks[r * 65 + d4 + 0] = kv.x;
            Ks[r * 65 + d4 + 1] = kv.y;
            Ks[r * 65 + d4 + 2] = kv.z;
            Ks[r * 65 + d4 + 3] = kv.w;
            float4 vv = *reinterpret_cast<const float4*>(&g_qkv[voff + (size_t)r * RS + d4]);
            *reinterpret_cast<float4*>(&Vs[r * 64 + d4]) = vv;
        }
        __syncthreads();

        float s[4][4] = {};
        #pragma unroll 8
        for (int d = 0; d < 64; d++) {
            float qv[4], kv[4];
            #pragma unroll
            for (int i = 0; i < 4; i++) qv[i] = Qs[(ty * 4 + i) * 64 + d];
            #pragma unroll
            for (int j = 0; j < 4; j++) kv[j] = Ks[(tx * 4 + j) * 65 + d];
            #pragma unroll
            for (int i = 0; i < 4; i++)
                #pragma unroll
                for (int j = 0; j < 4; j++)
                    s[i][j] += qv[i] * kv[j];
        }
        #pragma unroll
        for (int i = 0; i < 4; i++)
            #pragma unroll
            for (int j = 0; j < 4; j++)
                Ss[(ty * 4 + i) * 65 + tx * 4 + j] = s[i][j] * scale;
        __syncthreads();

        if (tid < 64) {
            float mold = m_s[tid];
            float mx = mold;
            #pragma unroll 8
            for (int j = 0; j < 64; j++) mx = fmaxf(mx, Ss[tid * 65 + j]);
            float sum = 0.f;
            #pragma unroll 8
            for (int j = 0; j < 64; j++) {
                float p = __expf(Ss[tid * 65 + j] - mx);
                Ss[tid * 65 + j] = p;
                sum += p;
            }
            float alpha = __expf(mold - mx);
            a_s[tid] = alpha;
            m_s[tid] = mx;
            l_s[tid] = l_s[tid] * alpha + sum;
        }
        __syncthreads();

        float alpha[4];
        #pragma unroll
        for (int i = 0; i < 4; i++) alpha[i] = a_s[ty * 4 + i];
        #pragma unroll
        for (int i = 0; i < 4; i++)
            #pragma unroll
            for (int j = 0; j < 4; j++)
                O[i][j] *= alpha[i];
        #pragma unroll 8
        for (int kv = 0; kv < 64; kv++) {
            float p[4], v[4];
            #pragma unroll
            for (int i = 0; i < 4; i++) p[i] = Ss[(ty * 4 + i) * 65 + kv];
            #pragma unroll
            for (int j = 0; j < 4; j++) v[j] = Vs[kv * 64 + tx * 4 + j];
            #pragma unroll
            for (int i = 0; i < 4; i++)
                #pragma unroll
                for (int j = 0; j < 4; j++)
                    O[i][j] += p[i] * v[j];
        }
        __syncthreads();
    }

    float inv_l[4];
    #pragma unroll
    for (int i = 0; i < 4; i++) inv_l[i] = 1.0f / l_s[ty * 4 + i];
    #pragma unroll
    for (int i = 0; i < 4; i++) {
        int q = qt * 64 + ty * 4 + i;
        size_t off = ((size_t)(b * SEQ + q)) * DIMC + h * HDIM + tx * 4;
        float4 v;
        v.x = O[i][0] * inv_l[i];
        v.y = O[i][1] * inv_l[i];
        v.z = O[i][2] * inv_l[i];
        v.w = O[i][3] * inv_l[i];
        *reinterpret_cast<float4*>(&g_attn[off]) = v;
    }
}

// ---------------------------------------------------------------------------

extern "C" void kernel_launch(void* const* d_in, const int* in_sizes, int n_in,
                              void* d_out, int out_size)
{
    const float* x     = (const float*)d_in[0];
    const float* Wqkv  = (const float*)d_in[1];
    const float* bqkv  = (const float*)d_in[2];
    const float* Wproj = (const float*)d_in[3];
    const float* bproj = (const float*)d_in[4];
    float* out = (float*)d_out;

    float *qkv = nullptr, *attn = nullptr;
    __nv_bfloat16 *ah, *al, *wqh, *wql, *wph, *wpl;
    __nv_bfloat16 *Qh, *Ql, *Kh, *Kl, *Vth, *Vtl;
    cudaGetSymbolAddress((void**)&qkv,  g_qkv);
    cudaGetSymbolAddress((void**)&attn, g_attn);
    cudaGetSymbolAddress((void**)&ah,   g_ah);
    cudaGetSymbolAddress((void**)&al,   g_al);
    cudaGetSymbolAddress((void**)&wqh,  g_wqh);
    cudaGetSymbolAddress((void**)&wql,  g_wql);
    cudaGetSymbolAddress((void**)&wph,  g_wph);
    cudaGetSymbolAddress((void**)&wpl,  g_wpl);
    cudaGetSymbolAddress((void**)&Qh,   g_q_h);
    cudaGetSymbolAddress((void**)&Ql,   g_q_l);
    cudaGetSymbolAddress((void**)&Kh,   g_k_h);
    cudaGetSymbolAddress((void**)&Kl,   g_k_l);
    cudaGetSymbolAddress((void**)&Vth,  g_vt_h);
    cudaGetSymbolAddress((void**)&Vtl,  g_vt_l);

    cudaFuncAttributes pa{};
    cudaFuncGetAttributes(&pa, feat_probe);
    bool use_tc = pa.sharedSizeBytes >= 1024;

    dim3 blk(256);

    if (use_tc) {
        cudaFuncSetAttribute(gemm_bf16x3_kernel<0>,
                             cudaFuncAttributeMaxDynamicSharedMemorySize, SMEM_GEMM);
        cudaFuncSetAttribute(gemm_bf16x3_kernel<1>,
                             cudaFuncAttributeMaxDynamicSharedMemorySize, SMEM_GEMM);
        cudaFuncSetAttribute(attn_tc_kernel,
                             cudaFuncAttributeMaxDynamicSharedMemorySize, SMEM_ATTN);

        int n4 = MTOT * DIMC / 4;
        split_kernel<<<(n4 + 255) / 256, 256>>>(x, ah, al, n4);
        dim3 tb(32, 32);
        transpose_split_kernel<<<dim3(NQKV / 32, DIMC / 32), tb>>>(Wqkv, wqh, wql, DIMC, NQKV);
        transpose_split_kernel<<<dim3(DIMC / 32, DIMC / 32), tb>>>(Wproj, wph, wpl, DIMC, DIMC);

        // QKV GEMM with fused repack epilogue
        dim3 g1(NQKV / 128, MTOT / 128);
        gemm_bf16x3_kernel<1><<<g1, blk, SMEM_GEMM>>>(ah, al, wqh, wql, bqkv,
                                                      nullptr, NQKV, DIMC,
                                                      Qh, Ql, Kh, Kl, Vth, Vtl);

        // attention (writes split output straight into ah/al)
        dim3 g2(SEQ / 128, NHEAD, BATCH);
        attn_tc_kernel<<<g2, blk, SMEM_ATTN>>>(Qh, Ql, Kh, Kl, Vth, Vtl, ah, al);

        // projection
        dim3 g3(DIMC / 128, MTOT / 128);
        gemm_bf16x3_kernel<0><<<g3, blk, SMEM_GEMM>>>(ah, al, wph, wpl, bproj,
                                                      out, DIMC, DIMC,
                                                      nullptr, nullptr, nullptr,
                                                      nullptr, nullptr, nullptr);
    } else {
        const int ATTN_SMEM = (64*64 + 64*65 + 64*64 + 64*65 + 3*64) * 4;
        cudaFuncSetAttribute(attn_kernel,
                             cudaFuncAttributeMaxDynamicSharedMemorySize, ATTN_SMEM);
        dim3 g1(NQKV / 128, MTOT / 128);
        sgemm_bias_kernel<<<g1, blk>>>(x, Wqkv, bqkv, qkv, MTOT, NQKV, DIMC);

        dim3 g2(SEQ / 64, NHEAD, BATCH);
        attn_kernel<<<g2, blk, ATTN_SMEM>>>();

        dim3 g3(DIMC / 128, MTOT / 128);
        sgemm_bias_kernel<<<g3, blk>>>(attn, Wproj, bproj, out, MTOT, DIMC, DIMC);
    }
}

// round 9
// speedup vs baseline: 1.5124x; 1.1090x over previous
#include <cuda_runtime.h>
#include <cuda_bf16.h>
#include <math.h>
#include <stdint.h>

#define DIMC 768
#define NHEAD 12
#define HDIM 64
#define BATCH 8
#define SEQ 1024
#define MTOT (BATCH*SEQ)   // 8192
#define NQKV (3*DIMC)      // 2304

#if defined(__CUDA_ARCH__) && (defined(__CUDA_ARCH_FEAT_SM103_ALL) || defined(__CUDA_ARCH_FEAT_SM100_ALL))
#define HAS_TCGEN05 1
#else
#define HAS_TCGEN05 0
#endif

// ---------------------------------------------------------------------------
// Scratch
// ---------------------------------------------------------------------------
__device__ __align__(16) float g_qkv[(size_t)MTOT * NQKV];      // fallback only
__device__ __align__(16) float g_attn[(size_t)MTOT * DIMC];     // fallback only
__device__ __align__(16) __nv_bfloat16 g_ah[(size_t)MTOT * DIMC];
__device__ __align__(16) __nv_bfloat16 g_al[(size_t)MTOT * DIMC];
__device__ __align__(16) __nv_bfloat16 g_wqh[(size_t)NQKV * DIMC];
__device__ __align__(16) __nv_bfloat16 g_wql[(size_t)NQKV * DIMC];
__device__ __align__(16) __nv_bfloat16 g_wph[(size_t)DIMC * DIMC];
__device__ __align__(16) __nv_bfloat16 g_wpl[(size_t)DIMC * DIMC];
__device__ __align__(16) __nv_bfloat16 g_q_h[(size_t)BATCH * NHEAD * SEQ * HDIM];
__device__ __align__(16) __nv_bfloat16 g_q_l[(size_t)BATCH * NHEAD * SEQ * HDIM];
__device__ __align__(16) __nv_bfloat16 g_k_h[(size_t)BATCH * NHEAD * SEQ * HDIM];
__device__ __align__(16) __nv_bfloat16 g_k_l[(size_t)BATCH * NHEAD * SEQ * HDIM];
__device__ __align__(16) __nv_bfloat16 g_vt_h[(size_t)BATCH * NHEAD * SEQ * HDIM];
__device__ __align__(16) __nv_bfloat16 g_vt_l[(size_t)BATCH * NHEAD * SEQ * HDIM];

// ---------------------------------------------------------------------------
// Probe kernel (host dispatch signal)
// ---------------------------------------------------------------------------
__global__ void feat_probe(int* out) {
#if HAS_TCGEN05
    __shared__ int s[256];
#else
    __shared__ int s[2];
#endif
    int n = (int)(sizeof(s) / sizeof(int));
    s[threadIdx.x % n] = (int)clock();
    __syncthreads();
    if (out) *out = s[0];
}

// ---------------------------------------------------------------------------
// Split fp32 -> bf16 hi/lo
// ---------------------------------------------------------------------------
__global__ __launch_bounds__(256)
void split_kernel(const float* __restrict__ src, __nv_bfloat16* __restrict__ hi,
                  __nv_bfloat16* __restrict__ lo, int n4)
{
    int i = blockIdx.x * blockDim.x + threadIdx.x;
    if (i >= n4) return;
    float4 v = reinterpret_cast<const float4*>(src)[i];
    __nv_bfloat16 h0 = __float2bfloat16(v.x);
    __nv_bfloat16 h1 = __float2bfloat16(v.y);
    __nv_bfloat16 h2 = __float2bfloat16(v.z);
    __nv_bfloat16 h3 = __float2bfloat16(v.w);
    __nv_bfloat16 l0 = __float2bfloat16(v.x - __bfloat162float(h0));
    __nv_bfloat16 l1 = __float2bfloat16(v.y - __bfloat162float(h1));
    __nv_bfloat16 l2 = __float2bfloat16(v.z - __bfloat162float(h2));
    __nv_bfloat16 l3 = __float2bfloat16(v.w - __bfloat162float(h3));
    __nv_bfloat162* ph = reinterpret_cast<__nv_bfloat162*>(hi);
    __nv_bfloat162* pl = reinterpret_cast<__nv_bfloat162*>(lo);
    ph[2*i]   = __nv_bfloat162{h0, h1};
    ph[2*i+1] = __nv_bfloat162{h2, h3};
    pl[2*i]   = __nv_bfloat162{l0, l1};
    pl[2*i+1] = __nv_bfloat162{l2, l3};
}

__global__ __launch_bounds__(1024)
void transpose_split_kernel(const float* __restrict__ W,
                            __nv_bfloat16* __restrict__ hiT,
                            __nv_bfloat16* __restrict__ loT, int K, int N)
{
    __shared__ float t[32][33];
    int n0 = blockIdx.x * 32, k0 = blockIdx.y * 32;
    int tx = threadIdx.x, ty = threadIdx.y;
    t[ty][tx] = W[(size_t)(k0 + ty) * N + n0 + tx];
    __syncthreads();
    float v = t[tx][ty];
    __nv_bfloat16 h = __float2bfloat16(v);
    __nv_bfloat16 l = __float2bfloat16(v - __bfloat162float(h));
    size_t off = (size_t)(n0 + ty) * K + k0 + tx;
    hiT[off] = h;
    loT[off] = l;
}

// ---------------------------------------------------------------------------
// helpers
// ---------------------------------------------------------------------------
__device__ __forceinline__ uint32_t smem_u32(const void* p) {
    uint32_t a;
    asm("{ .reg .u64 t; cvta.to.shared.u64 t, %1; cvt.u32.u64 %0, t; }"
        : "=r"(a) : "l"(p));
    return a;
}

#define SWZ128(o) ((o) ^ (((o) >> 3) & 0x70))

#define MBAR_INIT(addr, cnt) \
    asm volatile("mbarrier.init.shared.b64 [%0], %1;" :: "r"(addr), "r"(cnt) : "memory")

#define MBAR_WAIT(addr, parity) do {                                          \
    uint32_t _m = (addr); uint32_t _p = (parity); uint32_t _done;             \
    asm volatile("{\n\t.reg .pred p;\n\t"                                     \
        "mbarrier.try_wait.parity.acquire.cta.shared::cta.b64 p, [%1], %2;\n\t"\
        "selp.b32 %0, 1, 0, p;\n\t}" : "=r"(_done) : "r"(_m), "r"(_p) : "memory");\
    if (!_done) {                                                             \
        asm volatile("{\n\t.reg .pred P1;\n\t"                                \
            "WL_%=:\n\t"                                                      \
            "mbarrier.try_wait.parity.acquire.cta.shared::cta.b64 P1, [%0], %1, 0x989680;\n\t"\
            "@P1 bra.uni WD_%=;\n\t"                                          \
            "bra.uni WL_%=;\n\t"                                              \
            "WD_%=:\n\t}" :: "r"(_m), "r"(_p) : "memory");                    \
    }                                                                         \
} while (0)

#if HAS_TCGEN05
__device__ __forceinline__ uint32_t elect_one() {
    uint32_t pred;
    asm volatile("{\n\t.reg .pred p;\n\telect.sync _|p, 0xFFFFFFFF;\n\t"
                 "selp.b32 %0, 1, 0, p;\n\t}" : "=r"(pred));
    return pred;
}

#define TC_ALLOC(sm_dst, ncols) \
    asm volatile("tcgen05.alloc.cta_group::1.sync.aligned.shared::cta.b32 [%0], %1;" \
                 :: "r"(sm_dst), "r"(ncols) : "memory")
#define TC_DEALLOC(tm, ncols) \
    asm volatile("tcgen05.dealloc.cta_group::1.sync.aligned.b32 %0, %1;" :: "r"(tm), "r"(ncols))
#define TC_RELINQ() \
    asm volatile("tcgen05.relinquish_alloc_permit.cta_group::1.sync.aligned;")
#define TC_COMMIT(mbar) \
    asm volatile("tcgen05.commit.cta_group::1.mbarrier::arrive::one.shared::cluster.b64 [%0];" \
                 :: "r"(mbar) : "memory")
#define TC_FENCE_AFTER()  asm volatile("tcgen05.fence::after_thread_sync;" ::: "memory")
#define TC_FENCE_BEFORE() asm volatile("tcgen05.fence::before_thread_sync;" ::: "memory")
#define TC_WAIT_LD() asm volatile("tcgen05.wait::ld.sync.aligned;" ::: "memory")
#define FENCE_ASYNC() asm volatile("fence.proxy.async.shared::cta;" ::: "memory")

#define CP_ASYNC16(dst, src) \
    asm volatile("cp.async.cg.shared.global [%0], [%1], 16;" :: "r"(dst), "l"(src) : "memory")
#define CP_COMMIT() asm volatile("cp.async.commit_group;" ::: "memory")
#define CP_WAIT1()  asm volatile("cp.async.wait_group 1;" ::: "memory")
#define CP_WAIT0()  asm volatile("cp.async.wait_group 0;" ::: "memory")

#define TC_LD_X32(r, tm) \
    asm volatile("tcgen05.ld.sync.aligned.32x32b.x32.b32 "                    \
        "{%0, %1, %2, %3, %4, %5, %6, %7, "                                   \
        " %8, %9, %10, %11, %12, %13, %14, %15, "                             \
        " %16, %17, %18, %19, %20, %21, %22, %23, "                           \
        " %24, %25, %26, %27, %28, %29, %30, %31}, [%32];"                    \
        : "=r"((r)[0]),  "=r"((r)[1]),  "=r"((r)[2]),  "=r"((r)[3]),          \
          "=r"((r)[4]),  "=r"((r)[5]),  "=r"((r)[6]),  "=r"((r)[7]),          \
          "=r"((r)[8]),  "=r"((r)[9]),  "=r"((r)[10]), "=r"((r)[11]),         \
          "=r"((r)[12]), "=r"((r)[13]), "=r"((r)[14]), "=r"((r)[15]),         \
          "=r"((r)[16]), "=r"((r)[17]), "=r"((r)[18]), "=r"((r)[19]),         \
          "=r"((r)[20]), "=r"((r)[21]), "=r"((r)[22]), "=r"((r)[23]),         \
          "=r"((r)[24]), "=r"((r)[25]), "=r"((r)[26]), "=r"((r)[27]),         \
          "=r"((r)[28]), "=r"((r)[29]), "=r"((r)[30]), "=r"((r)[31])          \
        : "r"(tm))

#define MAKE_DESC(base) \
    ((uint64_t(2) << 61) | (uint64_t(1) << 46) | (uint64_t(64) << 32) | \
     (uint64_t(1) << 16) | ((uint64_t)((base) >> 4) & 0x3FFF))

__device__ __forceinline__ void mma_ss_f16(uint32_t d, uint64_t ad, uint64_t bd,
                                           uint32_t idesc, uint32_t en) {
    asm volatile(
        "{\n\t.reg .pred p;\n\t"
        "setp.ne.u32 p, %4, 0;\n\t"
        "tcgen05.mma.cta_group::1.kind::f16 [%0], %1, %2, %3, {%5, %5, %5, %5}, p;\n\t}"
        :: "r"(d), "l"(ad), "l"(bd), "r"(idesc), "r"(en), "r"(0u) : "memory");
}

#define IDESC_N128 (0x10u | 0x80u | 0x400u | (16u << 17) | (8u << 24))
#define IDESC_N64  (0x10u | 0x80u | 0x400u | (8u  << 17) | (8u << 24))

__device__ __forceinline__ void split2(float x, float y, uint32_t& hi, uint32_t& lo) {
    __nv_bfloat162 h = __floats2bfloat162_rn(x, y);
    float hx = __bfloat162float(__low2bfloat16(h));
    float hy = __bfloat162float(__high2bfloat16(h));
    __nv_bfloat162 l = __floats2bfloat162_rn(x - hx, y - hy);
    hi = *reinterpret_cast<uint32_t*>(&h);
    lo = *reinterpret_cast<uint32_t*>(&l);
}
#endif  // HAS_TCGEN05

// ---------------------------------------------------------------------------
// tcgen05 bf16x3 GEMM — 128x256 tile, 2-stage cp.async pipeline.
// MODE 0: C = A@B^T + bias (fp32 out);  MODE 1: QKV fused repack epilogue.
// ---------------------------------------------------------------------------
#define ST_STG 98304                      // Ah16K Al16K Bh32K Bl32K
#define SMEM_GEMM (1024 + 1024 + 2 * ST_STG)   // 198656

template<int MODE>
__global__ __launch_bounds__(256, 1)
void gemm_bf16x3_kernel(const __nv_bfloat16* __restrict__ Ah,
                        const __nv_bfloat16* __restrict__ Al,
                        const __nv_bfloat16* __restrict__ Bh,
                        const __nv_bfloat16* __restrict__ Bl,
                        const float* __restrict__ bias,
                        float* __restrict__ C, int N, int K,
                        __nv_bfloat16* qh, __nv_bfloat16* ql,
                        __nv_bfloat16* kh, __nv_bfloat16* kl,
                        __nv_bfloat16* vth, __nv_bfloat16* vtl)
{
#if HAS_TCGEN05
    extern __shared__ char smem[];
    uint32_t sb = smem_u32(smem);
    uint32_t ab = (sb + 1023u) & ~1023u;
    char* smp = smem + (ab - sb);

    int tid = threadIdx.x;
    int wid = tid >> 5, lid = tid & 31;
    int rowBase = blockIdx.y * 128;
    int colBase = blockIdx.x * 256;

    if (wid == 0) TC_ALLOC(ab + 0, 256);
    if (tid == 0) { MBAR_INIT(ab + 8, 1); MBAR_INIT(ab + 16, 1); }
    __syncthreads();
    uint32_t tmem;
    asm volatile("ld.shared.b32 %0, [%1];" : "=r"(tmem) : "r"(ab + 0));

    const int KC = K >> 6;
    const size_t rowK = (size_t)K;

    auto load_stage = [&](int kc, int buf) {
        uint32_t st = ab + 1024 + buf * ST_STG;
        // A hi/lo: 128 rows x 128B
        #pragma unroll
        for (int tl = 0; tl < 2; tl++) {
            const char* g = reinterpret_cast<const char*>(
                (tl ? Al : Ah) + (size_t)rowBase * rowK + kc * 64);
            uint32_t tb = st + tl * 16384;
            #pragma unroll
            for (int t = 0; t < 4; t++) {
                int i = tid + t * 256;
                int r = i >> 3, c = i & 7;
                CP_ASYNC16(tb + SWZ128((uint32_t)(r * 128 + c * 16)),
                           g + (size_t)r * (rowK * 2) + c * 16);
            }
        }
        // B hi/lo: 256 rows x 128B
        #pragma unroll
        for (int tl = 0; tl < 2; tl++) {
            const char* g = reinterpret_cast<const char*>(
                (tl ? Bl : Bh) + (size_t)colBase * rowK + kc * 64);
            uint32_t tb = st + 32768 + tl * 32768;
            #pragma unroll
            for (int t = 0; t < 8; t++) {
                int i = tid + t * 256;
                int r = i >> 3, c = i & 7;
                CP_ASYNC16(tb + SWZ128((uint32_t)(r * 128 + c * 16)),
                           g + (size_t)r * (rowK * 2) + c * 16);
            }
        }
    };

    load_stage(0, 0); CP_COMMIT();
    load_stage(1, 1); CP_COMMIT();

    int ph[2] = { 0, 0 };

    for (int kc = 0; kc < KC; kc++) {
        int buf = kc & 1;
        CP_WAIT1();
        __syncthreads();
        FENCE_ASYNC();

        uint32_t st = ab + 1024 + buf * ST_STG;
        if (wid == 0 && elect_one()) {
            uint64_t ahd = MAKE_DESC(st + 0);
            uint64_t ald = MAKE_DESC(st + 16384);
            #pragma unroll
            for (int ks = 0; ks < 4; ks++) {
                uint64_t off = ks * 2;
                #pragma unroll
                for (int ct = 0; ct < 2; ct++) {
                    uint64_t bhd = MAKE_DESC(st + 32768 + ct * 16384);
                    uint64_t bld = MAKE_DESC(st + 65536 + ct * 16384);
                    uint32_t d = tmem + ct * 128;
                    mma_ss_f16(d, ahd + off, bhd + off, IDESC_N128,
                               (kc == 0 && ks == 0) ? 0u : 1u);
                    mma_ss_f16(d, ahd + off, bld + off, IDESC_N128, 1u);
                    mma_ss_f16(d, ald + off, bhd + off, IDESC_N128, 1u);
                }
            }
            TC_COMMIT(ab + 8 + 8 * buf);
        }

        if (kc + 2 < KC) {
            MBAR_WAIT(ab + 8 + 8 * buf, ph[buf] & 1); ph[buf]++;
            load_stage(kc + 2, buf);
        }
        CP_COMMIT();
    }
    MBAR_WAIT(ab + 8,  ph[0] & 1);
    MBAR_WAIT(ab + 16, ph[1] & 1);
    TC_FENCE_AFTER();

    float* Ct = reinterpret_cast<float*>(smp + 1024);
    #pragma unroll
    for (int ct = 0; ct < 2; ct++) {
        int colB = colBase + ct * 128;
        if (wid < 4) {
            int row = wid * 32 + lid;
            #pragma unroll
            for (int cb = 0; cb < 4; cb++) {
                uint32_t r[32];
                TC_LD_X32(r, tmem + ct * 128 + cb * 32);
                TC_WAIT_LD();
                #pragma unroll
                for (int j = 0; j < 32; j++)
                    Ct[row * 129 + cb * 32 + j] = __uint_as_float(r[j]);
            }
            TC_FENCE_BEFORE();
        }
        __syncthreads();

        if (MODE == 0) {
            for (int i = tid; i < 128 * 32; i += 256) {
                int r = i >> 5, c = (i & 31) * 4;
                float4 v;
                v.x = Ct[r * 129 + c + 0] + bias[colB + c + 0];
                v.y = Ct[r * 129 + c + 1] + bias[colB + c + 1];
                v.z = Ct[r * 129 + c + 2] + bias[colB + c + 2];
                v.w = Ct[r * 129 + c + 3] + bias[colB + c + 3];
                *reinterpret_cast<float4*>(&C[(size_t)(rowBase + r) * N + colB + c]) = v;
            }
        } else {
            int type = colB / DIMC;
            if (type < 2) {
                __nv_bfloat16* dh = (type == 0) ? qh : kh;
                __nv_bfloat16* dl = (type == 0) ? ql : kl;
                for (int i = tid; i < 128 * 32; i += 256) {
                    int r = i >> 5, c4 = (i & 31) * 4;
                    int token = rowBase + r;
                    int b = token >> 10, tokin = token & 1023;
                    int col = colB + c4;
                    int hh = (col % DIMC) / HDIM;
                    int d = col & 63;
                    float v0 = Ct[r * 129 + c4 + 0] + bias[col + 0];
                    float v1 = Ct[r * 129 + c4 + 1] + bias[col + 1];
                    float v2 = Ct[r * 129 + c4 + 2] + bias[col + 2];
                    float v3 = Ct[r * 129 + c4 + 3] + bias[col + 3];
                    uint2 hi, lo;
                    split2(v0, v1, hi.x, lo.x);
                    split2(v2, v3, hi.y, lo.y);
                    size_t off = (((size_t)(b * NHEAD + hh) * SEQ + tokin) * HDIM + d);
                    *reinterpret_cast<uint2*>(dh + off) = hi;
                    *reinterpret_cast<uint2*>(dl + off) = lo;
                }
            } else {
                for (int t = 0; t < 32; t++) {
                    int idx = t * 256 + tid;
                    int c  = idx >> 6;
                    int rp = (idx & 63) * 2;
                    int token = rowBase + rp;
                    int b = token >> 10, tokin = token & 1023;
                    int kvblk = tokin >> 6, kvin = tokin & 63;
                    int col = colB + c;
                    int hh = (col % DIMC) / HDIM;
                    int d = col & 63;
                    float v0 = Ct[rp * 129 + c] + bias[col];
                    float v1 = Ct[(rp + 1) * 129 + c] + bias[col];
                    uint32_t hi, lo;
                    split2(v0, v1, hi, lo);
                    size_t off = (((size_t)(b * NHEAD + hh) * 16 + kvblk) * HDIM + d) * 64 + kvin;
                    *reinterpret_cast<uint32_t*>(vth + off) = hi;
                    *reinterpret_cast<uint32_t*>(vtl + off) = lo;
                }
            }
        }
        __syncthreads();
    }

    if (wid == 0) { TC_RELINQ(); TC_DEALLOC(tmem, 256); }
#endif
}

// ---------------------------------------------------------------------------
// tcgen05 attention: kv-tile 128, S double-buffered in TMEM, K double-buffered
// in smem. S(kt+1) overlaps exp(kt)+O(kt).
// ---------------------------------------------------------------------------
#define AT_Q_H   2048
#define AT_Q_L   (AT_Q_H + 16384)                 // 18432
#define AT_KB(buf) (34816 + (buf) * 32768)        // hi at +0, lo at +16384
#define AT_VT_H  100352                           // 2 blocks x 8192
#define AT_VT_L  (AT_VT_H + 16384)
#define AT_P_H   (AT_VT_L + 16384)                // 133120, 2 blocks x 16384
#define AT_P_L   (AT_P_H + 32768)                 // 165888
#define SMEM_ATTN (AT_P_L + 32768 + 1024)         // 199680

#if HAS_TCGEN05
__device__ __forceinline__ void cp_tile128(uint32_t dst, const __nv_bfloat16* src, int tid)
{
    const char* g = reinterpret_cast<const char*>(src);
    #pragma unroll
    for (int t = 0; t < 4; t++) {
        uint32_t bo = (uint32_t)(tid + t * 256) * 16;
        CP_ASYNC16(dst + SWZ128(bo), g + bo);
    }
}

__device__ __forceinline__ void attn_issue_S(uint32_t ab, uint32_t tmem_d, int kbuf)
{
    uint64_t qhd = MAKE_DESC(ab + AT_Q_H), qld = MAKE_DESC(ab + AT_Q_L);
    uint64_t khd = MAKE_DESC(ab + AT_KB(kbuf)), kld = MAKE_DESC(ab + AT_KB(kbuf) + 16384);
    #pragma unroll
    for (int ks = 0; ks < 4; ks++) {
        uint64_t off = ks * 2;
        mma_ss_f16(tmem_d, qhd + off, khd + off, IDESC_N128, ks > 0 ? 1u : 0u);
        mma_ss_f16(tmem_d, qhd + off, kld + off, IDESC_N128, 1u);
        mma_ss_f16(tmem_d, qld + off, khd + off, IDESC_N128, 1u);
    }
    TC_COMMIT(ab + 8);
}
#endif

__global__ __launch_bounds__(256, 1)
void attn_tc_kernel(const __nv_bfloat16* __restrict__ qh, const __nv_bfloat16* __restrict__ ql,
                    const __nv_bfloat16* __restrict__ kh, const __nv_bfloat16* __restrict__ kl,
                    const __nv_bfloat16* __restrict__ vth, const __nv_bfloat16* __restrict__ vtl,
                    __nv_bfloat16* __restrict__ oh, __nv_bfloat16* __restrict__ ol)
{
#if HAS_TCGEN05
    extern __shared__ char smem[];
    uint32_t sb = smem_u32(smem);
    uint32_t ab = (sb + 1023u) & ~1023u;
    char* smp = smem + (ab - sb);

    int tid = threadIdx.x;
    int wid = tid >> 5, lane = tid & 31;
    int sub = wid & 3, half = wid >> 2;
    int row = sub * 32 + lane;
    int qt = blockIdx.x, h = blockIdx.y, b = blockIdx.z;

    if (wid == 0) TC_ALLOC(ab + 0, 512);
    if (tid == 0) { MBAR_INIT(ab + 8, 1); MBAR_INIT(ab + 16, 1); }  // S, O
    __syncthreads();
    uint32_t tmem;
    asm volatile("ld.shared.b32 %0, [%1];" : "=r"(tmem) : "r"(ab + 0));
    // TMEM: S0 @ +0, S1 @ +128, O @ +256

    const size_t bh = (size_t)(b * NHEAD + h);
    const size_t qbase = (bh * SEQ + (size_t)qt * 128) * HDIM;

    // prologue: Q + K(0) -> group, wait, issue S(0); then K(1) async
    cp_tile128(ab + AT_Q_H, qh + qbase, tid);
    cp_tile128(ab + AT_Q_L, ql + qbase, tid);
    cp_tile128(ab + AT_KB(0),         kh + bh * SEQ * HDIM, tid);
    cp_tile128(ab + AT_KB(0) + 16384, kl + bh * SEQ * HDIM, tid);
    CP_COMMIT();
    CP_WAIT0();
    __syncthreads();
    FENCE_ASYNC();
    if (wid == 0 && elect_one()) attn_issue_S(ab, tmem + 0, 0);
    {
        const size_t kbase = (bh * SEQ + 128) * HDIM;
        cp_tile128(ab + AT_KB(1),         kh + kbase, tid);
        cp_tile128(ab + AT_KB(1) + 16384, kl + kbase, tid);
        CP_COMMIT();
    }

    float rsum = 0.f;
    const float scale = 0.125f;

    for (int kt = 0; kt < 8; kt++) {
        int sbuf = kt & 1;

        // O(kt-1) frees V and P
        if (kt > 0) MBAR_WAIT(ab + 16, (kt - 1) & 1);

        // start V(kt)
        {
            const size_t vbase = (bh * 16 + (size_t)kt * 2) * (HDIM * 64);
            cp_tile128(ab + AT_VT_H, vth + vbase, tid);
            cp_tile128(ab + AT_VT_L, vtl + vbase, tid);
            CP_COMMIT();
        }

        // wait S(kt), read it
        MBAR_WAIT(ab + 8, kt & 1);
        TC_FENCE_AFTER();
        uint32_t r0[32], r1[32];
        TC_LD_X32(r0, tmem + sbuf * 128 + half * 64);
        TC_LD_X32(r1, tmem + sbuf * 128 + half * 64 + 32);
        TC_WAIT_LD();

        // issue S(kt+1) into the other TMEM region (K(kt+1) in smem buf sbuf^1)
        if (kt < 7) {
            CP_WAIT1();          // K(kt+1) arrived (V(kt) may still be pending)
            __syncthreads();
            FENCE_ASYNC();
            if (wid == 0 && elect_one())
                attn_issue_S(ab, tmem + ((kt + 1) & 1) * 128, (kt + 1) & 1);
        }

        // exp + split P
        {
            char* pH = smp + AT_P_H + half * 16384;
            char* pL = smp + AT_P_L + half * 16384;
            #pragma unroll
            for (int g = 0; g < 8; g++) {
                float e[8];
                #pragma unroll
                for (int j = 0; j < 8; j++) {
                    int c = g * 8 + j;
                    float s = __uint_as_float(c < 32 ? r0[c] : r1[c - 32]);
                    e[j] = __expf(s * scale);
                    rsum += e[j];
                }
                uint4 hi, lo;
                split2(e[0], e[1], hi.x, lo.x); split2(e[2], e[3], hi.y, lo.y);
                split2(e[4], e[5], hi.z, lo.z); split2(e[6], e[7], hi.w, lo.w);
                uint32_t off = SWZ128((uint32_t)(row * 128 + g * 16));
                *reinterpret_cast<uint4*>(pH + off) = hi;
                *reinterpret_cast<uint4*>(pL + off) = lo;
            }
            TC_FENCE_BEFORE();
        }

        // prefetch K(kt+2) into buf sbuf (S(kt) done with it)
        if (kt < 6) {
            const size_t kbase = (bh * SEQ + (size_t)(kt + 2) * 128) * HDIM;
            cp_tile128(ab + AT_KB(sbuf),         kh + kbase, tid);
            cp_tile128(ab + AT_KB(sbuf) + 16384, kl + kbase, tid);
        }
        CP_COMMIT();             // real or dummy — keeps group order exact

        CP_WAIT1();              // V(kt) complete (K(kt+2) may pend)
        __syncthreads();         // P + V visible
        FENCE_ASYNC();

        // issue O(kt) += P V
        if (wid == 0 && elect_one()) {
            #pragma unroll
            for (int blk = 0; blk < 2; blk++) {
                uint64_t phd = MAKE_DESC(ab + AT_P_H + blk * 16384);
                uint64_t pld = MAKE_DESC(ab + AT_P_L + blk * 16384);
                uint64_t vhd = MAKE_DESC(ab + AT_VT_H + blk * 8192);
                uint64_t vld = MAKE_DESC(ab + AT_VT_L + blk * 8192);
                #pragma unroll
                for (int ks = 0; ks < 4; ks++) {
                    uint64_t off = ks * 2;
                    uint32_t acc = (kt == 0 && blk == 0 && ks == 0) ? 0u : 1u;
                    mma_ss_f16(tmem + 256, phd + off, vhd + off, IDESC_N64, acc);
                    mma_ss_f16(tmem + 256, phd + off, vld + off, IDESC_N64, 1u);
                    mma_ss_f16(tmem + 256, pld + off, vhd + off, IDESC_N64, 1u);
                }
            }
            TC_COMMIT(ab + 16);
        }
    }
    MBAR_WAIT(ab + 16, 7 & 1);
    TC_FENCE_AFTER();

    // normalize O and write split output
    float* rs = reinterpret_cast<float*>(smp + 512);   // [2][128]
    rs[half * 128 + row] = rsum;
    __syncthreads();

    {
        uint32_t o[32];
        TC_LD_X32(o, tmem + 256 + half * 32);
        TC_WAIT_LD();
        TC_FENCE_BEFORE();
        float inv = 1.0f / (rs[row] + rs[128 + row]);
        size_t off = ((size_t)(b * SEQ + qt * 128 + row)) * DIMC + h * HDIM + half * 32;
        #pragma unroll
        for (int j = 0; j < 32; j += 2) {
            uint32_t hi, lo;
            split2(__uint_as_float(o[j]) * inv, __uint_as_float(o[j + 1]) * inv, hi, lo);
            *reinterpret_cast<uint32_t*>(oh + off + j) = hi;
            *reinterpret_cast<uint32_t*>(ol + off + j) = lo;
        }
    }

    __syncthreads();
    if (wid == 0) { TC_RELINQ(); TC_DEALLOC(tmem, 512); }
#endif  // HAS_TCGEN05
}

// ---------------------------------------------------------------------------
// fp32 fallbacks (proven round-1 kernels)
// ---------------------------------------------------------------------------
__global__ __launch_bounds__(256)
void sgemm_bias_kernel(const float* __restrict__ A, const float* __restrict__ Bm,
                       const float* __restrict__ bias, float* __restrict__ C,
                       int M, int N, int K)
{
    const int BK = 16, PAD = 132;
    __shared__ float As[BK * PAD];
    __shared__ float Bs[BK * PAD];

    int tid = threadIdx.x;
    int tx = tid & 15, ty = tid >> 4;
    int rowBase = blockIdx.y * 128;
    int colBase = blockIdx.x * 128;

    float acc[8][8] = {};

    for (int k0 = 0; k0 < K; k0 += BK) {
        #pragma unroll
        for (int t = 0; t < 2; t++) {
            int i  = tid + t * 256;
            int r  = i >> 2;
            int kq = (i & 3) << 2;
            float4 v = *reinterpret_cast<const float4*>(
                &A[(size_t)(rowBase + r) * K + k0 + kq]);
            As[(kq + 0) * PAD + r] = v.x;
            As[(kq + 1) * PAD + r] = v.y;
            As[(kq + 2) * PAD + r] = v.z;
            As[(kq + 3) * PAD + r] = v.w;
        }
        #pragma unroll
        for (int t = 0; t < 2; t++) {
            int i  = tid + t * 256;
            int kk = i >> 5;
            int n4 = (i & 31) << 2;
            float4 v = *reinterpret_cast<const float4*>(
                &Bm[(size_t)(k0 + kk) * N + colBase + n4]);
            *reinterpret_cast<float4*>(&Bs[kk * PAD + n4]) = v;
        }
        __syncthreads();

        #pragma unroll
        for (int kk = 0; kk < BK; kk++) {
            float a[8], bb[8];
            *(float4*)&a[0] = *(float4*)&As[kk * PAD + ty * 8];
            *(float4*)&a[4] = *(float4*)&As[kk * PAD + ty * 8 + 4];
            *(float4*)&bb[0] = *(float4*)&Bs[kk * PAD + tx * 8];
            *(float4*)&bb[4] = *(float4*)&Bs[kk * PAD + tx * 8 + 4];
            #pragma unroll
            for (int i = 0; i < 8; i++)
                #pragma unroll
                for (int j = 0; j < 8; j++)
                    acc[i][j] += a[i] * bb[j];
        }
        __syncthreads();
    }

    #pragma unroll
    for (int i = 0; i < 8; i++) {
        int r = rowBase + ty * 8 + i;
        #pragma unroll
        for (int j = 0; j < 8; j += 4) {
            int c = colBase + tx * 8 + j;
            float4 v;
            v.x = acc[i][j + 0] + bias[c + 0];
            v.y = acc[i][j + 1] + bias[c + 1];
            v.z = acc[i][j + 2] + bias[c + 2];
            v.w = acc[i][j + 3] + bias[c + 3];
            *reinterpret_cast<float4*>(&C[(size_t)r * N + c]) = v;
        }
    }
}

__global__ __launch_bounds__(256)
void attn_kernel()
{
    extern __shared__ float sm[];
    float* Qs  = sm;
    float* Ks  = Qs + 64 * 64;
    float* Vs  = Ks + 64 * 65;
    float* Ss  = Vs + 64 * 64;
    float* m_s = Ss + 64 * 65;
    float* l_s = m_s + 64;
    float* a_s = l_s + 64;

    int qt = blockIdx.x, h = blockIdx.y, b = blockIdx.z;
    int tid = threadIdx.x;
    int tx = tid & 15, ty = tid >> 4;
    const float scale = 0.125f;
    const int RS = 3 * DIMC;

    size_t qoff = ((size_t)(b * SEQ + qt * 64)) * RS + h * HDIM;

    #pragma unroll
    for (int t = 0; t < 4; t++) {
        int i  = tid + t * 256;
        int r  = i >> 4;
        int d4 = (i & 15) << 2;
        float4 v = *reinterpret_cast<const float4*>(&g_qkv[qoff + (size_t)r * RS + d4]);
        *reinterpret_cast<float4*>(&Qs[r * 64 + d4]) = v;
    }
    if (tid < 64) { m_s[tid] = -1e30f; l_s[tid] = 0.f; }
    float O[4][4] = {};
    __syncthreads();

    for (int kt = 0; kt < 16; kt++) {
        size_t koff = ((size_t)(b * SEQ + kt * 64)) * RS + DIMC + h * HDIM;
        size_t voff = koff + DIMC;
        #pragma unroll
        for (int t = 0; t < 4; t++) {
            int i  = tid + t * 256;
            int r  = i >> 4;
            int d4 = (i & 15) << 2;
            float4 kv = *reinterpret_cast<const float4*>(&g_qkv[koff + (size_t)r * RS + d4]);
            Ks[r * 65 + d4 + 0] = kv.x;
            Ks[r * 65 + d4 + 1] = kv.y;
            Ks[r * 65 + d4 + 2] = kv.z;
            Ks[r * 65 + d4 + 3] = kv.w;
            float4 vv = *reinterpret_cast<const float4*>(&g_qkv[voff + (size_t)r * RS + d4]);
            *reinterpret_cast<float4*>(&Vs[r * 64 + d4]) = vv;
        }
        __syncthreads();

        float s[4][4] = {};
        #pragma unroll 8
        for (int d = 0; d < 64; d++) {
            float qv[4], kv[4];
            #pragma unroll
            for (int i = 0; i < 4; i++) qv[i] = Qs[(ty * 4 + i) * 64 + d];
            #pragma unroll
            for (int j = 0; j < 4; j++) kv[j] = Ks[(tx * 4 + j) * 65 + d];
            #pragma unroll
            for (int i = 0; i < 4; i++)
                #pragma unroll
                for (int j = 0; j < 4; j++)
                    s[i][j] += qv[i] * kv[j];
        }
        #pragma unroll
        for (int i = 0; i < 4; i++)
            #pragma unroll
            for (int j = 0; j < 4; j++)
                Ss[(ty * 4 + i) * 65 + tx * 4 + j] = s[i][j] * scale;
        __syncthreads();

        if (tid < 64) {
            float mold = m_s[tid];
            float mx = mold;
            #pragma unroll 8
            for (int j = 0; j < 64; j++) mx = fmaxf(mx, Ss[tid * 65 + j]);
            float sum = 0.f;
            #pragma unroll 8
            for (int j = 0; j < 64; j++) {
                float p = __expf(Ss[tid * 65 + j] - mx);
                Ss[tid * 65 + j] = p;
                sum += p;
            }
            float alpha = __expf(mold - mx);
            a_s[tid] = alpha;
            m_s[tid] = mx;
            l_s[tid] = l_s[tid] * alpha + sum;
        }
        __syncthreads();

        float alpha[4];
        #pragma unroll
        for (int i = 0; i < 4; i++) alpha[i] = a_s[ty * 4 + i];
        #pragma unroll
        for (int i = 0; i < 4; i++)
            #pragma unroll
            for (int j = 0; j < 4; j++)
                O[i][j] *= alpha[i];
        #pragma unroll 8
        for (int kv = 0; kv < 64; kv++) {
            float p[4], v[4];
            #pragma unroll
            for (int i = 0; i < 4; i++) p[i] = Ss[(ty * 4 + i) * 65 + kv];
            #pragma unroll
            for (int j = 0; j < 4; j++) v[j] = Vs[kv * 64 + tx * 4 + j];
            #pragma unroll
            for (int i = 0; i < 4; i++)
                #pragma unroll
                for (int j = 0; j < 4; j++)
                    O[i][j] += p[i] * v[j];
        }
        __syncthreads();
    }

    float inv_l[4];
    #pragma unroll
    for (int i = 0; i < 4; i++) inv_l[i] = 1.0f / l_s[ty * 4 + i];
    #pragma unroll
    for (int i = 0; i < 4; i++) {
        int q = qt * 64 + ty * 4 + i;
        size_t off = ((size_t)(b * SEQ + q)) * DIMC + h * HDIM + tx * 4;
        float4 v;
        v.x = O[i][0] * inv_l[i];
        v.y = O[i][1] * inv_l[i];
        v.z = O[i][2] * inv_l[i];
        v.w = O[i][3] * inv_l[i];
        *reinterpret_cast<float4*>(&g_attn[off]) = v;
    }
}

// ---------------------------------------------------------------------------

extern "C" void kernel_launch(void* const* d_in, const int* in_sizes, int n_in,
                              void* d_out, int out_size)
{
    const float* x     = (const float*)d_in[0];
    const float* Wqkv  = (const float*)d_in[1];
    const float* bqkv  = (const float*)d_in[2];
    const float* Wproj = (const float*)d_in[3];
    const float* bproj = (const float*)d_in[4];
    float* out = (float*)d_out;

    float *qkv = nullptr, *attn = nullptr;
    __nv_bfloat16 *ah, *al, *wqh, *wql, *wph, *wpl;
    __nv_bfloat16 *Qh, *Ql, *Kh, *Kl, *Vth, *Vtl;
    cudaGetSymbolAddress((void**)&qkv,  g_qkv);
    cudaGetSymbolAddress((void**)&attn, g_attn);
    cudaGetSymbolAddress((void**)&ah,   g_ah);
    cudaGetSymbolAddress((void**)&al,   g_al);
    cudaGetSymbolAddress((void**)&wqh,  g_wqh);
    cudaGetSymbolAddress((void**)&wql,  g_wql);
    cudaGetSymbolAddress((void**)&wph,  g_wph);
    cudaGetSymbolAddress((void**)&wpl,  g_wpl);
    cudaGetSymbolAddress((void**)&Qh,   g_q_h);
    cudaGetSymbolAddress((void**)&Ql,   g_q_l);
    cudaGetSymbolAddress((void**)&Kh,   g_k_h);
    cudaGetSymbolAddress((void**)&Kl,   g_k_l);
    cudaGetSymbolAddress((void**)&Vth,  g_vt_h);
    cudaGetSymbolAddress((void**)&Vtl,  g_vt_l);

    cudaFuncAttributes pa{};
    cudaFuncGetAttributes(&pa, feat_probe);
    bool use_tc = pa.sharedSizeBytes >= 1024;

    dim3 blk(256);

    if (use_tc) {
        cudaFuncSetAttribute(gemm_bf16x3_kernel<0>,
                             cudaFuncAttributeMaxDynamicSharedMemorySize, SMEM_GEMM);
        cudaFuncSetAttribute(gemm_bf16x3_kernel<1>,
                             cudaFuncAttributeMaxDynamicSharedMemorySize, SMEM_GEMM);
        cudaFuncSetAttribute(attn_tc_kernel,
                             cudaFuncAttributeMaxDynamicSharedMemorySize, SMEM_ATTN);

        int n4 = MTOT * DIMC / 4;
        split_kernel<<<(n4 + 255) / 256, 256>>>(x, ah, al, n4);
        dim3 tb(32, 32);
        transpose_split_kernel<<<dim3(NQKV / 32, DIMC / 32), tb>>>(Wqkv, wqh, wql, DIMC, NQKV);
        transpose_split_kernel<<<dim3(DIMC / 32, DIMC / 32), tb>>>(Wproj, wph, wpl, DIMC, DIMC);

        // QKV GEMM (128x256 tiles) with fused repack epilogue
        dim3 g1(NQKV / 256, MTOT / 128);    // 9 x 64
        gemm_bf16x3_kernel<1><<<g1, blk, SMEM_GEMM>>>(ah, al, wqh, wql, bqkv,
                                                      nullptr, NQKV, DIMC,
                                                      Qh, Ql, Kh, Kl, Vth, Vtl);

        // attention (pipelined S, writes split output into ah/al)
        dim3 g2(SEQ / 128, NHEAD, BATCH);
        attn_tc_kernel<<<g2, blk, SMEM_ATTN>>>(Qh, Ql, Kh, Kl, Vth, Vtl, ah, al);

        // projection (128x256 tiles)
        dim3 g3(DIMC / 256, MTOT / 128);    // 3 x 64
        gemm_bf16x3_kernel<0><<<g3, blk, SMEM_GEMM>>>(ah, al, wph, wpl, bproj,
                                                      out, DIMC, DIMC,
                                                      nullptr, nullptr, nullptr,
                                                      nullptr, nullptr, nullptr);
    } else {
        const int ATTN_SMEM = (64*64 + 64*65 + 64*64 + 64*65 + 3*64) * 4;
        cudaFuncSetAttribute(attn_kernel,
                             cudaFuncAttributeMaxDynamicSharedMemorySize, ATTN_SMEM);
        dim3 g1(NQKV / 128, MTOT / 128);
        sgemm_bias_kernel<<<g1, blk>>>(x, Wqkv, bqkv, qkv, MTOT, NQKV, DIMC);

        dim3 g2(SEQ / 64, NHEAD, BATCH);
        attn_kernel<<<g2, blk, ATTN_SMEM>>>();

        dim3 g3(DIMC / 128, MTOT / 128);
        sgemm_bias_kernel<<<g3, blk>>>(attn, Wproj, bproj, out, MTOT, DIMC, DIMC);
    }
}

// round 10
// speedup vs baseline: 2.5240x; 1.6689x over previous
#include <cuda_runtime.h>
#include <cuda_bf16.h>
#include <cuda_fp16.h>
#include <math.h>
#include <stdint.h>

#define DIMC 768
#define NHEAD 12
#define HDIM 64
#define BATCH 8
#define SEQ 1024
#define MTOT (BATCH*SEQ)   // 8192
#define NQKV (3*DIMC)      // 2304

#if defined(__CUDA_ARCH__) && (defined(__CUDA_ARCH_FEAT_SM103_ALL) || defined(__CUDA_ARCH_FEAT_SM100_ALL))
#define HAS_TCGEN05 1
#else
#define HAS_TCGEN05 0
#endif

// ---------------------------------------------------------------------------
// Scratch
// ---------------------------------------------------------------------------
__device__ __align__(16) float g_qkv[(size_t)MTOT * NQKV];      // fallback only
__device__ __align__(16) float g_attn[(size_t)MTOT * DIMC];     // fallback only
__device__ __align__(16) __half g_a16[(size_t)MTOT * DIMC];     // x, then attn out
__device__ __align__(16) __half g_wq16[(size_t)NQKV * DIMC];    // WqkvT [N,K]
__device__ __align__(16) __half g_wp16[(size_t)DIMC * DIMC];    // WprojT [N,K]
__device__ __align__(16) __half g_q16[(size_t)BATCH * NHEAD * SEQ * HDIM];
__device__ __align__(16) __half g_k16[(size_t)BATCH * NHEAD * SEQ * HDIM];
__device__ __align__(16) __half g_vt16[(size_t)BATCH * NHEAD * SEQ * HDIM];

// ---------------------------------------------------------------------------
// Probe kernel (host dispatch signal)
// ---------------------------------------------------------------------------
__global__ void feat_probe(int* out) {
#if HAS_TCGEN05
    __shared__ int s[256];
#else
    __shared__ int s[2];
#endif
    int n = (int)(sizeof(s) / sizeof(int));
    s[threadIdx.x % n] = (int)clock();
    __syncthreads();
    if (out) *out = s[0];
}

// ---------------------------------------------------------------------------
// fp32 -> fp16 convert kernels
// ---------------------------------------------------------------------------
__global__ __launch_bounds__(256)
void cvt16_kernel(const float* __restrict__ src, __half* __restrict__ dst, int n4)
{
    int i = blockIdx.x * blockDim.x + threadIdx.x;
    if (i >= n4) return;
    float4 v = reinterpret_cast<const float4*>(src)[i];
    __half2 a = __floats2half2_rn(v.x, v.y);
    __half2 b = __floats2half2_rn(v.z, v.w);
    uint2 o;
    o.x = *reinterpret_cast<uint32_t*>(&a);
    o.y = *reinterpret_cast<uint32_t*>(&b);
    reinterpret_cast<uint2*>(dst)[i] = o;
}

__global__ __launch_bounds__(1024)
void transpose_cvt16_kernel(const float* __restrict__ W,
                            __half* __restrict__ T16, int K, int N)
{
    __shared__ float t[32][33];
    int n0 = blockIdx.x * 32, k0 = blockIdx.y * 32;
    int tx = threadIdx.x, ty = threadIdx.y;
    t[ty][tx] = W[(size_t)(k0 + ty) * N + n0 + tx];
    __syncthreads();
    T16[(size_t)(n0 + ty) * K + k0 + tx] = __float2half_rn(t[tx][ty]);
}

// ---------------------------------------------------------------------------
// helpers
// ---------------------------------------------------------------------------
__device__ __forceinline__ uint32_t smem_u32(const void* p) {
    uint32_t a;
    asm("{ .reg .u64 t; cvta.to.shared.u64 t, %1; cvt.u32.u64 %0, t; }"
        : "=r"(a) : "l"(p));
    return a;
}

#define SWZ128(o) ((o) ^ (((o) >> 3) & 0x70))

#define MBAR_INIT(addr, cnt) \
    asm volatile("mbarrier.init.shared.b64 [%0], %1;" :: "r"(addr), "r"(cnt) : "memory")

#define MBAR_WAIT(addr, parity) do {                                          \
    uint32_t _m = (addr); uint32_t _p = (parity); uint32_t _done;             \
    asm volatile("{\n\t.reg .pred p;\n\t"                                     \
        "mbarrier.try_wait.parity.acquire.cta.shared::cta.b64 p, [%1], %2;\n\t"\
        "selp.b32 %0, 1, 0, p;\n\t}" : "=r"(_done) : "r"(_m), "r"(_p) : "memory");\
    if (!_done) {                                                             \
        asm volatile("{\n\t.reg .pred P1;\n\t"                                \
            "WL_%=:\n\t"                                                      \
            "mbarrier.try_wait.parity.acquire.cta.shared::cta.b64 P1, [%0], %1, 0x989680;\n\t"\
            "@P1 bra.uni WD_%=;\n\t"                                          \
            "bra.uni WL_%=;\n\t"                                              \
            "WD_%=:\n\t}" :: "r"(_m), "r"(_p) : "memory");                    \
    }                                                                         \
} while (0)

#if HAS_TCGEN05
__device__ __forceinline__ uint32_t elect_one() {
    uint32_t pred;
    asm volatile("{\n\t.reg .pred p;\n\telect.sync _|p, 0xFFFFFFFF;\n\t"
                 "selp.b32 %0, 1, 0, p;\n\t}" : "=r"(pred));
    return pred;
}

#define TC_ALLOC(sm_dst, ncols) \
    asm volatile("tcgen05.alloc.cta_group::1.sync.aligned.shared::cta.b32 [%0], %1;" \
                 :: "r"(sm_dst), "r"(ncols) : "memory")
#define TC_DEALLOC(tm, ncols) \
    asm volatile("tcgen05.dealloc.cta_group::1.sync.aligned.b32 %0, %1;" :: "r"(tm), "r"(ncols))
#define TC_RELINQ() \
    asm volatile("tcgen05.relinquish_alloc_permit.cta_group::1.sync.aligned;")
#define TC_COMMIT(mbar) \
    asm volatile("tcgen05.commit.cta_group::1.mbarrier::arrive::one.shared::cluster.b64 [%0];" \
                 :: "r"(mbar) : "memory")
#define TC_FENCE_AFTER()  asm volatile("tcgen05.fence::after_thread_sync;" ::: "memory")
#define TC_FENCE_BEFORE() asm volatile("tcgen05.fence::before_thread_sync;" ::: "memory")
#define TC_WAIT_LD() asm volatile("tcgen05.wait::ld.sync.aligned;" ::: "memory")
#define FENCE_ASYNC() asm volatile("fence.proxy.async.shared::cta;" ::: "memory")

#define CP_ASYNC16(dst, src) \
    asm volatile("cp.async.cg.shared.global [%0], [%1], 16;" :: "r"(dst), "l"(src) : "memory")
#define CP_COMMIT() asm volatile("cp.async.commit_group;" ::: "memory")
#define CP_WAIT1()  asm volatile("cp.async.wait_group 1;" ::: "memory")
#define CP_WAIT0()  asm volatile("cp.async.wait_group 0;" ::: "memory")

#define TC_LD_X32(r, tm) \
    asm volatile("tcgen05.ld.sync.aligned.32x32b.x32.b32 "                    \
        "{%0, %1, %2, %3, %4, %5, %6, %7, "                                   \
        " %8, %9, %10, %11, %12, %13, %14, %15, "                             \
        " %16, %17, %18, %19, %20, %21, %22, %23, "                           \
        " %24, %25, %26, %27, %28, %29, %30, %31}, [%32];"                    \
        : "=r"((r)[0]),  "=r"((r)[1]),  "=r"((r)[2]),  "=r"((r)[3]),          \
          "=r"((r)[4]),  "=r"((r)[5]),  "=r"((r)[6]),  "=r"((r)[7]),          \
          "=r"((r)[8]),  "=r"((r)[9]),  "=r"((r)[10]), "=r"((r)[11]),         \
          "=r"((r)[12]), "=r"((r)[13]), "=r"((r)[14]), "=r"((r)[15]),         \
          "=r"((r)[16]), "=r"((r)[17]), "=r"((r)[18]), "=r"((r)[19]),         \
          "=r"((r)[20]), "=r"((r)[21]), "=r"((r)[22]), "=r"((r)[23]),         \
          "=r"((r)[24]), "=r"((r)[25]), "=r"((r)[26]), "=r"((r)[27]),         \
          "=r"((r)[28]), "=r"((r)[29]), "=r"((r)[30]), "=r"((r)[31])          \
        : "r"(tm))

#define MAKE_DESC(base) \
    ((uint64_t(2) << 61) | (uint64_t(1) << 46) | (uint64_t(64) << 32) | \
     (uint64_t(1) << 16) | ((uint64_t)((base) >> 4) & 0x3FFF))

__device__ __forceinline__ void mma_ss_f16(uint32_t d, uint64_t ad, uint64_t bd,
                                           uint32_t idesc, uint32_t en) {
    asm volatile(
        "{\n\t.reg .pred p;\n\t"
        "setp.ne.u32 p, %4, 0;\n\t"
        "tcgen05.mma.cta_group::1.kind::f16 [%0], %1, %2, %3, {%5, %5, %5, %5}, p;\n\t}"
        :: "r"(d), "l"(ad), "l"(bd), "r"(idesc), "r"(en), "r"(0u) : "memory");
}

// fp16 inputs (atype=btype=0), fp32 accum, M=128
#define IDESC16_N128 (0x10u | (16u << 17) | (8u << 24))
#define IDESC16_N64  (0x10u | (8u  << 17) | (8u << 24))
#endif  // HAS_TCGEN05

// ---------------------------------------------------------------------------
// tcgen05 fp16 GEMM — 128x256 tile, 3-stage cp.async, deferred MMA wait
// (wait M(kc-1) at iter kc — MMAs run back-to-back).
// MODE 0: C = A@B^T + bias (fp32 out);  MODE 1: QKV fused repack epilogue.
// ---------------------------------------------------------------------------
#define ST16_STG 49152                    // A 16K + B 32K
#define SMEM_GEMM (1024 + 1024 + 3 * ST16_STG)   // 149504

template<int MODE>
__global__ __launch_bounds__(256, 1)
void gemm_f16_kernel(const __half* __restrict__ A16,
                     const __half* __restrict__ B16,
                     const float* __restrict__ bias,
                     float* __restrict__ C, int N, int K,
                     __half* q16, __half* k16, __half* vt16)
{
#if HAS_TCGEN05
    extern __shared__ char smem[];
    uint32_t sb = smem_u32(smem);
    uint32_t ab = (sb + 1023u) & ~1023u;
    char* smp = smem + (ab - sb);

    int tid = threadIdx.x;
    int wid = tid >> 5, lid = tid & 31;
    int rowBase = blockIdx.y * 128;
    int colBase = blockIdx.x * 256;

    if (wid == 0) TC_ALLOC(ab + 0, 256);
    if (tid == 0) { MBAR_INIT(ab + 8, 1); MBAR_INIT(ab + 16, 1); MBAR_INIT(ab + 24, 1); }
    __syncthreads();
    uint32_t tmem;
    asm volatile("ld.shared.b32 %0, [%1];" : "=r"(tmem) : "r"(ab + 0));

    const int KC = K >> 6;
    const size_t rowK = (size_t)K;

    auto load_stage = [&](int kc, int buf) {
        uint32_t st = ab + 1024 + buf * ST16_STG;
        // A: 128 rows x 128B
        {
            const char* g = reinterpret_cast<const char*>(
                A16 + (size_t)rowBase * rowK + kc * 64);
            #pragma unroll
            for (int t = 0; t < 4; t++) {
                int i = tid + t * 256;
                int r = i >> 3, c = i & 7;
                CP_ASYNC16(st + SWZ128((uint32_t)(r * 128 + c * 16)),
                           g + (size_t)r * (rowK * 2) + c * 16);
            }
        }
        // B: 256 rows x 128B
        {
            const char* g = reinterpret_cast<const char*>(
                B16 + (size_t)colBase * rowK + kc * 64);
            uint32_t tb = st + 16384;
            #pragma unroll
            for (int t = 0; t < 8; t++) {
                int i = tid + t * 256;
                int r = i >> 3, c = i & 7;
                CP_ASYNC16(tb + SWZ128((uint32_t)(r * 128 + c * 16)),
                           g + (size_t)r * (rowK * 2) + c * 16);
            }
        }
    };

    load_stage(0, 0); CP_COMMIT();
    load_stage(1, 1); CP_COMMIT();

    int ph[3] = { 0, 0, 0 };

    for (int kc = 0; kc < KC; kc++) {
        int buf = kc - (kc / 3) * 3;
        CP_WAIT1();              // L(kc) done (newest may pend)
        __syncthreads();
        FENCE_ASYNC();

        uint32_t st = ab + 1024 + buf * ST16_STG;
        if (wid == 0 && elect_one()) {
            uint64_t ahd = MAKE_DESC(st);
            #pragma unroll
            for (int ks = 0; ks < 4; ks++) {
                uint64_t off = ks * 2;
                #pragma unroll
                for (int ct = 0; ct < 2; ct++) {
                    uint64_t bhd = MAKE_DESC(st + 16384 + ct * 16384);
                    mma_ss_f16(tmem + ct * 128, ahd + off, bhd + off, IDESC16_N128,
                               (kc == 0 && ks == 0) ? 0u : 1u);
                }
            }
            TC_COMMIT(ab + 8 + 8 * buf);
        }

        // wait PREVIOUS chunk's MMA (issued last iteration) — not this one's
        if (kc >= 1) {
            int pb = (kc - 1) % 3;
            MBAR_WAIT(ab + 8 + 8 * pb, ph[pb] & 1); ph[pb]++;
        }
        if (kc + 2 < KC) load_stage(kc + 2, (kc + 2) % 3);
        CP_COMMIT();             // real or dummy
    }
    {
        int lb = (KC - 1) % 3;
        MBAR_WAIT(ab + 8 + 8 * lb, ph[lb] & 1);
    }
    CP_WAIT0();
    TC_FENCE_AFTER();

    float* Ct = reinterpret_cast<float*>(smp + 1024);
    #pragma unroll
    for (int ct = 0; ct < 2; ct++) {
        int colB = colBase + ct * 128;
        if (wid < 4) {
            int row = wid * 32 + lid;
            #pragma unroll
            for (int cb = 0; cb < 4; cb++) {
                uint32_t r[32];
                TC_LD_X32(r, tmem + ct * 128 + cb * 32);
                TC_WAIT_LD();
                #pragma unroll
                for (int j = 0; j < 32; j++)
                    Ct[row * 129 + cb * 32 + j] = __uint_as_float(r[j]);
            }
            TC_FENCE_BEFORE();
        }
        __syncthreads();

        if (MODE == 0) {
            for (int i = tid; i < 128 * 32; i += 256) {
                int r = i >> 5, c = (i & 31) * 4;
                float4 v;
                v.x = Ct[r * 129 + c + 0] + bias[colB + c + 0];
                v.y = Ct[r * 129 + c + 1] + bias[colB + c + 1];
                v.z = Ct[r * 129 + c + 2] + bias[colB + c + 2];
                v.w = Ct[r * 129 + c + 3] + bias[colB + c + 3];
                *reinterpret_cast<float4*>(&C[(size_t)(rowBase + r) * N + colB + c]) = v;
            }
        } else {
            int type = colB / DIMC;
            if (type < 2) {
                __half* dst = (type == 0) ? q16 : k16;
                for (int i = tid; i < 128 * 32; i += 256) {
                    int r = i >> 5, c4 = (i & 31) * 4;
                    int token = rowBase + r;
                    int b = token >> 10, tokin = token & 1023;
                    int col = colB + c4;
                    int hh = (col % DIMC) / HDIM;
                    int d = col & 63;
                    float v0 = Ct[r * 129 + c4 + 0] + bias[col + 0];
                    float v1 = Ct[r * 129 + c4 + 1] + bias[col + 1];
                    float v2 = Ct[r * 129 + c4 + 2] + bias[col + 2];
                    float v3 = Ct[r * 129 + c4 + 3] + bias[col + 3];
                    __half2 p0 = __floats2half2_rn(v0, v1);
                    __half2 p1 = __floats2half2_rn(v2, v3);
                    uint2 o;
                    o.x = *reinterpret_cast<uint32_t*>(&p0);
                    o.y = *reinterpret_cast<uint32_t*>(&p1);
                    size_t off = (((size_t)(b * NHEAD + hh) * SEQ + tokin) * HDIM + d);
                    *reinterpret_cast<uint2*>(dst + off) = o;
                }
            } else {
                // V: transpose to [b,h,kvblk,d,kv64] fp16 blocks
                for (int t = 0; t < 32; t++) {
                    int idx = t * 256 + tid;
                    int c  = idx >> 6;
                    int rp = (idx & 63) * 2;
                    int token = rowBase + rp;
                    int b = token >> 10, tokin = token & 1023;
                    int kvblk = tokin >> 6, kvin = tokin & 63;
                    int col = colB + c;
                    int hh = (col % DIMC) / HDIM;
                    int d = col & 63;
                    float v0 = Ct[rp * 129 + c] + bias[col];
                    float v1 = Ct[(rp + 1) * 129 + c] + bias[col];
                    __half2 p = __floats2half2_rn(v0, v1);
                    size_t off = (((size_t)(b * NHEAD + hh) * 16 + kvblk) * HDIM + d) * 64 + kvin;
                    *reinterpret_cast<uint32_t*>(vt16 + off) = *reinterpret_cast<uint32_t*>(&p);
                }
            }
        }
        __syncthreads();
    }

    if (wid == 0) { TC_RELINQ(); TC_DEALLOC(tmem, 256); }
#endif
}

// ---------------------------------------------------------------------------
// tcgen05 fp16 attention, kv-tile 128, ~84KB smem => 2 CTAs/SM, TMEM 256 each.
// ---------------------------------------------------------------------------
#define AT_Q   2048
#define AT_K   (AT_Q + 16384)    // 18432
#define AT_V   (AT_K + 16384)    // 34816  (2 blocks of [64d x 64kv] = 16KB)
#define AT_P   (AT_V + 16384)    // 51200  (2 blocks of [128q x 64kv] = 32KB)
#define SMEM_ATTN (AT_P + 32768 + 1024)   // 84992

#if HAS_TCGEN05
__device__ __forceinline__ void cp_tile16k(uint32_t dst, const __half* src, int tid)
{
    const char* g = reinterpret_cast<const char*>(src);
    #pragma unroll
    for (int t = 0; t < 4; t++) {
        uint32_t bo = (uint32_t)(tid + t * 256) * 16;
        CP_ASYNC16(dst + SWZ128(bo), g + bo);
    }
}
#endif

__global__ __launch_bounds__(256, 2)
void attn_tc_kernel(const __half* __restrict__ q16, const __half* __restrict__ k16,
                    const __half* __restrict__ vt16, __half* __restrict__ o16)
{
#if HAS_TCGEN05
    extern __shared__ char smem[];
    uint32_t sb = smem_u32(smem);
    uint32_t ab = (sb + 1023u) & ~1023u;
    char* smp = smem + (ab - sb);

    int tid = threadIdx.x;
    int wid = tid >> 5, lane = tid & 31;
    int sub = wid & 3, half_ = wid >> 2;
    int row = sub * 32 + lane;
    int qt = blockIdx.x, h = blockIdx.y, b = blockIdx.z;

    if (wid == 0) TC_ALLOC(ab + 0, 256);
    if (tid == 0) { MBAR_INIT(ab + 8, 1); MBAR_INIT(ab + 16, 1); }  // S, O
    __syncthreads();
    uint32_t tmem;
    asm volatile("ld.shared.b32 %0, [%1];" : "=r"(tmem) : "r"(ab + 0));
    // TMEM: S @ +0 (128 cols), O @ +128 (64 cols)

    const size_t bh = (size_t)(b * NHEAD + h);
    const size_t qbase = (bh * SEQ + (size_t)qt * 128) * HDIM;

    // prologue: Q + K(0)
    cp_tile16k(ab + AT_Q, q16 + qbase, tid);
    cp_tile16k(ab + AT_K, k16 + bh * SEQ * HDIM, tid);
    CP_COMMIT();

    float rsum = 0.f;
    const float scale = 0.125f;

    for (int kt = 0; kt < 8; kt++) {
        CP_WAIT0();              // K(kt) in smem
        __syncthreads();
        FENCE_ASYNC();

        // ---- issue S = Q K^T ----
        if (wid == 0 && elect_one()) {
            uint64_t qd = MAKE_DESC(ab + AT_Q);
            uint64_t kd = MAKE_DESC(ab + AT_K);
            #pragma unroll
            for (int ks = 0; ks < 4; ks++)
                mma_ss_f16(tmem, qd + ks * 2, kd + ks * 2, IDESC16_N128,
                           ks > 0 ? 1u : 0u);
            TC_COMMIT(ab + 8);
        }

        // ---- wait O(kt-1) (frees V, P), async-load V(kt) ----
        if (kt > 0) MBAR_WAIT(ab + 16, (kt - 1) & 1);
        {
            const size_t vbase = (bh * 16 + (size_t)kt * 2) * (HDIM * 64);
            cp_tile16k(ab + AT_V, vt16 + vbase, tid);
            CP_COMMIT();
        }

        // ---- wait S(kt), exp + cvt P -> fp16 smem ----
        MBAR_WAIT(ab + 8, kt & 1);
        TC_FENCE_AFTER();
        {
            uint32_t r0[32], r1[32];
            TC_LD_X32(r0, tmem + half_ * 64);
            TC_LD_X32(r1, tmem + half_ * 64 + 32);
            TC_WAIT_LD();
            char* pB = smp + AT_P + half_ * 16384;
            #pragma unroll
            for (int g = 0; g < 8; g++) {
                float e[8];
                #pragma unroll
                for (int j = 0; j < 8; j++) {
                    int c = g * 8 + j;
                    float s = __uint_as_float(c < 32 ? r0[c] : r1[c - 32]);
                    e[j] = __expf(s * scale);
                    rsum += e[j];
                }
                __half2 h0 = __floats2half2_rn(e[0], e[1]);
                __half2 h1 = __floats2half2_rn(e[2], e[3]);
                __half2 h2 = __floats2half2_rn(e[4], e[5]);
                __half2 h3 = __floats2half2_rn(e[6], e[7]);
                uint4 o;
                o.x = *reinterpret_cast<uint32_t*>(&h0);
                o.y = *reinterpret_cast<uint32_t*>(&h1);
                o.z = *reinterpret_cast<uint32_t*>(&h2);
                o.w = *reinterpret_cast<uint32_t*>(&h3);
                *reinterpret_cast<uint4*>(pB + SWZ128((uint32_t)(row * 128 + g * 16))) = o;
            }
            TC_FENCE_BEFORE();
        }
        CP_WAIT0();              // V(kt) arrived (overlapped with exp)
        __syncthreads();         // P + V visible
        FENCE_ASYNC();

        // ---- issue O += P V ----
        if (wid == 0 && elect_one()) {
            #pragma unroll
            for (int blk = 0; blk < 2; blk++) {
                uint64_t pd = MAKE_DESC(ab + AT_P + blk * 16384);
                uint64_t vd = MAKE_DESC(ab + AT_V + blk * 8192);
                #pragma unroll
                for (int ks = 0; ks < 4; ks++) {
                    uint32_t acc = (kt == 0 && blk == 0 && ks == 0) ? 0u : 1u;
                    mma_ss_f16(tmem + 128, pd + ks * 2, vd + ks * 2, IDESC16_N64, acc);
                }
            }
            TC_COMMIT(ab + 16);
        }

        // ---- prefetch K(kt+1) under O-MMA (S(kt) drained K) ----
        if (kt < 7) {
            const size_t kbase = (bh * SEQ + (size_t)(kt + 1) * 128) * HDIM;
            cp_tile16k(ab + AT_K, k16 + kbase, tid);
        }
        CP_COMMIT();
    }
    MBAR_WAIT(ab + 16, 7 & 1);
    TC_FENCE_AFTER();

    // ---- normalize O and write fp16 output ----
    float* rs = reinterpret_cast<float*>(smp + 512);   // [2][128]
    rs[half_ * 128 + row] = rsum;
    __syncthreads();

    {
        uint32_t o[32];
        TC_LD_X32(o, tmem + 128 + half_ * 32);
        TC_WAIT_LD();
        TC_FENCE_BEFORE();
        float inv = 1.0f / (rs[row] + rs[128 + row]);
        size_t off = ((size_t)(b * SEQ + qt * 128 + row)) * DIMC + h * HDIM + half_ * 32;
        #pragma unroll
        for (int j = 0; j < 32; j += 2) {
            __half2 p = __floats2half2_rn(__uint_as_float(o[j]) * inv,
                                          __uint_as_float(o[j + 1]) * inv);
            *reinterpret_cast<uint32_t*>(o16 + off + j) = *reinterpret_cast<uint32_t*>(&p);
        }
    }

    __syncthreads();
    if (wid == 0) { TC_RELINQ(); TC_DEALLOC(tmem, 256); }
#endif  // HAS_TCGEN05
}

// ---------------------------------------------------------------------------
// fp32 fallbacks (proven round-1 kernels)
// ---------------------------------------------------------------------------
__global__ __launch_bounds__(256)
void sgemm_bias_kernel(const float* __restrict__ A, const float* __restrict__ Bm,
                       const float* __restrict__ bias, float* __restrict__ C,
                       int M, int N, int K)
{
    const int BK = 16, PAD = 132;
    __shared__ float As[BK * PAD];
    __shared__ float Bs[BK * PAD];

    int tid = threadIdx.x;
    int tx = tid & 15, ty = tid >> 4;
    int rowBase = blockIdx.y * 128;
    int colBase = blockIdx.x * 128;

    float acc[8][8] = {};

    for (int k0 = 0; k0 < K; k0 += BK) {
        #pragma unroll
        for (int t = 0; t < 2; t++) {
            int i  = tid + t * 256;
            int r  = i >> 2;
            int kq = (i & 3) << 2;
            float4 v = *reinterpret_cast<const float4*>(
                &A[(size_t)(rowBase + r) * K + k0 + kq]);
            As[(kq + 0) * PAD + r] = v.x;
            As[(kq + 1) * PAD + r] = v.y;
            As[(kq + 2) * PAD + r] = v.z;
            As[(kq + 3) * PAD + r] = v.w;
        }
        #pragma unroll
        for (int t = 0; t < 2; t++) {
            int i  = tid + t * 256;
            int kk = i >> 5;
            int n4 = (i & 31) << 2;
            float4 v = *reinterpret_cast<const float4*>(
                &Bm[(size_t)(k0 + kk) * N + colBase + n4]);
            *reinterpret_cast<float4*>(&Bs[kk * PAD + n4]) = v;
        }
        __syncthreads();

        #pragma unroll
        for (int kk = 0; kk < BK; kk++) {
            float a[8], bb[8];
            *(float4*)&a[0] = *(float4*)&As[kk * PAD + ty * 8];
            *(float4*)&a[4] = *(float4*)&As[kk * PAD + ty * 8 + 4];
            *(float4*)&bb[0] = *(float4*)&Bs[kk * PAD + tx * 8];
            *(float4*)&bb[4] = *(float4*)&Bs[kk * PAD + tx * 8 + 4];
            #pragma unroll
            for (int i = 0; i < 8; i++)
                #pragma unroll
                for (int j = 0; j < 8; j++)
                    acc[i][j] += a[i] * bb[j];
        }
        __syncthreads();
    }

    #pragma unroll
    for (int i = 0; i < 8; i++) {
        int r = rowBase + ty * 8 + i;
        #pragma unroll
        for (int j = 0; j < 8; j += 4) {
            int c = colBase + tx * 8 + j;
            float4 v;
            v.x = acc[i][j + 0] + bias[c + 0];
            v.y = acc[i][j + 1] + bias[c + 1];
            v.z = acc[i][j + 2] + bias[c + 2];
            v.w = acc[i][j + 3] + bias[c + 3];
            *reinterpret_cast<float4*>(&C[(size_t)r * N + c]) = v;
        }
    }
}

__global__ __launch_bounds__(256)
void attn_kernel()
{
    extern __shared__ float sm[];
    float* Qs  = sm;
    float* Ks  = Qs + 64 * 64;
    float* Vs  = Ks + 64 * 65;
    float* Ss  = Vs + 64 * 64;
    float* m_s = Ss + 64 * 65;
    float* l_s = m_s + 64;
    float* a_s = l_s + 64;

    int qt = blockIdx.x, h = blockIdx.y, b = blockIdx.z;
    int tid = threadIdx.x;
    int tx = tid & 15, ty = tid >> 4;
    const float scale = 0.125f;
    const int RS = 3 * DIMC;

    size_t qoff = ((size_t)(b * SEQ + qt * 64)) * RS + h * HDIM;

    #pragma unroll
    for (int t = 0; t < 4; t++) {
        int i  = tid + t * 256;
        int r  = i >> 4;
        int d4 = (i & 15) << 2;
        float4 v = *reinterpret_cast<const float4*>(&g_qkv[qoff + (size_t)r * RS + d4]);
        *reinterpret_cast<float4*>(&Qs[r * 64 + d4]) = v;
    }
    if (tid < 64) { m_s[tid] = -1e30f; l_s[tid] = 0.f; }
    float O[4][4] = {};
    __syncthreads();

    for (int kt = 0; kt < 16; kt++) {
        size_t koff = ((size_t)(b * SEQ + kt * 64)) * RS + DIMC + h * HDIM;
        size_t voff = koff + DIMC;
        #pragma unroll
        for (int t = 0; t < 4; t++) {
            int i  = tid + t * 256;
            int r  = i >> 4;
            int d4 = (i & 15) << 2;
            float4 kv = *reinterpret_cast<const float4*>(&g_qkv[koff + (size_t)r * RS + d4]);
            Ks[r * 65 + d4 + 0] = kv.x;
            Ks[r * 65 + d4 + 1] = kv.y;
            Ks[r * 65 + d4 + 2] = kv.z;
            Ks[r * 65 + d4 + 3] = kv.w;
            float4 vv = *reinterpret_cast<const float4*>(&g_qkv[voff + (size_t)r * RS + d4]);
            *reinterpret_cast<float4*>(&Vs[r * 64 + d4]) = vv;
        }
        __syncthreads();

        float s[4][4] = {};
        #pragma unroll 8
        for (int d = 0; d < 64; d++) {
            float qv[4], kv[4];
            #pragma unroll
            for (int i = 0; i < 4; i++) qv[i] = Qs[(ty * 4 + i) * 64 + d];
            #pragma unroll
            for (int j = 0; j < 4; j++) kv[j] = Ks[(tx * 4 + j) * 65 + d];
            #pragma unroll
            for (int i = 0; i < 4; i++)
                #pragma unroll
                for (int j = 0; j < 4; j++)
                    s[i][j] += qv[i] * kv[j];
        }
        #pragma unroll
        for (int i = 0; i < 4; i++)
            #pragma unroll
            for (int j = 0; j < 4; j++)
                Ss[(ty * 4 + i) * 65 + tx * 4 + j] = s[i][j] * scale;
        __syncthreads();

        if (tid < 64) {
            float mold = m_s[tid];
            float mx = mold;
            #pragma unroll 8
            for (int j = 0; j < 64; j++) mx = fmaxf(mx, Ss[tid * 65 + j]);
            float sum = 0.f;
            #pragma unroll 8
            for (int j = 0; j < 64; j++) {
                float p = __expf(Ss[tid * 65 + j] - mx);
                Ss[tid * 65 + j] = p;
                sum += p;
            }
            float alpha = __expf(mold - mx);
            a_s[tid] = alpha;
            m_s[tid] = mx;
            l_s[tid] = l_s[tid] * alpha + sum;
        }
        __syncthreads();

        float alpha[4];
        #pragma unroll
        for (int i = 0; i < 4; i++) alpha[i] = a_s[ty * 4 + i];
        #pragma unroll
        for (int i = 0; i < 4; i++)
            #pragma unroll
            for (int j = 0; j < 4; j++)
                O[i][j] *= alpha[i];
        #pragma unroll 8
        for (int kv = 0; kv < 64; kv++) {
            float p[4], v[4];
            #pragma unroll
            for (int i = 0; i < 4; i++) p[i] = Ss[(ty * 4 + i) * 65 + kv];
            #pragma unroll
            for (int j = 0; j < 4; j++) v[j] = Vs[kv * 64 + tx * 4 + j];
            #pragma unroll
            for (int i = 0; i < 4; i++)
                #pragma unroll
                for (int j = 0; j < 4; j++)
                    O[i][j] += p[i] * v[j];
        }
        __syncthreads();
    }

    float inv_l[4];
    #pragma unroll
    for (int i = 0; i < 4; i++) inv_l[i] = 1.0f / l_s[ty * 4 + i];
    #pragma unroll
    for (int i = 0; i < 4; i++) {
        int q = qt * 64 + ty * 4 + i;
        size_t off = ((size_t)(b * SEQ + q)) * DIMC + h * HDIM + tx * 4;
        float4 v;
        v.x = O[i][0] * inv_l[i];
        v.y = O[i][1] * inv_l[i];
        v.z = O[i][2] * inv_l[i];
        v.w = O[i][3] * inv_l[i];
        *reinterpret_cast<float4*>(&g_attn[off]) = v;
    }
}

// ---------------------------------------------------------------------------

extern "C" void kernel_launch(void* const* d_in, const int* in_sizes, int n_in,
                              void* d_out, int out_size)
{
    const float* x     = (const float*)d_in[0];
    const float* Wqkv  = (const float*)d_in[1];
    const float* bqkv  = (const float*)d_in[2];
    const float* Wproj = (const float*)d_in[3];
    const float* bproj = (const float*)d_in[4];
    float* out = (float*)d_out;

    float *qkv = nullptr, *attn = nullptr;
    __half *a16, *wq16, *wp16, *q16, *k16, *vt16;
    cudaGetSymbolAddress((void**)&qkv,  g_qkv);
    cudaGetSymbolAddress((void**)&attn, g_attn);
    cudaGetSymbolAddress((void**)&a16,  g_a16);
    cudaGetSymbolAddress((void**)&wq16, g_wq16);
    cudaGetSymbolAddress((void**)&wp16, g_wp16);
    cudaGetSymbolAddress((void**)&q16,  g_q16);
    cudaGetSymbolAddress((void**)&k16,  g_k16);
    cudaGetSymbolAddress((void**)&vt16, g_vt16);

    cudaFuncAttributes pa{};
    cudaFuncGetAttributes(&pa, feat_probe);
    bool use_tc = pa.sharedSizeBytes >= 1024;

    dim3 blk(256);

    if (use_tc) {
        cudaFuncSetAttribute(gemm_f16_kernel<0>,
                             cudaFuncAttributeMaxDynamicSharedMemorySize, SMEM_GEMM);
        cudaFuncSetAttribute(gemm_f16_kernel<1>,
                             cudaFuncAttributeMaxDynamicSharedMemorySize, SMEM_GEMM);
        cudaFuncSetAttribute(attn_tc_kernel,
                             cudaFuncAttributeMaxDynamicSharedMemorySize, SMEM_ATTN);

        int n4 = MTOT * DIMC / 4;
        cvt16_kernel<<<(n4 + 255) / 256, 256>>>(x, a16, n4);
        dim3 tb(32, 32);
        transpose_cvt16_kernel<<<dim3(NQKV / 32, DIMC / 32), tb>>>(Wqkv, wq16, DIMC, NQKV);
        transpose_cvt16_kernel<<<dim3(DIMC / 32, DIMC / 32), tb>>>(Wproj, wp16, DIMC, DIMC);

        // QKV GEMM (fp16, 128x256) with fused repack epilogue
        dim3 g1(NQKV / 256, MTOT / 128);    // 9 x 64
        gemm_f16_kernel<1><<<g1, blk, SMEM_GEMM>>>(a16, wq16, bqkv,
                                                   nullptr, NQKV, DIMC,
                                                   q16, k16, vt16);

        // attention (fp16, 2 CTAs/SM), writes fp16 output into a16
        dim3 g2(SEQ / 128, NHEAD, BATCH);
        attn_tc_kernel<<<g2, blk, SMEM_ATTN>>>(q16, k16, vt16, a16);

        // projection (fp16 in, fp32 out)
        dim3 g3(DIMC / 256, MTOT / 128);    // 3 x 64
        gemm_f16_kernel<0><<<g3, blk, SMEM_GEMM>>>(a16, wp16, bproj,
                                                   out, DIMC, DIMC,
                                                   nullptr, nullptr, nullptr);
    } else {
        const int ATTN_SMEM = (64*64 + 64*65 + 64*64 + 64*65 + 3*64) * 4;
        cudaFuncSetAttribute(attn_kernel,
                             cudaFuncAttributeMaxDynamicSharedMemorySize, ATTN_SMEM);
        dim3 g1(NQKV / 128, MTOT / 128);
        sgemm_bias_kernel<<<g1, blk>>>(x, Wqkv, bqkv, qkv, MTOT, NQKV, DIMC);

        dim3 g2(SEQ / 64, NHEAD, BATCH);
        attn_kernel<<<g2, blk, ATTN_SMEM>>>();

        dim3 g3(DIMC / 128, MTOT / 128);
        sgemm_bias_kernel<<<g3, blk>>>(attn, Wproj, bproj, out, MTOT, DIMC, DIMC);
    }
}

// round 11
// speedup vs baseline: 2.7656x; 1.0957x over previous
#include <cuda_runtime.h>
#include <cuda_bf16.h>
#include <cuda_fp16.h>
#include <math.h>
#include <stdint.h>

#define DIMC 768
#define NHEAD 12
#define HDIM 64
#define BATCH 8
#define SEQ 1024
#define MTOT (BATCH*SEQ)   // 8192
#define NQKV (3*DIMC)      // 2304

#if defined(__CUDA_ARCH__) && (defined(__CUDA_ARCH_FEAT_SM103_ALL) || defined(__CUDA_ARCH_FEAT_SM100_ALL))
#define HAS_TCGEN05 1
#else
#define HAS_TCGEN05 0
#endif

// ---------------------------------------------------------------------------
// Scratch
// ---------------------------------------------------------------------------
__device__ __align__(16) float g_qkv[(size_t)MTOT * NQKV];      // fallback only
__device__ __align__(16) float g_attn[(size_t)MTOT * DIMC];     // fallback only
__device__ __align__(16) __half g_a16[(size_t)MTOT * DIMC];
__device__ __align__(16) __half g_wq16[(size_t)NQKV * DIMC];
__device__ __align__(16) __half g_wp16[(size_t)DIMC * DIMC];
__device__ __align__(16) __half g_q16[(size_t)BATCH * NHEAD * SEQ * HDIM];
__device__ __align__(16) __half g_k16[(size_t)BATCH * NHEAD * SEQ * HDIM];
__device__ __align__(16) __half g_vt16[(size_t)BATCH * NHEAD * SEQ * HDIM];

// ---------------------------------------------------------------------------
// Probe kernel (host dispatch signal)
// ---------------------------------------------------------------------------
__global__ void feat_probe(int* out) {
#if HAS_TCGEN05
    __shared__ int s[256];
#else
    __shared__ int s[2];
#endif
    int n = (int)(sizeof(s) / sizeof(int));
    s[threadIdx.x % n] = (int)clock();
    __syncthreads();
    if (out) *out = s[0];
}

// ---------------------------------------------------------------------------
// fp32 -> fp16 convert kernels
// ---------------------------------------------------------------------------
__global__ __launch_bounds__(256)
void cvt16_kernel(const float* __restrict__ src, __half* __restrict__ dst, int n4)
{
    int i = blockIdx.x * blockDim.x + threadIdx.x;
    if (i >= n4) return;
    float4 v = reinterpret_cast<const float4*>(src)[i];
    __half2 a = __floats2half2_rn(v.x, v.y);
    __half2 b = __floats2half2_rn(v.z, v.w);
    uint2 o;
    o.x = *reinterpret_cast<uint32_t*>(&a);
    o.y = *reinterpret_cast<uint32_t*>(&b);
    reinterpret_cast<uint2*>(dst)[i] = o;
}

__global__ __launch_bounds__(1024)
void transpose_cvt16_kernel(const float* __restrict__ W,
                            __half* __restrict__ T16, int K, int N)
{
    __shared__ float t[32][33];
    int n0 = blockIdx.x * 32, k0 = blockIdx.y * 32;
    int tx = threadIdx.x, ty = threadIdx.y;
    t[ty][tx] = W[(size_t)(k0 + ty) * N + n0 + tx];
    __syncthreads();
    T16[(size_t)(n0 + ty) * K + k0 + tx] = __float2half_rn(t[tx][ty]);
}

// ---------------------------------------------------------------------------
// helpers
// ---------------------------------------------------------------------------
__device__ __forceinline__ uint32_t smem_u32(const void* p) {
    uint32_t a;
    asm("{ .reg .u64 t; cvta.to.shared.u64 t, %1; cvt.u32.u64 %0, t; }"
        : "=r"(a) : "l"(p));
    return a;
}

#define SWZ128(o) ((o) ^ (((o) >> 3) & 0x70))

#define MBAR_INIT(addr, cnt) \
    asm volatile("mbarrier.init.shared.b64 [%0], %1;" :: "r"(addr), "r"(cnt) : "memory")

#define MBAR_WAIT(addr, parity) do {                                          \
    uint32_t _m = (addr); uint32_t _p = (parity); uint32_t _done;             \
    asm volatile("{\n\t.reg .pred p;\n\t"                                     \
        "mbarrier.try_wait.parity.acquire.cta.shared::cta.b64 p, [%1], %2;\n\t"\
        "selp.b32 %0, 1, 0, p;\n\t}" : "=r"(_done) : "r"(_m), "r"(_p) : "memory");\
    if (!_done) {                                                             \
        asm volatile("{\n\t.reg .pred P1;\n\t"                                \
            "WL_%=:\n\t"                                                      \
            "mbarrier.try_wait.parity.acquire.cta.shared::cta.b64 P1, [%0], %1, 0x989680;\n\t"\
            "@P1 bra.uni WD_%=;\n\t"                                          \
            "bra.uni WL_%=;\n\t"                                              \
            "WD_%=:\n\t}" :: "r"(_m), "r"(_p) : "memory");                    \
    }                                                                         \
} while (0)

#if HAS_TCGEN05
__device__ __forceinline__ uint32_t elect_one() {
    uint32_t pred;
    asm volatile("{\n\t.reg .pred p;\n\telect.sync _|p, 0xFFFFFFFF;\n\t"
                 "selp.b32 %0, 1, 0, p;\n\t}" : "=r"(pred));
    return pred;
}

#define TC_ALLOC(sm_dst, ncols) \
    asm volatile("tcgen05.alloc.cta_group::1.sync.aligned.shared::cta.b32 [%0], %1;" \
                 :: "r"(sm_dst), "r"(ncols) : "memory")
#define TC_DEALLOC(tm, ncols) \
    asm volatile("tcgen05.dealloc.cta_group::1.sync.aligned.b32 %0, %1;" :: "r"(tm), "r"(ncols))
#define TC_RELINQ() \
    asm volatile("tcgen05.relinquish_alloc_permit.cta_group::1.sync.aligned;")
#define TC_COMMIT(mbar) \
    asm volatile("tcgen05.commit.cta_group::1.mbarrier::arrive::one.shared::cluster.b64 [%0];" \
                 :: "r"(mbar) : "memory")
#define TC_FENCE_AFTER()  asm volatile("tcgen05.fence::after_thread_sync;" ::: "memory")
#define TC_FENCE_BEFORE() asm volatile("tcgen05.fence::before_thread_sync;" ::: "memory")
#define TC_WAIT_LD() asm volatile("tcgen05.wait::ld.sync.aligned;" ::: "memory")
#define TC_WAIT_ST() asm volatile("tcgen05.wait::st.sync.aligned;" ::: "memory")
#define FENCE_ASYNC() asm volatile("fence.proxy.async.shared::cta;" ::: "memory")

#define CP_ASYNC16(dst, src) \
    asm volatile("cp.async.cg.shared.global [%0], [%1], 16;" :: "r"(dst), "l"(src) : "memory")
#define CP_COMMIT() asm volatile("cp.async.commit_group;" ::: "memory")
#define CP_WAIT1()  asm volatile("cp.async.wait_group 1;" ::: "memory")
#define CP_WAIT0()  asm volatile("cp.async.wait_group 0;" ::: "memory")

#define TC_LD_X32(r, tm) \
    asm volatile("tcgen05.ld.sync.aligned.32x32b.x32.b32 "                    \
        "{%0, %1, %2, %3, %4, %5, %6, %7, "                                   \
        " %8, %9, %10, %11, %12, %13, %14, %15, "                             \
        " %16, %17, %18, %19, %20, %21, %22, %23, "                           \
        " %24, %25, %26, %27, %28, %29, %30, %31}, [%32];"                    \
        : "=r"((r)[0]),  "=r"((r)[1]),  "=r"((r)[2]),  "=r"((r)[3]),          \
          "=r"((r)[4]),  "=r"((r)[5]),  "=r"((r)[6]),  "=r"((r)[7]),          \
          "=r"((r)[8]),  "=r"((r)[9]),  "=r"((r)[10]), "=r"((r)[11]),         \
          "=r"((r)[12]), "=r"((r)[13]), "=r"((r)[14]), "=r"((r)[15]),         \
          "=r"((r)[16]), "=r"((r)[17]), "=r"((r)[18]), "=r"((r)[19]),         \
          "=r"((r)[20]), "=r"((r)[21]), "=r"((r)[22]), "=r"((r)[23]),         \
          "=r"((r)[24]), "=r"((r)[25]), "=r"((r)[26]), "=r"((r)[27]),         \
          "=r"((r)[28]), "=r"((r)[29]), "=r"((r)[30]), "=r"((r)[31])          \
        : "r"(tm))

#define TC_ST_X32(tm, r) \
    asm volatile("tcgen05.st.sync.aligned.32x32b.x32.b32 [%0], "              \
        "{%1, %2, %3, %4, %5, %6, %7, %8, "                                   \
        " %9, %10, %11, %12, %13, %14, %15, %16, "                            \
        " %17, %18, %19, %20, %21, %22, %23, %24, "                           \
        " %25, %26, %27, %28, %29, %30, %31, %32};"                           \
        :: "r"(tm),                                                           \
           "r"((r)[0]),  "r"((r)[1]),  "r"((r)[2]),  "r"((r)[3]),             \
           "r"((r)[4]),  "r"((r)[5]),  "r"((r)[6]),  "r"((r)[7]),             \
           "r"((r)[8]),  "r"((r)[9]),  "r"((r)[10]), "r"((r)[11]),            \
           "r"((r)[12]), "r"((r)[13]), "r"((r)[14]), "r"((r)[15]),            \
           "r"((r)[16]), "r"((r)[17]), "r"((r)[18]), "r"((r)[19]),            \
           "r"((r)[20]), "r"((r)[21]), "r"((r)[22]), "r"((r)[23]),            \
           "r"((r)[24]), "r"((r)[25]), "r"((r)[26]), "r"((r)[27]),            \
           "r"((r)[28]), "r"((r)[29]), "r"((r)[30]), "r"((r)[31])             \
        : "memory")

#define MAKE_DESC(base) \
    ((uint64_t(2) << 61) | (uint64_t(1) << 46) | (uint64_t(64) << 32) | \
     (uint64_t(1) << 16) | ((uint64_t)((base) >> 4) & 0x3FFF))

__device__ __forceinline__ void mma_ss_f16(uint32_t d, uint64_t ad, uint64_t bd,
                                           uint32_t idesc, uint32_t en) {
    asm volatile(
        "{\n\t.reg .pred p;\n\t"
        "setp.ne.u32 p, %4, 0;\n\t"
        "tcgen05.mma.cta_group::1.kind::f16 [%0], %1, %2, %3, {%5, %5, %5, %5}, p;\n\t}"
        :: "r"(d), "l"(ad), "l"(bd), "r"(idesc), "r"(en), "r"(0u) : "memory");
}

// TS mode: A in TMEM (lane = M row, 2 fp16 K per col; +8 cols per K=16 step)
__device__ __forceinline__ void mma_ts_f16(uint32_t d, uint32_t a_tmem, uint64_t bd,
                                           uint32_t idesc, uint32_t en) {
    asm volatile(
        "{\n\t.reg .pred p;\n\t"
        "setp.ne.u32 p, %4, 0;\n\t"
        "tcgen05.mma.cta_group::1.kind::f16 [%0], [%1], %2, %3, {%5, %5, %5, %5}, p;\n\t}"
        :: "r"(d), "r"(a_tmem), "l"(bd), "r"(idesc), "r"(en), "r"(0u) : "memory");
}

// fp16 inputs, fp32 accum, M=128
#define IDESC16_N128 (0x10u | (16u << 17) | (8u << 24))
#define IDESC16_N64  (0x10u | (8u  << 17) | (8u << 24))
#endif  // HAS_TCGEN05

// ---------------------------------------------------------------------------
// tcgen05 fp16 GEMM — 256x256 tile (4 TMEM quadrants), 3-stage cp.async,
// deferred MMA wait. MODE 0: fp32 out + bias; MODE 1: QKV repack epilogue.
// ---------------------------------------------------------------------------
#define ST16_STG 65536                    // A 32K + B 32K
#define SMEM_GEMM (1024 + 1024 + 3 * ST16_STG)   // 198656

template<int MODE>
__global__ __launch_bounds__(256, 1)
void gemm_f16_kernel(const __half* __restrict__ A16,
                     const __half* __restrict__ B16,
                     const float* __restrict__ bias,
                     float* __restrict__ C, int N, int K,
                     __half* q16, __half* k16, __half* vt16)
{
#if HAS_TCGEN05
    extern __shared__ char smem[];
    uint32_t sb = smem_u32(smem);
    uint32_t ab = (sb + 1023u) & ~1023u;
    char* smp = smem + (ab - sb);

    int tid = threadIdx.x;
    int wid = tid >> 5, lid = tid & 31;
    int rowBase = blockIdx.y * 256;
    int colBase = blockIdx.x * 256;

    if (wid == 0) TC_ALLOC(ab + 0, 512);
    if (tid == 0) { MBAR_INIT(ab + 8, 1); MBAR_INIT(ab + 16, 1); MBAR_INIT(ab + 24, 1); }
    __syncthreads();
    uint32_t tmem;
    asm volatile("ld.shared.b32 %0, [%1];" : "=r"(tmem) : "r"(ab + 0));
    // TMEM: D(mh,ct) at mh*256 + ct*128

    const int KC = K >> 6;
    const size_t rowK = (size_t)K;

    auto load_stage = [&](int kc, int buf) {
        uint32_t st = ab + 1024 + buf * ST16_STG;
        // A: 256 rows x 128B -> two 16K sub-tiles
        {
            const char* g = reinterpret_cast<const char*>(
                A16 + (size_t)rowBase * rowK + kc * 64);
            #pragma unroll
            for (int t = 0; t < 8; t++) {
                int i = tid + t * 256;
                int r = i >> 3, c = i & 7;
                uint32_t dst = st + (r >> 7) * 16384
                             + SWZ128((uint32_t)((r & 127) * 128 + c * 16));
                CP_ASYNC16(dst, g + (size_t)r * (rowK * 2) + c * 16);
            }
        }
        // B: 256 rows x 128B -> two 16K sub-tiles
        {
            const char* g = reinterpret_cast<const char*>(
                B16 + (size_t)colBase * rowK + kc * 64);
            #pragma unroll
            for (int t = 0; t < 8; t++) {
                int i = tid + t * 256;
                int r = i >> 3, c = i & 7;
                uint32_t dst = st + 32768 + (r >> 7) * 16384
                             + SWZ128((uint32_t)((r & 127) * 128 + c * 16));
                CP_ASYNC16(dst, g + (size_t)r * (rowK * 2) + c * 16);
            }
        }
    };

    load_stage(0, 0); CP_COMMIT();
    load_stage(1, 1); CP_COMMIT();

    int ph[3] = { 0, 0, 0 };

    for (int kc = 0; kc < KC; kc++) {
        int buf = kc - (kc / 3) * 3;
        CP_WAIT1();
        __syncthreads();
        FENCE_ASYNC();

        uint32_t st = ab + 1024 + buf * ST16_STG;
        if (wid == 0 && elect_one()) {
            #pragma unroll
            for (int ks = 0; ks < 4; ks++) {
                uint64_t off = ks * 2;
                #pragma unroll
                for (int mh = 0; mh < 2; mh++) {
                    uint64_t ahd = MAKE_DESC(st + mh * 16384);
                    #pragma unroll
                    for (int ct = 0; ct < 2; ct++) {
                        uint64_t bhd = MAKE_DESC(st + 32768 + ct * 16384);
                        mma_ss_f16(tmem + mh * 256 + ct * 128,
                                   ahd + off, bhd + off, IDESC16_N128,
                                   (kc == 0 && ks == 0) ? 0u : 1u);
                    }
                }
            }
            TC_COMMIT(ab + 8 + 8 * buf);
        }

        // wait PREVIOUS chunk's MMA (frees the buffer load(kc+2) will fill)
        if (kc >= 1) {
            int pb = (kc - 1) % 3;
            MBAR_WAIT(ab + 8 + 8 * pb, ph[pb] & 1); ph[pb]++;
        }
        if (kc + 2 < KC) load_stage(kc + 2, (kc + 2) % 3);
        CP_COMMIT();
    }
    {
        int lb = (KC - 1) % 3;
        MBAR_WAIT(ab + 8 + 8 * lb, ph[lb] & 1);
    }
    CP_WAIT0();
    TC_FENCE_AFTER();

    float* Ct = reinterpret_cast<float*>(smp + 1024);
    #pragma unroll
    for (int mh = 0; mh < 2; mh++) {
        #pragma unroll
        for (int ct = 0; ct < 2; ct++) {
            int colB = colBase + ct * 128;
            int rowB = rowBase + mh * 128;
            if (wid < 4) {
                int row = wid * 32 + lid;
                #pragma unroll
                for (int cb = 0; cb < 4; cb++) {
                    uint32_t r[32];
                    TC_LD_X32(r, tmem + mh * 256 + ct * 128 + cb * 32);
                    TC_WAIT_LD();
                    #pragma unroll
                    for (int j = 0; j < 32; j++)
                        Ct[row * 129 + cb * 32 + j] = __uint_as_float(r[j]);
                }
                TC_FENCE_BEFORE();
            }
            __syncthreads();

            if (MODE == 0) {
                for (int i = tid; i < 128 * 32; i += 256) {
                    int r = i >> 5, c = (i & 31) * 4;
                    float4 v;
                    v.x = Ct[r * 129 + c + 0] + bias[colB + c + 0];
                    v.y = Ct[r * 129 + c + 1] + bias[colB + c + 1];
                    v.z = Ct[r * 129 + c + 2] + bias[colB + c + 2];
                    v.w = Ct[r * 129 + c + 3] + bias[colB + c + 3];
                    *reinterpret_cast<float4*>(&C[(size_t)(rowB + r) * N + colB + c]) = v;
                }
            } else {
                int type = colB / DIMC;
                if (type < 2) {
                    __half* dst = (type == 0) ? q16 : k16;
                    for (int i = tid; i < 128 * 32; i += 256) {
                        int r = i >> 5, c4 = (i & 31) * 4;
                        int token = rowB + r;
                        int b = token >> 10, tokin = token & 1023;
                        int col = colB + c4;
                        int hh = (col % DIMC) / HDIM;
                        int d = col & 63;
                        float v0 = Ct[r * 129 + c4 + 0] + bias[col + 0];
                        float v1 = Ct[r * 129 + c4 + 1] + bias[col + 1];
                        float v2 = Ct[r * 129 + c4 + 2] + bias[col + 2];
                        float v3 = Ct[r * 129 + c4 + 3] + bias[col + 3];
                        __half2 p0 = __floats2half2_rn(v0, v1);
                        __half2 p1 = __floats2half2_rn(v2, v3);
                        uint2 o;
                        o.x = *reinterpret_cast<uint32_t*>(&p0);
                        o.y = *reinterpret_cast<uint32_t*>(&p1);
                        size_t off = (((size_t)(b * NHEAD + hh) * SEQ + tokin) * HDIM + d);
                        *reinterpret_cast<uint2*>(dst + off) = o;
                    }
                } else {
                    for (int t = 0; t < 32; t++) {
                        int idx = t * 256 + tid;
                        int c  = idx >> 6;
                        int rp = (idx & 63) * 2;
                        int token = rowB + rp;
                        int b = token >> 10, tokin = token & 1023;
                        int kvblk = tokin >> 6, kvin = tokin & 63;
                        int col = colB + c;
                        int hh = (col % DIMC) / HDIM;
                        int d = col & 63;
                        float v0 = Ct[rp * 129 + c] + bias[col];
                        float v1 = Ct[(rp + 1) * 129 + c] + bias[col];
                        __half2 p = __floats2half2_rn(v0, v1);
                        size_t off = (((size_t)(b * NHEAD + hh) * 16 + kvblk) * HDIM + d) * 64 + kvin;
                        *reinterpret_cast<uint32_t*>(vt16 + off) = *reinterpret_cast<uint32_t*>(&p);
                    }
                }
            }
            __syncthreads();
        }
    }

    if (wid == 0) { TC_RELINQ(); TC_DEALLOC(tmem, 512); }
#endif
}

// ---------------------------------------------------------------------------
// tcgen05 fp16 attention: kv-tile 128, P lives in TMEM (TS-mode O MMA),
// ~51KB smem, 2 CTAs/SM (TMEM 256 each).
// TMEM: S @0 (128 cols fp32), P @128 (64 cols fp16x2), O @192 (64 cols fp32)
// ---------------------------------------------------------------------------
#define AT_Q   2048
#define AT_K   (AT_Q + 16384)    // 18432
#define AT_V   (AT_K + 16384)    // 34816  (2 blocks of [64d x 64kv])
#define SMEM_ATTN (AT_V + 16384 + 1024)   // 52224

#if HAS_TCGEN05
__device__ __forceinline__ void cp_tile16k(uint32_t dst, const __half* src, int tid)
{
    const char* g = reinterpret_cast<const char*>(src);
    #pragma unroll
    for (int t = 0; t < 4; t++) {
        uint32_t bo = (uint32_t)(tid + t * 256) * 16;
        CP_ASYNC16(dst + SWZ128(bo), g + bo);
    }
}
#endif

__global__ __launch_bounds__(256, 2)
void attn_tc_kernel(const __half* __restrict__ q16, const __half* __restrict__ k16,
                    const __half* __restrict__ vt16, __half* __restrict__ o16)
{
#if HAS_TCGEN05
    extern __shared__ char smem[];
    uint32_t sb = smem_u32(smem);
    uint32_t ab = (sb + 1023u) & ~1023u;
    char* smp = smem + (ab - sb);

    int tid = threadIdx.x;
    int wid = tid >> 5, lane = tid & 31;
    int sub = wid & 3, half_ = wid >> 2;
    int row = sub * 32 + lane;
    int qt = blockIdx.x, h = blockIdx.y, b = blockIdx.z;

    if (wid == 0) TC_ALLOC(ab + 0, 256);
    if (tid == 0) { MBAR_INIT(ab + 8, 1); MBAR_INIT(ab + 16, 1); }  // S, O
    __syncthreads();
    uint32_t tmem;
    asm volatile("ld.shared.b32 %0, [%1];" : "=r"(tmem) : "r"(ab + 0));

    const size_t bh = (size_t)(b * NHEAD + h);
    const size_t qbase = (bh * SEQ + (size_t)qt * 128) * HDIM;

    // prologue: Q + K(0)
    cp_tile16k(ab + AT_Q, q16 + qbase, tid);
    cp_tile16k(ab + AT_K, k16 + bh * SEQ * HDIM, tid);
    CP_COMMIT();

    float rsum = 0.f;
    const float scale = 0.125f;
    const uint32_t lane_base = (uint32_t)sub << 21;   // STTM subpartition base

    for (int kt = 0; kt < 8; kt++) {
        CP_WAIT0();              // K(kt) in smem
        __syncthreads();
        FENCE_ASYNC();

        // ---- issue S = Q K^T (SS mode) ----
        if (wid == 0 && elect_one()) {
            uint64_t qd = MAKE_DESC(ab + AT_Q);
            uint64_t kd = MAKE_DESC(ab + AT_K);
            #pragma unroll
            for (int ks = 0; ks < 4; ks++)
                mma_ss_f16(tmem, qd + ks * 2, kd + ks * 2, IDESC16_N128,
                           ks > 0 ? 1u : 0u);
            TC_COMMIT(ab + 8);
        }

        // ---- wait O(kt-1) (frees V smem AND P TMEM), async-load V(kt) ----
        if (kt > 0) MBAR_WAIT(ab + 16, (kt - 1) & 1);
        {
            const size_t vbase = (bh * 16 + (size_t)kt * 2) * (HDIM * 64);
            cp_tile16k(ab + AT_V, vt16 + vbase, tid);
            CP_COMMIT();
        }

        // ---- wait S(kt): LDTM -> exp -> pack fp16 -> STTM P ----
        MBAR_WAIT(ab + 8, kt & 1);
        TC_FENCE_AFTER();
        {
            uint32_t r0[32], r1[32];
            TC_LD_X32(r0, tmem + half_ * 64);
            TC_LD_X32(r1, tmem + half_ * 64 + 32);
            TC_WAIT_LD();
            uint32_t pk[32];
            #pragma unroll
            for (int g = 0; g < 8; g++) {
                float e[8];
                #pragma unroll
                for (int j = 0; j < 8; j++) {
                    int c = g * 8 + j;
                    float s = __uint_as_float(c < 32 ? r0[c] : r1[c - 32]);
                    e[j] = __expf(s * scale);
                    rsum += e[j];
                }
                __half2 h0 = __floats2half2_rn(e[0], e[1]);
                __half2 h1 = __floats2half2_rn(e[2], e[3]);
                __half2 h2 = __floats2half2_rn(e[4], e[5]);
                __half2 h3 = __floats2half2_rn(e[6], e[7]);
                pk[g * 4 + 0] = *reinterpret_cast<uint32_t*>(&h0);
                pk[g * 4 + 1] = *reinterpret_cast<uint32_t*>(&h1);
                pk[g * 4 + 2] = *reinterpret_cast<uint32_t*>(&h2);
                pk[g * 4 + 3] = *reinterpret_cast<uint32_t*>(&h3);
            }
            // P: cols [128,192); this warp writes 32 cols at 128 + half_*32
            TC_ST_X32(tmem + lane_base + 128 + half_ * 32, pk);
            TC_WAIT_ST();
            TC_FENCE_BEFORE();
        }
        CP_WAIT0();              // V(kt) arrived (overlapped with exp)
        __syncthreads();         // all warps' P in TMEM, V visible
        FENCE_ASYNC();

        // ---- issue O += P V (TS mode: A = P in TMEM) ----
        if (wid == 0 && elect_one()) {
            TC_FENCE_AFTER();
            #pragma unroll
            for (int blk = 0; blk < 2; blk++) {
                uint64_t vd = MAKE_DESC(ab + AT_V + blk * 8192);
                #pragma unroll
                for (int ks = 0; ks < 4; ks++) {          // K=16 per step
                    uint32_t a_tm = tmem + 128 + blk * 32 + ks * 8;
                    uint32_t acc = (kt == 0 && blk == 0 && ks == 0) ? 0u : 1u;
                    mma_ts_f16(tmem + 192, a_tm, vd + ks * 2, IDESC16_N64, acc);
                }
            }
            TC_COMMIT(ab + 16);
        }

        // ---- prefetch K(kt+1) under O-MMA ----
        if (kt < 7) {
            const size_t kbase = (bh * SEQ + (size_t)(kt + 1) * 128) * HDIM;
            cp_tile16k(ab + AT_K, k16 + kbase, tid);
        }
        CP_COMMIT();
    }
    MBAR_WAIT(ab + 16, 7 & 1);
    TC_FENCE_AFTER();

    // ---- normalize O and write fp16 output ----
    float* rs = reinterpret_cast<float*>(smp + 512);   // [2][128]
    rs[half_ * 128 + row] = rsum;
    __syncthreads();

    {
        uint32_t o[32];
        TC_LD_X32(o, tmem + 192 + half_ * 32);
        TC_WAIT_LD();
        TC_FENCE_BEFORE();
        float inv = 1.0f / (rs[row] + rs[128 + row]);
        size_t off = ((size_t)(b * SEQ + qt * 128 + row)) * DIMC + h * HDIM + half_ * 32;
        #pragma unroll
        for (int j = 0; j < 32; j += 2) {
            __half2 p = __floats2half2_rn(__uint_as_float(o[j]) * inv,
                                          __uint_as_float(o[j + 1]) * inv);
            *reinterpret_cast<uint32_t*>(o16 + off + j) = *reinterpret_cast<uint32_t*>(&p);
        }
    }

    __syncthreads();
    if (wid == 0) { TC_RELINQ(); TC_DEALLOC(tmem, 256); }
#endif  // HAS_TCGEN05
}

// ---------------------------------------------------------------------------
// fp32 fallbacks (proven round-1 kernels)
// ---------------------------------------------------------------------------
__global__ __launch_bounds__(256)
void sgemm_bias_kernel(const float* __restrict__ A, const float* __restrict__ Bm,
                       const float* __restrict__ bias, float* __restrict__ C,
                       int M, int N, int K)
{
    const int BK = 16, PAD = 132;
    __shared__ float As[BK * PAD];
    __shared__ float Bs[BK * PAD];

    int tid = threadIdx.x;
    int tx = tid & 15, ty = tid >> 4;
    int rowBase = blockIdx.y * 128;
    int colBase = blockIdx.x * 128;

    float acc[8][8] = {};

    for (int k0 = 0; k0 < K; k0 += BK) {
        #pragma unroll
        for (int t = 0; t < 2; t++) {
            int i  = tid + t * 256;
            int r  = i >> 2;
            int kq = (i & 3) << 2;
            float4 v = *reinterpret_cast<const float4*>(
                &A[(size_t)(rowBase + r) * K + k0 + kq]);
            As[(kq + 0) * PAD + r] = v.x;
            As[(kq + 1) * PAD + r] = v.y;
            As[(kq + 2) * PAD + r] = v.z;
            As[(kq + 3) * PAD + r] = v.w;
        }
        #pragma unroll
        for (int t = 0; t < 2; t++) {
            int i  = tid + t * 256;
            int kk = i >> 5;
            int n4 = (i & 31) << 2;
            float4 v = *reinterpret_cast<const float4*>(
                &Bm[(size_t)(k0 + kk) * N + colBase + n4]);
            *reinterpret_cast<float4*>(&Bs[kk * PAD + n4]) = v;
        }
        __syncthreads();

        #pragma unroll
        for (int kk = 0; kk < BK; kk++) {
            float a[8], bb[8];
            *(float4*)&a[0] = *(float4*)&As[kk * PAD + ty * 8];
            *(float4*)&a[4] = *(float4*)&As[kk * PAD + ty * 8 + 4];
            *(float4*)&bb[0] = *(float4*)&Bs[kk * PAD + tx * 8];
            *(float4*)&bb[4] = *(float4*)&Bs[kk * PAD + tx * 8 + 4];
            #pragma unroll
            for (int i = 0; i < 8; i++)
                #pragma unroll
                for (int j = 0; j < 8; j++)
                    acc[i][j] += a[i] * bb[j];
        }
        __syncthreads();
    }

    #pragma unroll
    for (int i = 0; i < 8; i++) {
        int r = rowBase + ty * 8 + i;
        #pragma unroll
        for (int j = 0; j < 8; j += 4) {
            int c = colBase + tx * 8 + j;
            float4 v;
            v.x = acc[i][j + 0] + bias[c + 0];
            v.y = acc[i][j + 1] + bias[c + 1];
            v.z = acc[i][j + 2] + bias[c + 2];
            v.w = acc[i][j + 3] + bias[c + 3];
            *reinterpret_cast<float4*>(&C[(size_t)r * N + c]) = v;
        }
    }
}

__global__ __launch_bounds__(256)
void attn_kernel()
{
    extern __shared__ float sm[];
    float* Qs  = sm;
    float* Ks  = Qs + 64 * 64;
    float* Vs  = Ks + 64 * 65;
    float* Ss  = Vs + 64 * 64;
    float* m_s = Ss + 64 * 65;
    float* l_s = m_s + 64;
    float* a_s = l_s + 64;

    int qt = blockIdx.x, h = blockIdx.y, b = blockIdx.z;
    int tid = threadIdx.x;
    int tx = tid & 15, ty = tid >> 4;
    const float scale = 0.125f;
    const int RS = 3 * DIMC;

    size_t qoff = ((size_t)(b * SEQ + qt * 64)) * RS + h * HDIM;

    #pragma unroll
    for (int t = 0; t < 4; t++) {
        int i  = tid + t * 256;
        int r  = i >> 4;
        int d4 = (i & 15) << 2;
        float4 v = *reinterpret_cast<const float4*>(&g_qkv[qoff + (size_t)r * RS + d4]);
        *reinterpret_cast<float4*>(&Qs[r * 64 + d4]) = v;
    }
    if (tid < 64) { m_s[tid] = -1e30f; l_s[tid] = 0.f; }
    float O[4][4] = {};
    __syncthreads();

    for (int kt = 0; kt < 16; kt++) {
        size_t koff = ((size_t)(b * SEQ + kt * 64)) * RS + DIMC + h * HDIM;
        size_t voff = koff + DIMC;
        #pragma unroll
        for (int t = 0; t < 4; t++) {
            int i  = tid + t * 256;
            int r  = i >> 4;
            int d4 = (i & 15) << 2;
            float4 kv = *reinterpret_cast<const float4*>(&g_qkv[koff + (size_t)r * RS + d4]);
            Ks[r * 65 + d4 + 0] = kv.x;
            Ks[r * 65 + d4 + 1] = kv.y;
            Ks[r * 65 + d4 + 2] = kv.z;
            Ks[r * 65 + d4 + 3] = kv.w;
            float4 vv = *reinterpret_cast<const float4*>(&g_qkv[voff + (size_t)r * RS + d4]);
            *reinterpret_cast<float4*>(&Vs[r * 64 + d4]) = vv;
        }
        __syncthreads();

        float s[4][4] = {};
        #pragma unroll 8
        for (int d = 0; d < 64; d++) {
            float qv[4], kv[4];
            #pragma unroll
            for (int i = 0; i < 4; i++) qv[i] = Qs[(ty * 4 + i) * 64 + d];
            #pragma unroll
            for (int j = 0; j < 4; j++) kv[j] = Ks[(tx * 4 + j) * 65 + d];
            #pragma unroll
            for (int i = 0; i < 4; i++)
                #pragma unroll
                for (int j = 0; j < 4; j++)
                    s[i][j] += qv[i] * kv[j];
        }
        #pragma unroll
        for (int i = 0; i < 4; i++)
            #pragma unroll
            for (int j = 0; j < 4; j++)
                Ss[(ty * 4 + i) * 65 + tx * 4 + j] = s[i][j] * scale;
        __syncthreads();

        if (tid < 64) {
            float mold = m_s[tid];
            float mx = mold;
            #pragma unroll 8
            for (int j = 0; j < 64; j++) mx = fmaxf(mx, Ss[tid * 65 + j]);
            float sum = 0.f;
            #pragma unroll 8
            for (int j = 0; j < 64; j++) {
                float p = __expf(Ss[tid * 65 + j] - mx);
                Ss[tid * 65 + j] = p;
                sum += p;
            }
            float alpha = __expf(mold - mx);
            a_s[tid] = alpha;
            m_s[tid] = mx;
            l_s[tid] = l_s[tid] * alpha + sum;
        }
        __syncthreads();

        float alpha[4];
        #pragma unroll
        for (int i = 0; i < 4; i++) alpha[i] = a_s[ty * 4 + i];
        #pragma unroll
        for (int i = 0; i < 4; i++)
            #pragma unroll
            for (int j = 0; j < 4; j++)
                O[i][j] *= alpha[i];
        #pragma unroll 8
        for (int kv = 0; kv < 64; kv++) {
            float p[4], v[4];
            #pragma unroll
            for (int i = 0; i < 4; i++) p[i] = Ss[(ty * 4 + i) * 65 + kv];
            #pragma unroll
            for (int j = 0; j < 4; j++) v[j] = Vs[kv * 64 + tx * 4 + j];
            #pragma unroll
            for (int i = 0; i < 4; i++)
                #pragma unroll
                for (int j = 0; j < 4; j++)
                    O[i][j] += p[i] * v[j];
        }
        __syncthreads();
    }

    float inv_l[4];
    #pragma unroll
    for (int i = 0; i < 4; i++) inv_l[i] = 1.0f / l_s[ty * 4 + i];
    #pragma unroll
    for (int i = 0; i < 4; i++) {
        int q = qt * 64 + ty * 4 + i;
        size_t off = ((size_t)(b * SEQ + q)) * DIMC + h * HDIM + tx * 4;
        float4 v;
        v.x = O[i][0] * inv_l[i];
        v.y = O[i][1] * inv_l[i];
        v.z = O[i][2] * inv_l[i];
        v.w = O[i][3] * inv_l[i];
        *reinterpret_cast<float4*>(&g_attn[off]) = v;
    }
}

// ---------------------------------------------------------------------------

extern "C" void kernel_launch(void* const* d_in, const int* in_sizes, int n_in,
                              void* d_out, int out_size)
{
    const float* x     = (const float*)d_in[0];
    const float* Wqkv  = (const float*)d_in[1];
    const float* bqkv  = (const float*)d_in[2];
    const float* Wproj = (const float*)d_in[3];
    const float* bproj = (const float*)d_in[4];
    float* out = (float*)d_out;

    float *qkv = nullptr, *attn = nullptr;
    __half *a16, *wq16, *wp16, *q16, *k16, *vt16;
    cudaGetSymbolAddress((void**)&qkv,  g_qkv);
    cudaGetSymbolAddress((void**)&attn, g_attn);
    cudaGetSymbolAddress((void**)&a16,  g_a16);
    cudaGetSymbolAddress((void**)&wq16, g_wq16);
    cudaGetSymbolAddress((void**)&wp16, g_wp16);
    cudaGetSymbolAddress((void**)&q16,  g_q16);
    cudaGetSymbolAddress((void**)&k16,  g_k16);
    cudaGetSymbolAddress((void**)&vt16, g_vt16);

    cudaFuncAttributes pa{};
    cudaFuncGetAttributes(&pa, feat_probe);
    bool use_tc = pa.sharedSizeBytes >= 1024;

    dim3 blk(256);

    if (use_tc) {
        cudaFuncSetAttribute(gemm_f16_kernel<0>,
                             cudaFuncAttributeMaxDynamicSharedMemorySize, SMEM_GEMM);
        cudaFuncSetAttribute(gemm_f16_kernel<1>,
                             cudaFuncAttributeMaxDynamicSharedMemorySize, SMEM_GEMM);
        cudaFuncSetAttribute(attn_tc_kernel,
                             cudaFuncAttributeMaxDynamicSharedMemorySize, SMEM_ATTN);

        int n4 = MTOT * DIMC / 4;
        cvt16_kernel<<<(n4 + 255) / 256, 256>>>(x, a16, n4);
        dim3 tb(32, 32);
        transpose_cvt16_kernel<<<dim3(NQKV / 32, DIMC / 32), tb>>>(Wqkv, wq16, DIMC, NQKV);
        transpose_cvt16_kernel<<<dim3(DIMC / 32, DIMC / 32), tb>>>(Wproj, wp16, DIMC, DIMC);

        // QKV GEMM (fp16, 256x256) with fused repack epilogue
        dim3 g1(NQKV / 256, MTOT / 256);    // 9 x 32
        gemm_f16_kernel<1><<<g1, blk, SMEM_GEMM>>>(a16, wq16, bqkv,
                                                   nullptr, NQKV, DIMC,
                                                   q16, k16, vt16);

        // attention (fp16, P in TMEM, 2 CTAs/SM)
        dim3 g2(SEQ / 128, NHEAD, BATCH);
        attn_tc_kernel<<<g2, blk, SMEM_ATTN>>>(q16, k16, vt16, a16);

        // projection (fp16 in, fp32 out, 256x256)
        dim3 g3(DIMC / 256, MTOT / 256);    // 3 x 32
        gemm_f16_kernel<0><<<g3, blk, SMEM_GEMM>>>(a16, wp16, bproj,
                                                   out, DIMC, DIMC,
                                                   nullptr, nullptr, nullptr);
    } else {
        const int ATTN_SMEM = (64*64 + 64*65 + 64*64 + 64*65 + 3*64) * 4;
        cudaFuncSetAttribute(attn_kernel,
                             cudaFuncAttributeMaxDynamicSharedMemorySize, ATTN_SMEM);
        dim3 g1(NQKV / 128, MTOT / 128);
        sgemm_bias_kernel<<<g1, blk>>>(x, Wqkv, bqkv, qkv, MTOT, NQKV, DIMC);

        dim3 g2(SEQ / 64, NHEAD, BATCH);
        attn_kernel<<<g2, blk, ATTN_SMEM>>>();

        dim3 g3(DIMC / 128, MTOT / 128);
        sgemm_bias_kernel<<<g3, blk>>>(attn, Wproj, bproj, out, MTOT, DIMC, DIMC);
    }
}

// round 12
// speedup vs baseline: 3.0145x; 1.0900x over previous
#include <cuda_runtime.h>
#include <cuda_bf16.h>
#include <cuda_fp16.h>
#include <math.h>
#include <stdint.h>

#define DIMC 768
#define NHEAD 12
#define HDIM 64
#define BATCH 8
#define SEQ 1024
#define MTOT (BATCH*SEQ)   // 8192
#define NQKV (3*DIMC)      // 2304

#if defined(__CUDA_ARCH__) && (defined(__CUDA_ARCH_FEAT_SM103_ALL) || defined(__CUDA_ARCH_FEAT_SM100_ALL))
#define HAS_TCGEN05 1
#else
#define HAS_TCGEN05 0
#endif

// ---------------------------------------------------------------------------
// Scratch
// ---------------------------------------------------------------------------
__device__ __align__(16) float g_qkv[(size_t)MTOT * NQKV];      // fallback only
__device__ __align__(16) float g_attn[(size_t)MTOT * DIMC];     // fallback only
__device__ __align__(16) __half g_a16[(size_t)MTOT * DIMC];
__device__ __align__(16) __half g_wq16[(size_t)NQKV * DIMC];
__device__ __align__(16) __half g_wp16[(size_t)DIMC * DIMC];
__device__ __align__(16) __half g_q16[(size_t)BATCH * NHEAD * SEQ * HDIM];
__device__ __align__(16) __half g_k16[(size_t)BATCH * NHEAD * SEQ * HDIM];
__device__ __align__(16) __half g_vt16[(size_t)BATCH * NHEAD * SEQ * HDIM];

// ---------------------------------------------------------------------------
// Probe kernel (host dispatch signal)
// ---------------------------------------------------------------------------
__global__ void feat_probe(int* out) {
#if HAS_TCGEN05
    __shared__ int s[256];
#else
    __shared__ int s[2];
#endif
    int n = (int)(sizeof(s) / sizeof(int));
    s[threadIdx.x % n] = (int)clock();
    __syncthreads();
    if (out) *out = s[0];
}

// ---------------------------------------------------------------------------
// fp32 -> fp16 convert kernels
// ---------------------------------------------------------------------------
__global__ __launch_bounds__(256)
void cvt16_kernel(const float* __restrict__ src, __half* __restrict__ dst, int n4)
{
    int i = blockIdx.x * blockDim.x + threadIdx.x;
    if (i >= n4) return;
    float4 v = reinterpret_cast<const float4*>(src)[i];
    __half2 a = __floats2half2_rn(v.x, v.y);
    __half2 b = __floats2half2_rn(v.z, v.w);
    uint2 o;
    o.x = *reinterpret_cast<uint32_t*>(&a);
    o.y = *reinterpret_cast<uint32_t*>(&b);
    reinterpret_cast<uint2*>(dst)[i] = o;
}

__global__ __launch_bounds__(1024)
void transpose_cvt16_kernel(const float* __restrict__ W,
                            __half* __restrict__ T16, int K, int N)
{
    __shared__ float t[32][33];
    int n0 = blockIdx.x * 32, k0 = blockIdx.y * 32;
    int tx = threadIdx.x, ty = threadIdx.y;
    t[ty][tx] = W[(size_t)(k0 + ty) * N + n0 + tx];
    __syncthreads();
    T16[(size_t)(n0 + ty) * K + k0 + tx] = __float2half_rn(t[tx][ty]);
}

// ---------------------------------------------------------------------------
// helpers
// ---------------------------------------------------------------------------
__device__ __forceinline__ uint32_t smem_u32(const void* p) {
    uint32_t a;
    asm("{ .reg .u64 t; cvta.to.shared.u64 t, %1; cvt.u32.u64 %0, t; }"
        : "=r"(a) : "l"(p));
    return a;
}

#define SWZ128(o) ((o) ^ (((o) >> 3) & 0x70))

#define MBAR_INIT(addr, cnt) \
    asm volatile("mbarrier.init.shared.b64 [%0], %1;" :: "r"(addr), "r"(cnt) : "memory")

#define MBAR_WAIT(addr, parity) do {                                          \
    uint32_t _m = (addr); uint32_t _p = (parity); uint32_t _done;             \
    asm volatile("{\n\t.reg .pred p;\n\t"                                     \
        "mbarrier.try_wait.parity.acquire.cta.shared::cta.b64 p, [%1], %2;\n\t"\
        "selp.b32 %0, 1, 0, p;\n\t}" : "=r"(_done) : "r"(_m), "r"(_p) : "memory");\
    if (!_done) {                                                             \
        asm volatile("{\n\t.reg .pred P1;\n\t"                                \
            "WL_%=:\n\t"                                                      \
            "mbarrier.try_wait.parity.acquire.cta.shared::cta.b64 P1, [%0], %1, 0x989680;\n\t"\
            "@P1 bra.uni WD_%=;\n\t"                                          \
            "bra.uni WL_%=;\n\t"                                              \
            "WD_%=:\n\t}" :: "r"(_m), "r"(_p) : "memory");                    \
    }                                                                         \
} while (0)

#if HAS_TCGEN05
__device__ __forceinline__ uint32_t elect_one() {
    uint32_t pred;
    asm volatile("{\n\t.reg .pred p;\n\telect.sync _|p, 0xFFFFFFFF;\n\t"
                 "selp.b32 %0, 1, 0, p;\n\t}" : "=r"(pred));
    return pred;
}

#define TC_ALLOC(sm_dst, ncols) \
    asm volatile("tcgen05.alloc.cta_group::1.sync.aligned.shared::cta.b32 [%0], %1;" \
                 :: "r"(sm_dst), "r"(ncols) : "memory")
#define TC_DEALLOC(tm, ncols) \
    asm volatile("tcgen05.dealloc.cta_group::1.sync.aligned.b32 %0, %1;" :: "r"(tm), "r"(ncols))
#define TC_RELINQ() \
    asm volatile("tcgen05.relinquish_alloc_permit.cta_group::1.sync.aligned;")
#define TC_COMMIT(mbar) \
    asm volatile("tcgen05.commit.cta_group::1.mbarrier::arrive::one.shared::cluster.b64 [%0];" \
                 :: "r"(mbar) : "memory")
#define TC_FENCE_AFTER()  asm volatile("tcgen05.fence::after_thread_sync;" ::: "memory")
#define TC_FENCE_BEFORE() asm volatile("tcgen05.fence::before_thread_sync;" ::: "memory")
#define TC_WAIT_LD() asm volatile("tcgen05.wait::ld.sync.aligned;" ::: "memory")
#define TC_WAIT_ST() asm volatile("tcgen05.wait::st.sync.aligned;" ::: "memory")
#define FENCE_ASYNC() asm volatile("fence.proxy.async.shared::cta;" ::: "memory")

#define CP_ASYNC16(dst, src) \
    asm volatile("cp.async.cg.shared.global [%0], [%1], 16;" :: "r"(dst), "l"(src) : "memory")
#define CP_COMMIT() asm volatile("cp.async.commit_group;" ::: "memory")
#define CP_WAIT1()  asm volatile("cp.async.wait_group 1;" ::: "memory")
#define CP_WAIT0()  asm volatile("cp.async.wait_group 0;" ::: "memory")

#define TC_LD_X32(r, tm) \
    asm volatile("tcgen05.ld.sync.aligned.32x32b.x32.b32 "                    \
        "{%0, %1, %2, %3, %4, %5, %6, %7, "                                   \
        " %8, %9, %10, %11, %12, %13, %14, %15, "                             \
        " %16, %17, %18, %19, %20, %21, %22, %23, "                           \
        " %24, %25, %26, %27, %28, %29, %30, %31}, [%32];"                    \
        : "=r"((r)[0]),  "=r"((r)[1]),  "=r"((r)[2]),  "=r"((r)[3]),          \
          "=r"((r)[4]),  "=r"((r)[5]),  "=r"((r)[6]),  "=r"((r)[7]),          \
          "=r"((r)[8]),  "=r"((r)[9]),  "=r"((r)[10]), "=r"((r)[11]),         \
          "=r"((r)[12]), "=r"((r)[13]), "=r"((r)[14]), "=r"((r)[15]),         \
          "=r"((r)[16]), "=r"((r)[17]), "=r"((r)[18]), "=r"((r)[19]),         \
          "=r"((r)[20]), "=r"((r)[21]), "=r"((r)[22]), "=r"((r)[23]),         \
          "=r"((r)[24]), "=r"((r)[25]), "=r"((r)[26]), "=r"((r)[27]),         \
          "=r"((r)[28]), "=r"((r)[29]), "=r"((r)[30]), "=r"((r)[31])          \
        : "r"(tm))

#define TC_ST_X32(tm, r) \
    asm volatile("tcgen05.st.sync.aligned.32x32b.x32.b32 [%0], "              \
        "{%1, %2, %3, %4, %5, %6, %7, %8, "                                   \
        " %9, %10, %11, %12, %13, %14, %15, %16, "                            \
        " %17, %18, %19, %20, %21, %22, %23, %24, "                           \
        " %25, %26, %27, %28, %29, %30, %31, %32};"                           \
        :: "r"(tm),                                                           \
           "r"((r)[0]),  "r"((r)[1]),  "r"((r)[2]),  "r"((r)[3]),             \
           "r"((r)[4]),  "r"((r)[5]),  "r"((r)[6]),  "r"((r)[7]),             \
           "r"((r)[8]),  "r"((r)[9]),  "r"((r)[10]), "r"((r)[11]),            \
           "r"((r)[12]), "r"((r)[13]), "r"((r)[14]), "r"((r)[15]),            \
           "r"((r)[16]), "r"((r)[17]), "r"((r)[18]), "r"((r)[19]),            \
           "r"((r)[20]), "r"((r)[21]), "r"((r)[22]), "r"((r)[23]),            \
           "r"((r)[24]), "r"((r)[25]), "r"((r)[26]), "r"((r)[27]),            \
           "r"((r)[28]), "r"((r)[29]), "r"((r)[30]), "r"((r)[31])             \
        : "memory")

#define MAKE_DESC(base) \
    ((uint64_t(2) << 61) | (uint64_t(1) << 46) | (uint64_t(64) << 32) | \
     (uint64_t(1) << 16) | ((uint64_t)((base) >> 4) & 0x3FFF))

__device__ __forceinline__ void mma_ss_f16(uint32_t d, uint64_t ad, uint64_t bd,
                                           uint32_t idesc, uint32_t en) {
    asm volatile(
        "{\n\t.reg .pred p;\n\t"
        "setp.ne.u32 p, %4, 0;\n\t"
        "tcgen05.mma.cta_group::1.kind::f16 [%0], %1, %2, %3, {%5, %5, %5, %5}, p;\n\t}"
        :: "r"(d), "l"(ad), "l"(bd), "r"(idesc), "r"(en), "r"(0u) : "memory");
}

__device__ __forceinline__ void mma_ts_f16(uint32_t d, uint32_t a_tmem, uint64_t bd,
                                           uint32_t idesc, uint32_t en) {
    asm volatile(
        "{\n\t.reg .pred p;\n\t"
        "setp.ne.u32 p, %4, 0;\n\t"
        "tcgen05.mma.cta_group::1.kind::f16 [%0], [%1], %2, %3, {%5, %5, %5, %5}, p;\n\t}"
        :: "r"(d), "r"(a_tmem), "l"(bd), "r"(idesc), "r"(en), "r"(0u) : "memory");
}

#define IDESC16_N128 (0x10u | (16u << 17) | (8u << 24))
#define IDESC16_N64  (0x10u | (8u  << 17) | (8u << 24))
#endif  // HAS_TCGEN05

// ---------------------------------------------------------------------------
// tcgen05 fp16 GEMM — 256x256 tile, 3-stage cp.async (proven round-11).
// ---------------------------------------------------------------------------
#define ST16_STG 65536
#define SMEM_GEMM (1024 + 1024 + 3 * ST16_STG)   // 198656

template<int MODE>
__global__ __launch_bounds__(256, 1)
void gemm_f16_kernel(const __half* __restrict__ A16,
                     const __half* __restrict__ B16,
                     const float* __restrict__ bias,
                     float* __restrict__ C, int N, int K,
                     __half* q16, __half* k16, __half* vt16)
{
#if HAS_TCGEN05
    extern __shared__ char smem[];
    uint32_t sb = smem_u32(smem);
    uint32_t ab = (sb + 1023u) & ~1023u;
    char* smp = smem + (ab - sb);

    int tid = threadIdx.x;
    int wid = tid >> 5, lid = tid & 31;
    int rowBase = blockIdx.y * 256;
    int colBase = blockIdx.x * 256;

    if (wid == 0) TC_ALLOC(ab + 0, 512);
    if (tid == 0) { MBAR_INIT(ab + 8, 1); MBAR_INIT(ab + 16, 1); MBAR_INIT(ab + 24, 1); }
    __syncthreads();
    uint32_t tmem;
    asm volatile("ld.shared.b32 %0, [%1];" : "=r"(tmem) : "r"(ab + 0));

    const int KC = K >> 6;
    const size_t rowK = (size_t)K;

    auto load_stage = [&](int kc, int buf) {
        uint32_t st = ab + 1024 + buf * ST16_STG;
        {
            const char* g = reinterpret_cast<const char*>(
                A16 + (size_t)rowBase * rowK + kc * 64);
            #pragma unroll
            for (int t = 0; t < 8; t++) {
                int i = tid + t * 256;
                int r = i >> 3, c = i & 7;
                uint32_t dst = st + (r >> 7) * 16384
                             + SWZ128((uint32_t)((r & 127) * 128 + c * 16));
                CP_ASYNC16(dst, g + (size_t)r * (rowK * 2) + c * 16);
            }
        }
        {
            const char* g = reinterpret_cast<const char*>(
                B16 + (size_t)colBase * rowK + kc * 64);
            #pragma unroll
            for (int t = 0; t < 8; t++) {
                int i = tid + t * 256;
                int r = i >> 3, c = i & 7;
                uint32_t dst = st + 32768 + (r >> 7) * 16384
                             + SWZ128((uint32_t)((r & 127) * 128 + c * 16));
                CP_ASYNC16(dst, g + (size_t)r * (rowK * 2) + c * 16);
            }
        }
    };

    load_stage(0, 0); CP_COMMIT();
    load_stage(1, 1); CP_COMMIT();

    int ph[3] = { 0, 0, 0 };

    for (int kc = 0; kc < KC; kc++) {
        int buf = kc - (kc / 3) * 3;
        CP_WAIT1();
        __syncthreads();
        FENCE_ASYNC();

        uint32_t st = ab + 1024 + buf * ST16_STG;
        if (wid == 0 && elect_one()) {
            #pragma unroll
            for (int ks = 0; ks < 4; ks++) {
                uint64_t off = ks * 2;
                #pragma unroll
                for (int mh = 0; mh < 2; mh++) {
                    uint64_t ahd = MAKE_DESC(st + mh * 16384);
                    #pragma unroll
                    for (int ct = 0; ct < 2; ct++) {
                        uint64_t bhd = MAKE_DESC(st + 32768 + ct * 16384);
                        mma_ss_f16(tmem + mh * 256 + ct * 128,
                                   ahd + off, bhd + off, IDESC16_N128,
                                   (kc == 0 && ks == 0) ? 0u : 1u);
                    }
                }
            }
            TC_COMMIT(ab + 8 + 8 * buf);
        }

        if (kc >= 1) {
            int pb = (kc - 1) % 3;
            MBAR_WAIT(ab + 8 + 8 * pb, ph[pb] & 1); ph[pb]++;
        }
        if (kc + 2 < KC) load_stage(kc + 2, (kc + 2) % 3);
        CP_COMMIT();
    }
    {
        int lb = (KC - 1) % 3;
        MBAR_WAIT(ab + 8 + 8 * lb, ph[lb] & 1);
    }
    CP_WAIT0();
    TC_FENCE_AFTER();

    float* Ct = reinterpret_cast<float*>(smp + 1024);
    #pragma unroll
    for (int mh = 0; mh < 2; mh++) {
        #pragma unroll
        for (int ct = 0; ct < 2; ct++) {
            int colB = colBase + ct * 128;
            int rowB = rowBase + mh * 128;
            if (wid < 4) {
                int row = wid * 32 + lid;
                #pragma unroll
                for (int cb = 0; cb < 4; cb++) {
                    uint32_t r[32];
                    TC_LD_X32(r, tmem + mh * 256 + ct * 128 + cb * 32);
                    TC_WAIT_LD();
                    #pragma unroll
                    for (int j = 0; j < 32; j++)
                        Ct[row * 129 + cb * 32 + j] = __uint_as_float(r[j]);
                }
                TC_FENCE_BEFORE();
            }
            __syncthreads();

            if (MODE == 0) {
                for (int i = tid; i < 128 * 32; i += 256) {
                    int r = i >> 5, c = (i & 31) * 4;
                    float4 v;
                    v.x = Ct[r * 129 + c + 0] + bias[colB + c + 0];
                    v.y = Ct[r * 129 + c + 1] + bias[colB + c + 1];
                    v.z = Ct[r * 129 + c + 2] + bias[colB + c + 2];
                    v.w = Ct[r * 129 + c + 3] + bias[colB + c + 3];
                    *reinterpret_cast<float4*>(&C[(size_t)(rowB + r) * N + colB + c]) = v;
                }
            } else {
                int type = colB / DIMC;
                if (type < 2) {
                    __half* dst = (type == 0) ? q16 : k16;
                    for (int i = tid; i < 128 * 32; i += 256) {
                        int r = i >> 5, c4 = (i & 31) * 4;
                        int token = rowB + r;
                        int b = token >> 10, tokin = token & 1023;
                        int col = colB + c4;
                        int hh = (col % DIMC) / HDIM;
                        int d = col & 63;
                        float v0 = Ct[r * 129 + c4 + 0] + bias[col + 0];
                        float v1 = Ct[r * 129 + c4 + 1] + bias[col + 1];
                        float v2 = Ct[r * 129 + c4 + 2] + bias[col + 2];
                        float v3 = Ct[r * 129 + c4 + 3] + bias[col + 3];
                        __half2 p0 = __floats2half2_rn(v0, v1);
                        __half2 p1 = __floats2half2_rn(v2, v3);
                        uint2 o;
                        o.x = *reinterpret_cast<uint32_t*>(&p0);
                        o.y = *reinterpret_cast<uint32_t*>(&p1);
                        size_t off = (((size_t)(b * NHEAD + hh) * SEQ + tokin) * HDIM + d);
                        *reinterpret_cast<uint2*>(dst + off) = o;
                    }
                } else {
                    for (int t = 0; t < 32; t++) {
                        int idx = t * 256 + tid;
                        int c  = idx >> 6;
                        int rp = (idx & 63) * 2;
                        int token = rowB + rp;
                        int b = token >> 10, tokin = token & 1023;
                        int kvblk = tokin >> 6, kvin = tokin & 63;
                        int col = colB + c;
                        int hh = (col % DIMC) / HDIM;
                        int d = col & 63;
                        float v0 = Ct[rp * 129 + c] + bias[col];
                        float v1 = Ct[(rp + 1) * 129 + c] + bias[col];
                        __half2 p = __floats2half2_rn(v0, v1);
                        size_t off = (((size_t)(b * NHEAD + hh) * 16 + kvblk) * HDIM + d) * 64 + kvin;
                        *reinterpret_cast<uint32_t*>(vt16 + off) = *reinterpret_cast<uint32_t*>(&p);
                    }
                }
            }
            __syncthreads();
        }
    }

    if (wid == 0) { TC_RELINQ(); TC_DEALLOC(tmem, 512); }
#endif
}

// ---------------------------------------------------------------------------
// tcgen05 fp16 attention: 2 q-tiles per CTA share the K/V sweep.
// K/V double-buffered in smem, prefetched one iteration early.
// TMEM(512): S_A@0 S_B@128 P_A@256 P_B@320 O_A@384 O_B@448
// ---------------------------------------------------------------------------
#define AT_QA  3072
#define AT_QB  (AT_QA + 16384)   // 19456
#define AT_KB(b) (35840 + (b) * 16384)
#define AT_VB(b) (68608 + (b) * 16384)
#define SMEM_ATTN (101376 + 1024)   // 102400

#if HAS_TCGEN05
__device__ __forceinline__ void cp_tile16k(uint32_t dst, const __half* src, int tid)
{
    const char* g = reinterpret_cast<const char*>(src);
    #pragma unroll
    for (int t = 0; t < 4; t++) {
        uint32_t bo = (uint32_t)(tid + t * 256) * 16;
        CP_ASYNC16(dst + SWZ128(bo), g + bo);
    }
}
#endif

__global__ __launch_bounds__(256, 1)
void attn_tc_kernel(const __half* __restrict__ q16, const __half* __restrict__ k16,
                    const __half* __restrict__ vt16, __half* __restrict__ o16)
{
#if HAS_TCGEN05
    extern __shared__ char smem[];
    uint32_t sb = smem_u32(smem);
    uint32_t ab = (sb + 1023u) & ~1023u;
    char* smp = smem + (ab - sb);

    int tid = threadIdx.x;
    int wid = tid >> 5, lane = tid & 31;
    int sub = wid & 3, half_ = wid >> 2;
    int row = sub * 32 + lane;
    int qp = blockIdx.x, h = blockIdx.y, b = blockIdx.z;
    int qtA = qp * 2, qtB = qp * 2 + 1;

    if (wid == 0) TC_ALLOC(ab + 0, 512);
    if (tid == 0) {
        MBAR_INIT(ab + 8, 1);    // S_A
        MBAR_INIT(ab + 16, 1);   // S_B
        MBAR_INIT(ab + 24, 2);   // O (two commits per phase)
    }
    __syncthreads();
    uint32_t tmem;
    asm volatile("ld.shared.b32 %0, [%1];" : "=r"(tmem) : "r"(ab + 0));

    const size_t bh = (size_t)(b * NHEAD + h);
    const size_t kvstride = (size_t)SEQ * HDIM;

    // prologue: Q_A, Q_B, K(0), V(0)
    cp_tile16k(ab + AT_QA, q16 + (bh * SEQ + (size_t)qtA * 128) * HDIM, tid);
    cp_tile16k(ab + AT_QB, q16 + (bh * SEQ + (size_t)qtB * 128) * HDIM, tid);
    cp_tile16k(ab + AT_KB(0), k16 + bh * kvstride, tid);
    cp_tile16k(ab + AT_VB(0), vt16 + bh * kvstride, tid);
    CP_COMMIT();

    float rsumA = 0.f, rsumB = 0.f;
    const float scale = 0.125f;
    const uint32_t lane_base = (uint32_t)sub << 21;

    for (int kt = 0; kt < 8; kt++) {
        int buf = kt & 1;
        CP_WAIT0();              // K(kt), V(kt) ready
        __syncthreads();
        FENCE_ASYNC();

        // ---- issue S_A, S_B (share K tile) ----
        if (wid == 0 && elect_one()) {
            uint64_t kd = MAKE_DESC(ab + AT_KB(buf));
            uint64_t qa = MAKE_DESC(ab + AT_QA);
            uint64_t qb = MAKE_DESC(ab + AT_QB);
            #pragma unroll
            for (int ks = 0; ks < 4; ks++)
                mma_ss_f16(tmem, qa + ks * 2, kd + ks * 2, IDESC16_N128,
                           ks > 0 ? 1u : 0u);
            TC_COMMIT(ab + 8);
            #pragma unroll
            for (int ks = 0; ks < 4; ks++)
                mma_ss_f16(tmem + 128, qb + ks * 2, kd + ks * 2, IDESC16_N128,
                           ks > 0 ? 1u : 0u);
            TC_COMMIT(ab + 16);
        }

        // ---- wait O(kt-1): frees P TMEM and buf^1 (V(kt-1)) ----
        if (kt > 0) MBAR_WAIT(ab + 24, (kt - 1) & 1);

        // ---- prefetch K(kt+1), V(kt+1) into buf^1 (covered by S+exp) ----
        if (kt < 7) {
            const size_t kbase = bh * kvstride + (size_t)(kt + 1) * 128 * HDIM;
            const size_t vbase = (bh * 16 + (size_t)(kt + 1) * 2) * (HDIM * 64);
            cp_tile16k(ab + AT_KB(buf ^ 1), k16 + kbase, tid);
            cp_tile16k(ab + AT_VB(buf ^ 1), vt16 + vbase, tid);
        }
        CP_COMMIT();

        // ---- tile A: wait S_A, LDTM, exp, STTM P_A ----
        MBAR_WAIT(ab + 8, kt & 1);
        TC_FENCE_AFTER();
        {
            uint32_t r0[32], r1[32];
            TC_LD_X32(r0, tmem + half_ * 64);
            TC_LD_X32(r1, tmem + half_ * 64 + 32);
            TC_WAIT_LD();
            uint32_t pk[32];
            #pragma unroll
            for (int g = 0; g < 8; g++) {
                float e[8];
                #pragma unroll
                for (int j = 0; j < 8; j++) {
                    int c = g * 8 + j;
                    float s = __uint_as_float(c < 32 ? r0[c] : r1[c - 32]);
                    e[j] = __expf(s * scale);
                    rsumA += e[j];
                }
                __half2 h0 = __floats2half2_rn(e[0], e[1]);
                __half2 h1 = __floats2half2_rn(e[2], e[3]);
                __half2 h2 = __floats2half2_rn(e[4], e[5]);
                __half2 h3 = __floats2half2_rn(e[6], e[7]);
                pk[g * 4 + 0] = *reinterpret_cast<uint32_t*>(&h0);
                pk[g * 4 + 1] = *reinterpret_cast<uint32_t*>(&h1);
                pk[g * 4 + 2] = *reinterpret_cast<uint32_t*>(&h2);
                pk[g * 4 + 3] = *reinterpret_cast<uint32_t*>(&h3);
            }
            TC_ST_X32(tmem + lane_base + 256 + half_ * 32, pk);
            TC_WAIT_ST();
        }
        // ---- tile B: wait S_B, LDTM, exp, STTM P_B ----
        MBAR_WAIT(ab + 16, kt & 1);
        {
            uint32_t r0[32], r1[32];
            TC_LD_X32(r0, tmem + 128 + half_ * 64);
            TC_LD_X32(r1, tmem + 128 + half_ * 64 + 32);
            TC_WAIT_LD();
            uint32_t pk[32];
            #pragma unroll
            for (int g = 0; g < 8; g++) {
                float e[8];
                #pragma unroll
                for (int j = 0; j < 8; j++) {
                    int c = g * 8 + j;
                    float s = __uint_as_float(c < 32 ? r0[c] : r1[c - 32]);
                    e[j] = __expf(s * scale);
                    rsumB += e[j];
                }
                __half2 h0 = __floats2half2_rn(e[0], e[1]);
                __half2 h1 = __floats2half2_rn(e[2], e[3]);
                __half2 h2 = __floats2half2_rn(e[4], e[5]);
                __half2 h3 = __floats2half2_rn(e[6], e[7]);
                pk[g * 4 + 0] = *reinterpret_cast<uint32_t*>(&h0);
                pk[g * 4 + 1] = *reinterpret_cast<uint32_t*>(&h1);
                pk[g * 4 + 2] = *reinterpret_cast<uint32_t*>(&h2);
                pk[g * 4 + 3] = *reinterpret_cast<uint32_t*>(&h3);
            }
            TC_ST_X32(tmem + lane_base + 320 + half_ * 32, pk);
            TC_WAIT_ST();
            TC_FENCE_BEFORE();
        }
        __syncthreads();         // all P in TMEM; V(kt) already waited at top
        FENCE_ASYNC();

        // ---- issue O_A += P_A V, O_B += P_B V (TS mode) ----
        if (wid == 0 && elect_one()) {
            TC_FENCE_AFTER();
            uint32_t acc0 = (kt == 0) ? 0u : 1u;
            #pragma unroll
            for (int blk = 0; blk < 2; blk++) {
                uint64_t vd = MAKE_DESC(ab + AT_VB(buf) + blk * 8192);
                #pragma unroll
                for (int ks = 0; ks < 4; ks++) {
                    uint32_t a0 = (blk == 0 && ks == 0) ? acc0 : 1u;
                    mma_ts_f16(tmem + 384, tmem + 256 + blk * 32 + ks * 8,
                               vd + ks * 2, IDESC16_N64, a0);
                }
            }
            TC_COMMIT(ab + 24);
            #pragma unroll
            for (int blk = 0; blk < 2; blk++) {
                uint64_t vd = MAKE_DESC(ab + AT_VB(buf) + blk * 8192);
                #pragma unroll
                for (int ks = 0; ks < 4; ks++) {
                    uint32_t a0 = (blk == 0 && ks == 0) ? acc0 : 1u;
                    mma_ts_f16(tmem + 448, tmem + 320 + blk * 32 + ks * 8,
                               vd + ks * 2, IDESC16_N64, a0);
                }
            }
            TC_COMMIT(ab + 24);
        }
    }
    MBAR_WAIT(ab + 24, 7 & 1);
    TC_FENCE_AFTER();

    // ---- normalize and write both tiles ----
    float* rsA = reinterpret_cast<float*>(smp + 1024);   // [2][128]
    float* rsB = rsA + 256;
    rsA[half_ * 128 + row] = rsumA;
    rsB[half_ * 128 + row] = rsumB;
    __syncthreads();

    {
        uint32_t o[32];
        TC_LD_X32(o, tmem + 384 + half_ * 32);
        TC_WAIT_LD();
        float inv = 1.0f / (rsA[row] + rsA[128 + row]);
        size_t off = ((size_t)(b * SEQ + qtA * 128 + row)) * DIMC + h * HDIM + half_ * 32;
        #pragma unroll
        for (int j = 0; j < 32; j += 2) {
            __half2 p = __floats2half2_rn(__uint_as_float(o[j]) * inv,
                                          __uint_as_float(o[j + 1]) * inv);
            *reinterpret_cast<uint32_t*>(o16 + off + j) = *reinterpret_cast<uint32_t*>(&p);
        }
    }
    {
        uint32_t o[32];
        TC_LD_X32(o, tmem + 448 + half_ * 32);
        TC_WAIT_LD();
        TC_FENCE_BEFORE();
        float inv = 1.0f / (rsB[row] + rsB[128 + row]);
        size_t off = ((size_t)(b * SEQ + qtB * 128 + row)) * DIMC + h * HDIM + half_ * 32;
        #pragma unroll
        for (int j = 0; j < 32; j += 2) {
            __half2 p = __floats2half2_rn(__uint_as_float(o[j]) * inv,
                                          __uint_as_float(o[j + 1]) * inv);
            *reinterpret_cast<uint32_t*>(o16 + off + j) = *reinterpret_cast<uint32_t*>(&p);
        }
    }

    __syncthreads();
    if (wid == 0) { TC_RELINQ(); TC_DEALLOC(tmem, 512); }
#endif  // HAS_TCGEN05
}

// ---------------------------------------------------------------------------
// fp32 fallbacks (proven round-1 kernels)
// ---------------------------------------------------------------------------
__global__ __launch_bounds__(256)
void sgemm_bias_kernel(const float* __restrict__ A, const float* __restrict__ Bm,
                       const float* __restrict__ bias, float* __restrict__ C,
                       int M, int N, int K)
{
    const int BK = 16, PAD = 132;
    __shared__ float As[BK * PAD];
    __shared__ float Bs[BK * PAD];

    int tid = threadIdx.x;
    int tx = tid & 15, ty = tid >> 4;
    int rowBase = blockIdx.y * 128;
    int colBase = blockIdx.x * 128;

    float acc[8][8] = {};

    for (int k0 = 0; k0 < K; k0 += BK) {
        #pragma unroll
        for (int t = 0; t < 2; t++) {
            int i  = tid + t * 256;
            int r  = i >> 2;
            int kq = (i & 3) << 2;
            float4 v = *reinterpret_cast<const float4*>(
                &A[(size_t)(rowBase + r) * K + k0 + kq]);
            As[(kq + 0) * PAD + r] = v.x;
            As[(kq + 1) * PAD + r] = v.y;
            As[(kq + 2) * PAD + r] = v.z;
            As[(kq + 3) * PAD + r] = v.w;
        }
        #pragma unroll
        for (int t = 0; t < 2; t++) {
            int i  = tid + t * 256;
            int kk = i >> 5;
            int n4 = (i & 31) << 2;
            float4 v = *reinterpret_cast<const float4*>(
                &Bm[(size_t)(k0 + kk) * N + colBase + n4]);
            *reinterpret_cast<float4*>(&Bs[kk * PAD + n4]) = v;
        }
        __syncthreads();

        #pragma unroll
        for (int kk = 0; kk < BK; kk++) {
            float a[8], bb[8];
            *(float4*)&a[0] = *(float4*)&As[kk * PAD + ty * 8];
            *(float4*)&a[4] = *(float4*)&As[kk * PAD + ty * 8 + 4];
            *(float4*)&bb[0] = *(float4*)&Bs[kk * PAD + tx * 8];
            *(float4*)&bb[4] = *(float4*)&Bs[kk * PAD + tx * 8 + 4];
            #pragma unroll
            for (int i = 0; i < 8; i++)
                #pragma unroll
                for (int j = 0; j < 8; j++)
                    acc[i][j] += a[i] * bb[j];
        }
        __syncthreads();
    }

    #pragma unroll
    for (int i = 0; i < 8; i++) {
        int r = rowBase + ty * 8 + i;
        #pragma unroll
        for (int j = 0; j < 8; j += 4) {
            int c = colBase + tx * 8 + j;
            float4 v;
            v.x = acc[i][j + 0] + bias[c + 0];
            v.y = acc[i][j + 1] + bias[c + 1];
            v.z = acc[i][j + 2] + bias[c + 2];
            v.w = acc[i][j + 3] + bias[c + 3];
            *reinterpret_cast<float4*>(&C[(size_t)r * N + c]) = v;
        }
    }
}

__global__ __launch_bounds__(256)
void attn_kernel()
{
    extern __shared__ float sm[];
    float* Qs  = sm;
    float* Ks  = Qs + 64 * 64;
    float* Vs  = Ks + 64 * 65;
    float* Ss  = Vs + 64 * 64;
    float* m_s = Ss + 64 * 65;
    float* l_s = m_s + 64;
    float* a_s = l_s + 64;

    int qt = blockIdx.x, h = blockIdx.y, b = blockIdx.z;
    int tid = threadIdx.x;
    int tx = tid & 15, ty = tid >> 4;
    const float scale = 0.125f;
    const int RS = 3 * DIMC;

    size_t qoff = ((size_t)(b * SEQ + qt * 64)) * RS + h * HDIM;

    #pragma unroll
    for (int t = 0; t < 4; t++) {
        int i  = tid + t * 256;
        int r  = i >> 4;
        int d4 = (i & 15) << 2;
        float4 v = *reinterpret_cast<const float4*>(&g_qkv[qoff + (size_t)r * RS + d4]);
        *reinterpret_cast<float4*>(&Qs[r * 64 + d4]) = v;
    }
    if (tid < 64) { m_s[tid] = -1e30f; l_s[tid] = 0.f; }
    float O[4][4] = {};
    __syncthreads();

    for (int kt = 0; kt < 16; kt++) {
        size_t koff = ((size_t)(b * SEQ + kt * 64)) * RS + DIMC + h * HDIM;
        size_t voff = koff + DIMC;
        #pragma unroll
        for (int t = 0; t < 4; t++) {
            int i  = tid + t * 256;
            int r  = i >> 4;
            int d4 = (i & 15) << 2;
            float4 kv = *reinterpret_cast<const float4*>(&g_qkv[koff + (size_t)r * RS + d4]);
            Ks[r * 65 + d4 + 0] = kv.x;
            Ks[r * 65 + d4 + 1] = kv.y;
            Ks[r * 65 + d4 + 2] = kv.z;
            Ks[r * 65 + d4 + 3] = kv.w;
            float4 vv = *reinterpret_cast<const float4*>(&g_qkv[voff + (size_t)r * RS + d4]);
            *reinterpret_cast<float4*>(&Vs[r * 64 + d4]) = vv;
        }
        __syncthreads();

        float s[4][4] = {};
        #pragma unroll 8
        for (int d = 0; d < 64; d++) {
            float qv[4], kv[4];
            #pragma unroll
            for (int i = 0; i < 4; i++) qv[i] = Qs[(ty * 4 + i) * 64 + d];
            #pragma unroll
            for (int j = 0; j < 4; j++) kv[j] = Ks[(tx * 4 + j) * 65 + d];
            #pragma unroll
            for (int i = 0; i < 4; i++)
                #pragma unroll
                for (int j = 0; j < 4; j++)
                    s[i][j] += qv[i] * kv[j];
        }
        #pragma unroll
        for (int i = 0; i < 4; i++)
            #pragma unroll
            for (int j = 0; j < 4; j++)
                Ss[(ty * 4 + i) * 65 + tx * 4 + j] = s[i][j] * scale;
        __syncthreads();

        if (tid < 64) {
            float mold = m_s[tid];
            float mx = mold;
            #pragma unroll 8
            for (int j = 0; j < 64; j++) mx = fmaxf(mx, Ss[tid * 65 + j]);
            float sum = 0.f;
            #pragma unroll 8
            for (int j = 0; j < 64; j++) {
                float p = __expf(Ss[tid * 65 + j] - mx);
                Ss[tid * 65 + j] = p;
                sum += p;
            }
            float alpha = __expf(mold - mx);
            a_s[tid] = alpha;
            m_s[tid] = mx;
            l_s[tid] = l_s[tid] * alpha + sum;
        }
        __syncthreads();

        float alpha[4];
        #pragma unroll
        for (int i = 0; i < 4; i++) alpha[i] = a_s[ty * 4 + i];
        #pragma unroll
        for (int i = 0; i < 4; i++)
            #pragma unroll
            for (int j = 0; j < 4; j++)
                O[i][j] *= alpha[i];
        #pragma unroll 8
        for (int kv = 0; kv < 64; kv++) {
            float p[4], v[4];
            #pragma unroll
            for (int i = 0; i < 4; i++) p[i] = Ss[(ty * 4 + i) * 65 + kv];
            #pragma unroll
            for (int j = 0; j < 4; j++) v[j] = Vs[kv * 64 + tx * 4 + j];
            #pragma unroll
            for (int i = 0; i < 4; i++)
                #pragma unroll
                for (int j = 0; j < 4; j++)
                    O[i][j] += p[i] * v[j];
        }
        __syncthreads();
    }

    float inv_l[4];
    #pragma unroll
    for (int i = 0; i < 4; i++) inv_l[i] = 1.0f / l_s[ty * 4 + i];
    #pragma unroll
    for (int i = 0; i < 4; i++) {
        int q = qt * 64 + ty * 4 + i;
        size_t off = ((size_t)(b * SEQ + q)) * DIMC + h * HDIM + tx * 4;
        float4 v;
        v.x = O[i][0] * inv_l[i];
        v.y = O[i][1] * inv_l[i];
        v.z = O[i][2] * inv_l[i];
        v.w = O[i][3] * inv_l[i];
        *reinterpret_cast<float4*>(&g_attn[off]) = v;
    }
}

// ---------------------------------------------------------------------------

extern "C" void kernel_launch(void* const* d_in, const int* in_sizes, int n_in,
                              void* d_out, int out_size)
{
    const float* x     = (const float*)d_in[0];
    const float* Wqkv  = (const float*)d_in[1];
    const float* bqkv  = (const float*)d_in[2];
    const float* Wproj = (const float*)d_in[3];
    const float* bproj = (const float*)d_in[4];
    float* out = (float*)d_out;

    float *qkv = nullptr, *attn = nullptr;
    __half *a16, *wq16, *wp16, *q16, *k16, *vt16;
    cudaGetSymbolAddress((void**)&qkv,  g_qkv);
    cudaGetSymbolAddress((void**)&attn, g_attn);
    cudaGetSymbolAddress((void**)&a16,  g_a16);
    cudaGetSymbolAddress((void**)&wq16, g_wq16);
    cudaGetSymbolAddress((void**)&wp16, g_wp16);
    cudaGetSymbolAddress((void**)&q16,  g_q16);
    cudaGetSymbolAddress((void**)&k16,  g_k16);
    cudaGetSymbolAddress((void**)&vt16, g_vt16);

    cudaFuncAttributes pa{};
    cudaFuncGetAttributes(&pa, feat_probe);
    bool use_tc = pa.sharedSizeBytes >= 1024;

    dim3 blk(256);

    if (use_tc) {
        cudaFuncSetAttribute(gemm_f16_kernel<0>,
                             cudaFuncAttributeMaxDynamicSharedMemorySize, SMEM_GEMM);
        cudaFuncSetAttribute(gemm_f16_kernel<1>,
                             cudaFuncAttributeMaxDynamicSharedMemorySize, SMEM_GEMM);
        cudaFuncSetAttribute(attn_tc_kernel,
                             cudaFuncAttributeMaxDynamicSharedMemorySize, SMEM_ATTN);

        int n4 = MTOT * DIMC / 4;
        cvt16_kernel<<<(n4 + 255) / 256, 256>>>(x, a16, n4);
        dim3 tb(32, 32);
        transpose_cvt16_kernel<<<dim3(NQKV / 32, DIMC / 32), tb>>>(Wqkv, wq16, DIMC, NQKV);
        transpose_cvt16_kernel<<<dim3(DIMC / 32, DIMC / 32), tb>>>(Wproj, wp16, DIMC, DIMC);

        dim3 g1(NQKV / 256, MTOT / 256);    // 9 x 32
        gemm_f16_kernel<1><<<g1, blk, SMEM_GEMM>>>(a16, wq16, bqkv,
                                                   nullptr, NQKV, DIMC,
                                                   q16, k16, vt16);

        // attention: 2 q-tiles per CTA, shared K/V sweep
        dim3 g2(SEQ / 256, NHEAD, BATCH);   // 4 x 12 x 8 = 384
        attn_tc_kernel<<<g2, blk, SMEM_ATTN>>>(q16, k16, vt16, a16);

        dim3 g3(DIMC / 256, MTOT / 256);    // 3 x 32
        gemm_f16_kernel<0><<<g3, blk, SMEM_GEMM>>>(a16, wp16, bproj,
                                                   out, DIMC, DIMC,
                                                   nullptr, nullptr, nullptr);
    } else {
        const int ATTN_SMEM = (64*64 + 64*65 + 64*64 + 64*65 + 3*64) * 4;
        cudaFuncSetAttribute(attn_kernel,
                             cudaFuncAttributeMaxDynamicSharedMemorySize, ATTN_SMEM);
        dim3 g1(NQKV / 128, MTOT / 128);
        sgemm_bias_kernel<<<g1, blk>>>(x, Wqkv, bqkv, qkv, MTOT, NQKV, DIMC);

        dim3 g2(SEQ / 64, NHEAD, BATCH);
        attn_kernel<<<g2, blk, ATTN_SMEM>>>();

        dim3 g3(DIMC / 128, MTOT / 128);
        sgemm_bias_kernel<<<g3, blk>>>(attn, Wproj, bproj, out, MTOT, DIMC, DIMC);
    }
}